// round 5
// baseline (speedup 1.0000x reference)
#include <cuda_runtime.h>
#include <math.h>
#include <stdint.h>

#define BDIM 384
#define HEADS 8
#define HD 48
#define NSEQ 2048
#define NB 4
#define MROWS (NB*NSEQ)      /* 8192 */
#define MLPH 1536
#define QKVN (3*BDIM)        /* 1152 */

/* ------------ scratch (device globals; no allocation allowed) ------------ */
__device__ float g_h [MROWS*BDIM];
__device__ float g_q [MROWS*BDIM];
__device__ float g_k [MROWS*BDIM];
__device__ float g_v [MROWS*BDIM];
__device__ float g_pe[MROWS*HD];
__device__ float g_att[MROWS*BDIM];
__device__ float g_x1[MROWS*BDIM];
__device__ float g_hid[MROWS*MLPH];
__device__ int   g_mask[MROWS];
__device__ float g_mb [MROWS];          /* 0 or -1e30 mask bias */
__device__ float g_wqkv[BDIM*QKVN];
__device__ float g_bqkv[QKVN];

__device__ __forceinline__ float gelu_exact(float x) {
    return 0.5f * x * (1.0f + erff(x * 0.70710678118654752f));
}

/* m16n8k8 tf32 mma, fp32 accumulate. Raw f32 bits fed as tf32 (HW truncates). */
__device__ __forceinline__ void mma8(float* c,
                                     uint32_t a0, uint32_t a1, uint32_t a2, uint32_t a3,
                                     uint32_t b0, uint32_t b1) {
    asm volatile(
      "mma.sync.aligned.m16n8k8.row.col.f32.tf32.tf32.f32 "
      "{%0,%1,%2,%3},{%4,%5,%6,%7},{%8,%9},{%0,%1,%2,%3};"
      : "+f"(c[0]), "+f"(c[1]), "+f"(c[2]), "+f"(c[3])
      : "r"(a0), "r"(a1), "r"(a2), "r"(a3), "r"(b0), "r"(b1));
}

__device__ __forceinline__ void cpa16(void* dst, const void* src) {
    uint32_t d = (uint32_t)__cvta_generic_to_shared(dst);
    asm volatile("cp.async.ca.shared.global [%0], [%1], 16;" :: "r"(d), "l"(src));
}
__device__ __forceinline__ void cpa4(void* dst, const void* src) {
    uint32_t d = (uint32_t)__cvta_generic_to_shared(dst);
    asm volatile("cp.async.ca.shared.global [%0], [%1], 4;" :: "r"(d), "l"(src));
}
#define CP_COMMIT() asm volatile("cp.async.commit_group;")
template<int N> __device__ __forceinline__ void cp_wait() {
    asm volatile("cp.async.wait_group %0;" :: "n"(N));
}

/* ------------ mask dtype sniffing + conversion (+ float bias) ------------ */
__global__ void mask_convert_kernel(const void* __restrict__ mptr, int n,
                                    int* __restrict__ out, float* __restrict__ fb) {
    const unsigned char* b = (const unsigned char*)mptr;
    __shared__ int f32flag, nm4flag;
    if (threadIdx.x == 0) { f32flag = 0; nm4flag = 0; }
    __syncthreads();
    int lf = 0, ln4 = 0;
    for (int i = threadIdx.x; i < n; i += blockDim.x) {
        unsigned char c = b[i];
        if (c == 0x3Fu && (i & 3) == 3) lf = 1;
        if (c != 0u   && (i & 3) != 0) ln4 = 1;
    }
    if (lf)  atomicOr(&f32flag, 1);
    if (ln4) atomicOr(&nm4flag, 1);
    __syncthreads();
    int mode = f32flag ? 2 : (nm4flag ? 0 : 1);
    for (int i = threadIdx.x; i < n; i += blockDim.x) {
        int v;
        if      (mode == 0) v = (b[i] != 0);
        else if (mode == 1) v = (((const int*)mptr)[i]   != 0);
        else                v = (((const float*)mptr)[i] != 0.0f);
        out[i] = v;
        fb[i]  = v ? 0.0f : -1e30f;
    }
}

/* ------------ pack Wq|Wk|Wv -> [384][1152] ------------ */
__global__ void pack_qkv_kernel(const float* __restrict__ Wq, const float* __restrict__ Wk,
                                const float* __restrict__ Wv, const float* __restrict__ bq,
                                const float* __restrict__ bk, const float* __restrict__ bv,
                                float* __restrict__ Wp, float* __restrict__ bp) {
    int idx = blockIdx.x * 256 + threadIdx.x;
    if (idx < BDIM*QKVN) {
        int r = idx / QKVN, c = idx % QKVN;
        int sec = c / BDIM, cc = c % BDIM;
        float v = (sec == 0) ? Wq[r*BDIM+cc] : (sec == 1) ? Wk[r*BDIM+cc] : Wv[r*BDIM+cc];
        Wp[idx] = v;
    }
    if (idx < QKVN) {
        int sec = idx / BDIM, cc = idx % BDIM;
        bp[idx] = (sec == 0) ? bq[cc] : (sec == 1) ? bk[cc] : bv[cc];
    }
}

/* ------------ LayerNorm over 384 cols ------------ */
__device__ __forceinline__ float warp_sum(float v) {
    #pragma unroll
    for (int o = 16; o; o >>= 1) v += __shfl_xor_sync(0xffffffffu, v, o);
    return v;
}

__global__ void ln_kernel(const float* __restrict__ X,
                          const float* __restrict__ g,
                          const float* __restrict__ be,
                          float* __restrict__ Y) {
    int row = blockIdx.x;
    const float* x = X + (size_t)row * BDIM;
    float*       y = Y + (size_t)row * BDIM;
    int t = threadIdx.x;
    float v0 = x[t], v1 = x[t + 128], v2 = x[t + 256];
    float s  = v0 + v1 + v2;
    float sq = v0*v0 + v1*v1 + v2*v2;
    s = warp_sum(s); sq = warp_sum(sq);
    __shared__ float ss[4], sqq[4];
    int w = t >> 5, lane = t & 31;
    if (lane == 0) { ss[w] = s; sqq[w] = sq; }
    __syncthreads();
    float S  = ss[0] + ss[1] + ss[2] + ss[3];
    float SQ = sqq[0] + sqq[1] + sqq[2] + sqq[3];
    float mean = S * (1.0f / BDIM);
    float var  = SQ * (1.0f / BDIM) - mean * mean;
    float rstd = rsqrtf(var + 1e-5f);
    y[t      ] = (v0 - mean) * rstd * g[t      ] + be[t      ];
    y[t + 128] = (v1 - mean) * rstd * g[t + 128] + be[t + 128];
    y[t + 256] = (v2 - mean) * rstd * g[t + 256] + be[t + 256];
}

/* ------------ positional MLP: one warp per row, 8 rows/block ------------ */
__global__ __launch_bounds__(256)
void pe_kernel(const float* __restrict__ pos,
               const float* __restrict__ pw1, const float* __restrict__ pb1,
               const float* __restrict__ pw2, const float* __restrict__ pb2,
               float* __restrict__ pe) {
    __shared__ float w2s[HD*HD];
    __shared__ float w1s[3*HD], b1s[HD], b2s[HD];
    int tid = threadIdx.x, lane = tid & 31, w = tid >> 5;
    for (int i = tid; i < HD*HD; i += 256) w2s[i] = pw2[i];
    if (tid < 3*HD) w1s[tid] = pw1[tid];
    else if (tid < 4*HD) b1s[tid - 3*HD] = pb1[tid - 3*HD];
    else if (tid < 5*HD) b2s[tid - 4*HD] = pb2[tid - 4*HD];
    __syncthreads();
    int row = blockIdx.x*8 + w;
    float p0 = pos[row*3], p1 = pos[row*3+1], p2 = pos[row*3+2];
    float h0, h1 = 0.f;
    {
        int k = lane;
        h0 = gelu_exact(p0*w1s[k] + p1*w1s[HD+k] + p2*w1s[2*HD+k] + b1s[k]);
    }
    if (lane < 16) {
        int k = 32 + lane;
        h1 = gelu_exact(p0*w1s[k] + p1*w1s[HD+k] + p2*w1s[2*HD+k] + b1s[k]);
    }
    float acc0 = b2s[lane];
    float acc1 = (lane < 16) ? b2s[32 + lane] : 0.f;
    #pragma unroll 8
    for (int k = 0; k < HD; k++) {
        float hk = (k < 32) ? __shfl_sync(0xffffffffu, h0, k)
                            : __shfl_sync(0xffffffffu, h1, k - 32);
        acc0 += hk * w2s[k*HD + lane];
        if (lane < 16) acc1 += hk * w2s[k*HD + 32 + lane];
    }
    pe[(size_t)row*HD + lane] = acc0;
    if (lane < 16) pe[(size_t)row*HD + 32 + lane] = acc1;
}

/* ------------ tf32 tensor-core GEMM, 128x64x32, cp.async 2-stage ------------
   EPI 1: fused QKV scatter -> q/k/v[(b,h,n,d)] = acc+bias (+pe for K section)
   EPI 2: Wo           -> C = (acc+bias)*mask[row] + extra[row,col]
   EPI 3: MLP1         -> C = gelu(acc+bias)
   EPI 4: MLP2         -> C = (acc+bias+extra[row,col])*mask[row]            */
#define GBM 128
#define GBN 64
#define GBK 32
#define APAD 36
#define WPAD 72

template<int EPI>
__global__ __launch_bounds__(256, 3)
void gemm_tc(const float* __restrict__ A, const float* __restrict__ W,
             const float* __restrict__ bias, float* __restrict__ C,
             int K, int Nc,
             const float* __restrict__ extra, const int* __restrict__ mask,
             float* __restrict__ Ck, float* __restrict__ Cv) {
    __shared__ float As[2][GBM*APAD];
    __shared__ float Ws[2][GBK*WPAD];
    int tid = threadIdx.x, lane = tid & 31, w = tid >> 5;
    int g = lane >> 2, t = lane & 3;
    int wm = w >> 1, wn = w & 1;
    int bm = blockIdx.x * GBM, bn = blockIdx.y * GBN;

    float acc[2][4][4];
    #pragma unroll
    for (int mi = 0; mi < 2; mi++)
        #pragma unroll
        for (int nj = 0; nj < 4; nj++)
            #pragma unroll
            for (int r = 0; r < 4; r++) acc[mi][nj][r] = 0.f;

    int a_r = tid >> 3, a_c = (tid & 7) * 4;       /* rows 0..31 (+32i), cols */
    int w_r = tid >> 4, w_c = (tid & 15) * 4;      /* rows 0..15 (+16i) */

    /* prologue: stage 0 */
    {
        #pragma unroll
        for (int i = 0; i < 4; i++)
            cpa16(&As[0][(a_r + i*32)*APAD + a_c],
                  A + (size_t)(bm + a_r + i*32)*K + a_c);
        #pragma unroll
        for (int i = 0; i < 2; i++)
            cpa16(&Ws[0][(w_r + i*16)*WPAD + w_c],
                  W + (size_t)(w_r + i*16)*Nc + bn + w_c);
        CP_COMMIT();
    }

    int ntiles = K / GBK;
    for (int kt = 0; kt < ntiles; kt++) {
        __syncthreads();                   /* next stage buf free of readers */
        if (kt + 1 < ntiles) {
            int k0 = (kt + 1) * GBK, st = (kt + 1) & 1;
            #pragma unroll
            for (int i = 0; i < 4; i++)
                cpa16(&As[st][(a_r + i*32)*APAD + a_c],
                      A + (size_t)(bm + a_r + i*32)*K + k0 + a_c);
            #pragma unroll
            for (int i = 0; i < 2; i++)
                cpa16(&Ws[st][(w_r + i*16)*WPAD + w_c],
                      W + (size_t)(k0 + w_r + i*16)*Nc + bn + w_c);
            CP_COMMIT();
            cp_wait<1>();
        } else {
            cp_wait<0>();
        }
        __syncthreads();
        const float* as = As[kt & 1];
        const float* ws = Ws[kt & 1];

        #pragma unroll
        for (int ks = 0; ks < 4; ks++) {
            int kb = ks*8;
            uint32_t af[2][4];
            #pragma unroll
            for (int mi = 0; mi < 2; mi++) {
                int rb = wm*32 + mi*16 + g;
                af[mi][0] = __float_as_uint(as[rb*APAD + kb + t]);
                af[mi][1] = __float_as_uint(as[(rb+8)*APAD + kb + t]);
                af[mi][2] = __float_as_uint(as[rb*APAD + kb + t + 4]);
                af[mi][3] = __float_as_uint(as[(rb+8)*APAD + kb + t + 4]);
            }
            #pragma unroll
            for (int nj = 0; nj < 4; nj++) {
                int nb = wn*32 + nj*8 + g;
                uint32_t b0 = __float_as_uint(ws[(kb+t)*WPAD + nb]);
                uint32_t b1 = __float_as_uint(ws[(kb+t+4)*WPAD + nb]);
                mma8(acc[0][nj], af[0][0], af[0][1], af[0][2], af[0][3], b0, b1);
                mma8(acc[1][nj], af[1][0], af[1][1], af[1][2], af[1][3], b0, b1);
            }
        }
    }

    #pragma unroll
    for (int mi = 0; mi < 2; mi++) {
        #pragma unroll
        for (int half = 0; half < 2; half++) {
            int row = bm + wm*32 + mi*16 + g + half*8;
            #pragma unroll
            for (int nj = 0; nj < 4; nj++) {
                int col = bn + wn*32 + nj*8 + 2*t;
                float v0 = acc[mi][nj][half*2+0] + bias[col];
                float v1 = acc[mi][nj][half*2+1] + bias[col+1];
                if (EPI == 1) {
                    int sec = col / BDIM;
                    int c2  = col - sec*BDIM;
                    int d = c2 % HD, hh = c2 / HD;
                    if (sec == 1) {
                        v0 += extra[(size_t)row*HD + d];
                        v1 += extra[(size_t)row*HD + d + 1];
                    }
                    int bb = row >> 11, n = row & (NSEQ-1);
                    float* base = (sec == 0) ? C : (sec == 1) ? Ck : Cv;
                    float* p = base + (((size_t)(bb*HEADS + hh))*NSEQ + n)*HD + d;
                    p[0] = v0; p[1] = v1;
                } else if (EPI == 2) {
                    float m = (float)mask[row];
                    v0 = v0*m + extra[(size_t)row*Nc + col];
                    v1 = v1*m + extra[(size_t)row*Nc + col + 1];
                    float* p = C + (size_t)row*Nc + col;
                    p[0] = v0; p[1] = v1;
                } else if (EPI == 3) {
                    float* p = C + (size_t)row*Nc + col;
                    p[0] = gelu_exact(v0); p[1] = gelu_exact(v1);
                } else {
                    float m = (float)mask[row];
                    v0 = (v0 + extra[(size_t)row*Nc + col])*m;
                    v1 = (v1 + extra[(size_t)row*Nc + col + 1])*m;
                    float* p = C + (size_t)row*Nc + col;
                    p[0] = v0; p[1] = v1;
                }
            }
        }
    }
}

/* ------------ flash attention: 128 q-rows/block, warp-owned rows ------------
   8 warps x 16 rows; 64-key tiles, cp.async double-buffered K/V/maskbias;
   softmax fully in registers (quad shuffles); P in warp-private smem.       */
#define KPAD 52
#define VPAD 56
#define PPAD 68
#define BQ 128
#define NT (NSEQ/64)
#define ATT_F_KS 0
#define ATT_F_VS (2*64*KPAD)                      /* 6656 */
#define ATT_F_MB (ATT_F_VS + 2*64*VPAD)           /* 13824 */
#define ATT_F_PS (ATT_F_MB + 2*64)                /* 13952 */
#define ATT_SMEM ((ATT_F_PS + 8*16*PPAD) * 4)     /* 90624 B */

__global__ __launch_bounds__(256, 2)
void attn_tc(const float* __restrict__ Q, const float* __restrict__ Kb,
             const float* __restrict__ Vb, const float* __restrict__ mb,
             float* __restrict__ O) {
    extern __shared__ float sm[];
    float* Ks  = sm + ATT_F_KS;
    float* Vs  = sm + ATT_F_VS;
    float* MBs = sm + ATT_F_MB;
    float* Ps  = sm + ATT_F_PS;

    int bh = blockIdx.y, b = bh >> 3, h = bh & 7;
    int q0 = blockIdx.x * BQ;
    int tid = threadIdx.x, lane = tid & 31, w = tid >> 5;
    int g = lane >> 2, t = lane & 3;
    const float* qp = Q  + (size_t)bh * NSEQ * HD;
    const float* kp = Kb + (size_t)bh * NSEQ * HD;
    const float* vp = Vb + (size_t)bh * NSEQ * HD;
    const float* mbp = mb + b * NSEQ;

    /* stage Q (raw f32) into Ps region, extract fragments */
    #pragma unroll
    for (int i = 0; i < 6; i++) {
        int idx = tid + i*256;
        int r = idx / 12, c4 = (idx % 12) * 4;
        *(float4*)(Ps + r*KPAD + c4) = *(const float4*)(qp + (size_t)(q0 + r)*HD + c4);
    }
    __syncthreads();
    uint32_t qf[6][4];
    {
        int rq = w*16 + g;
        #pragma unroll
        for (int ks = 0; ks < 6; ks++) {
            int kb = ks*8;
            qf[ks][0] = __float_as_uint(Ps[rq*KPAD + kb + t]);
            qf[ks][1] = __float_as_uint(Ps[(rq+8)*KPAD + kb + t]);
            qf[ks][2] = __float_as_uint(Ps[rq*KPAD + kb + t + 4]);
            qf[ks][3] = __float_as_uint(Ps[(rq+8)*KPAD + kb + t + 4]);
        }
    }
    __syncthreads();   /* Ps reused for P below */

    float o[6][4];
    #pragma unroll
    for (int nj = 0; nj < 6; nj++)
        #pragma unroll
        for (int r = 0; r < 4; r++) o[nj][r] = 0.f;
    float mA = -INFINITY, mB = -INFINITY, lA = 0.f, lB = 0.f;
    const float scale = 0.14433756729740643f;   /* 48^-0.5 */

    /* prologue: stage 0 */
    {
        #pragma unroll
        for (int i = 0; i < 3; i++) {
            int idx = tid + i*256;
            int r = idx / 12, c4 = (idx % 12) * 4;
            cpa16(Ks + r*KPAD + c4, kp + (size_t)r*HD + c4);
            cpa16(Vs + r*VPAD + c4, vp + (size_t)r*HD + c4);
        }
        if (tid < 64) cpa4(MBs + tid, mbp + tid);
        CP_COMMIT();
    }

    for (int kt = 0; kt < NT; kt++) {
        __syncthreads();                /* next-stage buffers free of readers */
        if (kt + 1 < NT) {
            int st = (kt + 1) & 1, k0 = (kt + 1) * 64;
            #pragma unroll
            for (int i = 0; i < 3; i++) {
                int idx = tid + i*256;
                int r = idx / 12, c4 = (idx % 12) * 4;
                cpa16(Ks + st*64*KPAD + r*KPAD + c4, kp + (size_t)(k0 + r)*HD + c4);
                cpa16(Vs + st*64*VPAD + r*VPAD + c4, vp + (size_t)(k0 + r)*HD + c4);
            }
            if (tid < 64) cpa4(MBs + st*64 + tid, mbp + k0 + tid);
            CP_COMMIT();
            cp_wait<1>();
        } else {
            cp_wait<0>();
        }
        __syncthreads();
        int st = kt & 1;
        const float* Kst  = Ks + st*64*KPAD;
        const float* Vst  = Vs + st*64*VPAD;
        const float* MBst = MBs + st*64;

        /* S = Q K^T : warp tile 16x64 */
        float s[8][4];
        #pragma unroll
        for (int nj = 0; nj < 8; nj++)
            #pragma unroll
            for (int r = 0; r < 4; r++) s[nj][r] = 0.f;
        #pragma unroll
        for (int ks = 0; ks < 6; ks++) {
            int kb = ks*8;
            #pragma unroll
            for (int nj = 0; nj < 8; nj++) {
                int nb = nj*8 + g;
                uint32_t b0 = __float_as_uint(Kst[nb*KPAD + kb + t]);
                uint32_t b1 = __float_as_uint(Kst[nb*KPAD + kb + t + 4]);
                mma8(s[nj], qf[ks][0], qf[ks][1], qf[ks][2], qf[ks][3], b0, b1);
            }
        }

        /* scale + mask bias, row max */
        float mxA = -INFINITY, mxB = -INFINITY;
        #pragma unroll
        for (int nj = 0; nj < 8; nj++) {
            float2 mbv = *(const float2*)(MBst + nj*8 + 2*t);
            s[nj][0] = s[nj][0]*scale + mbv.x;
            s[nj][1] = s[nj][1]*scale + mbv.y;
            s[nj][2] = s[nj][2]*scale + mbv.x;
            s[nj][3] = s[nj][3]*scale + mbv.y;
            mxA = fmaxf(mxA, fmaxf(s[nj][0], s[nj][1]));
            mxB = fmaxf(mxB, fmaxf(s[nj][2], s[nj][3]));
        }
        mxA = fmaxf(mxA, __shfl_xor_sync(0xffffffffu, mxA, 1));
        mxA = fmaxf(mxA, __shfl_xor_sync(0xffffffffu, mxA, 2));
        mxB = fmaxf(mxB, __shfl_xor_sync(0xffffffffu, mxB, 1));
        mxB = fmaxf(mxB, __shfl_xor_sync(0xffffffffu, mxB, 2));

        float mAn = fmaxf(mA, mxA), fA = __expf(mA - mAn);
        float mBn = fmaxf(mB, mxB), fB = __expf(mB - mBn);
        mA = mAn; mB = mBn;
        lA *= fA;  lB *= fB;

        /* P = exp(S - m), write to warp-private smem (raw f32 -> tf32 trunc) */
        float* Pw = Ps + w*16*PPAD;
        #pragma unroll
        for (int nj = 0; nj < 8; nj++) {
            float p0 = __expf(s[nj][0] - mA);
            float p1 = __expf(s[nj][1] - mA);
            float p2 = __expf(s[nj][2] - mB);
            float p3 = __expf(s[nj][3] - mB);
            lA += p0 + p1; lB += p2 + p3;
            *(float2*)(Pw + g*PPAD     + nj*8 + 2*t) = make_float2(p0, p1);
            *(float2*)(Pw + (g+8)*PPAD + nj*8 + 2*t) = make_float2(p2, p3);
        }
        /* rescale output accumulators */
        #pragma unroll
        for (int nj = 0; nj < 6; nj++) {
            o[nj][0] *= fA; o[nj][1] *= fA;
            o[nj][2] *= fB; o[nj][3] *= fB;
        }
        __syncwarp();

        /* O += P V : warp tile 16x48 */
        #pragma unroll
        for (int ks = 0; ks < 8; ks++) {
            int kb = ks*8;
            uint32_t a0 = __float_as_uint(Pw[g*PPAD + kb + t]);
            uint32_t a1 = __float_as_uint(Pw[(g+8)*PPAD + kb + t]);
            uint32_t a2 = __float_as_uint(Pw[g*PPAD + kb + t + 4]);
            uint32_t a3 = __float_as_uint(Pw[(g+8)*PPAD + kb + t + 4]);
            #pragma unroll
            for (int nj = 0; nj < 6; nj++) {
                int nb = nj*8 + g;
                uint32_t b0 = __float_as_uint(Vst[(kb+t)*VPAD + nb]);
                uint32_t b1 = __float_as_uint(Vst[(kb+t+4)*VPAD + nb]);
                mma8(o[nj], a0, a1, a2, a3, b0, b1);
            }
        }
    }

    /* epilogue: reduce l across quad, divide, store */
    lA += __shfl_xor_sync(0xffffffffu, lA, 1);
    lA += __shfl_xor_sync(0xffffffffu, lA, 2);
    lB += __shfl_xor_sync(0xffffffffu, lB, 1);
    lB += __shfl_xor_sync(0xffffffffu, lB, 2);
    float invA = 1.0f / lA, invB = 1.0f / lB;
    int rA = q0 + w*16 + g, rB = rA + 8;
    #pragma unroll
    for (int nj = 0; nj < 6; nj++) {
        int cb = nj*8 + 2*t;
        *(float2*)(O + ((size_t)(b*NSEQ + rA))*BDIM + h*HD + cb) =
            make_float2(o[nj][0]*invA, o[nj][1]*invA);
        *(float2*)(O + ((size_t)(b*NSEQ + rB))*BDIM + h*HD + cb) =
            make_float2(o[nj][2]*invB, o[nj][3]*invB);
    }
}

/* ------------------------------ launch ------------------------------ */
extern "C" void kernel_launch(void* const* d_in, const int* in_sizes, int n_in,
                              void* d_out, int out_size) {
    const float* x    = (const float*)d_in[0];
    const float* pos  = (const float*)d_in[1];
    const void*  mask = d_in[2];
    const float* Wq   = (const float*)d_in[3];
    const float* bq   = (const float*)d_in[4];
    const float* Wk   = (const float*)d_in[5];
    const float* bk   = (const float*)d_in[6];
    const float* Wv   = (const float*)d_in[7];
    const float* bv   = (const float*)d_in[8];
    const float* pw1  = (const float*)d_in[9];
    const float* pb1  = (const float*)d_in[10];
    const float* pw2  = (const float*)d_in[11];
    const float* pb2  = (const float*)d_in[12];
    const float* Wo   = (const float*)d_in[13];
    const float* bo   = (const float*)d_in[14];
    const float* mw1  = (const float*)d_in[15];
    const float* mb1  = (const float*)d_in[16];
    const float* mw2  = (const float*)d_in[17];
    const float* mb2  = (const float*)d_in[18];
    const float* g1   = (const float*)d_in[19];
    const float* be1  = (const float*)d_in[20];
    const float* g2   = (const float*)d_in[21];
    const float* be2  = (const float*)d_in[22];
    float* out = (float*)d_out;

    void *ph, *pq, *pk, *pv, *ppe, *patt, *px1, *phid, *pm, *pmb, *pwq, *pbq;
    cudaGetSymbolAddress(&ph,  g_h);
    cudaGetSymbolAddress(&pq,  g_q);
    cudaGetSymbolAddress(&pk,  g_k);
    cudaGetSymbolAddress(&pv,  g_v);
    cudaGetSymbolAddress(&ppe, g_pe);
    cudaGetSymbolAddress(&patt,g_att);
    cudaGetSymbolAddress(&px1, g_x1);
    cudaGetSymbolAddress(&phid,g_hid);
    cudaGetSymbolAddress(&pm,  g_mask);
    cudaGetSymbolAddress(&pmb, g_mb);
    cudaGetSymbolAddress(&pwq, g_wqkv);
    cudaGetSymbolAddress(&pbq, g_bqkv);
    float* h    = (float*)ph;
    float* q    = (float*)pq;
    float* k    = (float*)pk;
    float* v    = (float*)pv;
    float* pe   = (float*)ppe;
    float* att  = (float*)patt;
    float* x1   = (float*)px1;
    float* hid  = (float*)phid;
    int*   msk  = (int*)pm;
    float* mbf  = (float*)pmb;
    float* wqkv = (float*)pwq;
    float* bqkv = (float*)pbq;

    cudaFuncSetAttribute(attn_tc,
                         cudaFuncAttributeMaxDynamicSharedMemorySize, ATT_SMEM);

    /* 1. mask (+float bias) */
    mask_convert_kernel<<<1, 256>>>(mask, MROWS, msk, mbf);
    /* 2. pack QKV weights */
    pack_qkv_kernel<<<(BDIM*QKVN + 255)/256, 256>>>(Wq, Wk, Wv, bq, bk, bv, wqkv, bqkv);
    /* 3. LN1 */
    ln_kernel<<<MROWS, 128>>>(x, g1, be1, h);
    /* 4. positional MLP */
    pe_kernel<<<MROWS/8, 256>>>(pos, pw1, pb1, pw2, pb2, pe);
    /* 5. fused QKV projection */
    dim3 gqkv(MROWS/GBM, QKVN/GBN);
    gemm_tc<1><<<gqkv, 256>>>(h, wqkv, bqkv, q, BDIM, QKVN, pe, nullptr, k, v);
    /* 6. attention */
    dim3 ga(NSEQ/BQ, NB*HEADS);
    attn_tc<<<ga, 256, ATT_SMEM>>>(q, k, v, mbf, att);
    /* 7. Wo + mask + residual -> x1 */
    dim3 gwo(MROWS/GBM, BDIM/GBN);
    gemm_tc<2><<<gwo, 256>>>(att, Wo, bo, x1, BDIM, BDIM, x, msk, nullptr, nullptr);
    /* 8. LN2 */
    ln_kernel<<<MROWS, 128>>>(x1, g2, be2, h);
    /* 9. MLP1 + gelu */
    dim3 gm1(MROWS/GBM, MLPH/GBN);
    gemm_tc<3><<<gm1, 256>>>(h, mw1, mb1, hid, BDIM, MLPH, nullptr, nullptr, nullptr, nullptr);
    /* 10. MLP2 + residual + mask -> out */
    gemm_tc<4><<<gwo, 256>>>(hid, mw2, mb2, out, MLPH, BDIM, x1, msk, nullptr, nullptr);
}

// round 6
// speedup vs baseline: 1.4556x; 1.4556x over previous
#include <cuda_runtime.h>
#include <cuda_fp16.h>
#include <math.h>
#include <stdint.h>

#define BDIM 384
#define HEADS 8
#define HD 48
#define NSEQ 2048
#define NB 4
#define MROWS (NB*NSEQ)      /* 8192 */
#define MLPH 1536
#define QKVN (3*BDIM)        /* 1152 */

/* ------------ scratch (device globals; no allocation allowed) ------------ */
__device__ __half g_h16 [MROWS*BDIM];
__device__ __half g_q16 [MROWS*BDIM];
__device__ __half g_k16 [MROWS*BDIM];
__device__ __half g_v16t[MROWS*BDIM];          /* V^T: [bh][d][n] */
__device__ __half g_att16[MROWS*BDIM];
__device__ __half g_hid16[MROWS*MLPH];
__device__ __half g_wqkvT[QKVN*BDIM];
__device__ __half g_woT  [BDIM*BDIM];
__device__ __half g_mw1T [MLPH*BDIM];
__device__ __half g_mw2T [BDIM*MLPH];
__device__ float  g_pe[MROWS*HD];
__device__ float  g_x1[MROWS*BDIM];
__device__ int    g_mask[MROWS];
__device__ float  g_mb [MROWS];
__device__ float  g_bqkv[QKVN];

__device__ __forceinline__ float gelu_exact(float x) {
    return 0.5f * x * (1.0f + erff(x * 0.70710678118654752f));
}

/* m16n8k16 fp16 mma, fp32 accumulate. regs are packed half2. */
__device__ __forceinline__ void mma16(float* c,
                                      uint32_t a0, uint32_t a1, uint32_t a2, uint32_t a3,
                                      uint32_t b0, uint32_t b1) {
    asm volatile(
      "mma.sync.aligned.m16n8k16.row.col.f32.f16.f16.f32 "
      "{%0,%1,%2,%3},{%4,%5,%6,%7},{%8,%9},{%0,%1,%2,%3};"
      : "+f"(c[0]), "+f"(c[1]), "+f"(c[2]), "+f"(c[3])
      : "r"(a0), "r"(a1), "r"(a2), "r"(a3), "r"(b0), "r"(b1));
}

__device__ __forceinline__ void cpa16(void* dst, const void* src) {
    uint32_t d = (uint32_t)__cvta_generic_to_shared(dst);
    asm volatile("cp.async.ca.shared.global [%0], [%1], 16;" :: "r"(d), "l"(src));
}
__device__ __forceinline__ void cpa4(void* dst, const void* src) {
    uint32_t d = (uint32_t)__cvta_generic_to_shared(dst);
    asm volatile("cp.async.ca.shared.global [%0], [%1], 4;" :: "r"(d), "l"(src));
}
#define CP_COMMIT() asm volatile("cp.async.commit_group;")
template<int N> __device__ __forceinline__ void cp_wait() {
    asm volatile("cp.async.wait_group %0;" :: "n"(N));
}
__device__ __forceinline__ uint32_t h2pack(float a, float b) {
    __half2 h = __floats2half2_rn(a, b);
    return *(uint32_t*)&h;
}

/* ------------ mask dtype sniffing + conversion (+ float bias) ------------ */
__global__ void mask_convert_kernel(const void* __restrict__ mptr, int n,
                                    int* __restrict__ out, float* __restrict__ fb) {
    const unsigned char* b = (const unsigned char*)mptr;
    __shared__ int f32flag, nm4flag;
    if (threadIdx.x == 0) { f32flag = 0; nm4flag = 0; }
    __syncthreads();
    int lf = 0, ln4 = 0;
    for (int i = threadIdx.x; i < n; i += blockDim.x) {
        unsigned char c = b[i];
        if (c == 0x3Fu && (i & 3) == 3) lf = 1;
        if (c != 0u   && (i & 3) != 0) ln4 = 1;
    }
    if (lf)  atomicOr(&f32flag, 1);
    if (ln4) atomicOr(&nm4flag, 1);
    __syncthreads();
    int mode = f32flag ? 2 : (nm4flag ? 0 : 1);
    for (int i = threadIdx.x; i < n; i += blockDim.x) {
        int v;
        if      (mode == 0) v = (b[i] != 0);
        else if (mode == 1) v = (((const int*)mptr)[i]   != 0);
        else                v = (((const float*)mptr)[i] != 0.0f);
        out[i] = v;
        fb[i]  = v ? 0.0f : -1e30f;
    }
}

/* ------------ tiled transpose f32[K][N] -> fp16[N][K] ------------ */
__global__ void transpose_h_kernel(const float* __restrict__ W, __half* __restrict__ Wt,
                                   int K, int N) {
    __shared__ float tile[32][33];
    int k0 = blockIdx.y*32, n0 = blockIdx.x*32;
    int tx = threadIdx.x, ty = threadIdx.y;          /* 32 x 8 */
    #pragma unroll
    for (int i = 0; i < 32; i += 8)
        tile[ty+i][tx] = W[(size_t)(k0+ty+i)*N + n0+tx];
    __syncthreads();
    #pragma unroll
    for (int i = 0; i < 32; i += 8)
        Wt[(size_t)(n0+ty+i)*K + k0+tx] = __float2half_rn(tile[tx][ty+i]);
}

__global__ void pack_bias_kernel(const float* __restrict__ bq, const float* __restrict__ bk,
                                 const float* __restrict__ bv, float* __restrict__ bp) {
    int i = blockIdx.x*256 + threadIdx.x;
    if (i < QKVN) {
        int sec = i / BDIM, c = i % BDIM;
        bp[i] = (sec == 0) ? bq[c] : (sec == 1) ? bk[c] : bv[c];
    }
}

/* ------------ LayerNorm over 384 cols -> fp16 ------------ */
__device__ __forceinline__ float warp_sum(float v) {
    #pragma unroll
    for (int o = 16; o; o >>= 1) v += __shfl_xor_sync(0xffffffffu, v, o);
    return v;
}

__global__ void ln_kernel(const float* __restrict__ X,
                          const float* __restrict__ g,
                          const float* __restrict__ be,
                          __half* __restrict__ Y) {
    int row = blockIdx.x;
    const float* x = X + (size_t)row * BDIM;
    __half*      y = Y + (size_t)row * BDIM;
    int t = threadIdx.x;
    float v0 = x[t], v1 = x[t + 128], v2 = x[t + 256];
    float s  = v0 + v1 + v2;
    float sq = v0*v0 + v1*v1 + v2*v2;
    s = warp_sum(s); sq = warp_sum(sq);
    __shared__ float ss[4], sqq[4];
    int w = t >> 5, lane = t & 31;
    if (lane == 0) { ss[w] = s; sqq[w] = sq; }
    __syncthreads();
    float S  = ss[0] + ss[1] + ss[2] + ss[3];
    float SQ = sqq[0] + sqq[1] + sqq[2] + sqq[3];
    float mean = S * (1.0f / BDIM);
    float var  = SQ * (1.0f / BDIM) - mean * mean;
    float rstd = rsqrtf(var + 1e-5f);
    y[t      ] = __float2half_rn((v0 - mean) * rstd * g[t      ] + be[t      ]);
    y[t + 128] = __float2half_rn((v1 - mean) * rstd * g[t + 128] + be[t + 128]);
    y[t + 256] = __float2half_rn((v2 - mean) * rstd * g[t + 256] + be[t + 256]);
}

/* ------------ positional MLP: one warp per row ------------ */
__global__ __launch_bounds__(256)
void pe_kernel(const float* __restrict__ pos,
               const float* __restrict__ pw1, const float* __restrict__ pb1,
               const float* __restrict__ pw2, const float* __restrict__ pb2,
               float* __restrict__ pe) {
    __shared__ float w2s[HD*HD];
    __shared__ float w1s[3*HD], b1s[HD], b2s[HD];
    int tid = threadIdx.x, lane = tid & 31, w = tid >> 5;
    for (int i = tid; i < HD*HD; i += 256) w2s[i] = pw2[i];
    if (tid < 3*HD) w1s[tid] = pw1[tid];
    else if (tid < 4*HD) b1s[tid - 3*HD] = pb1[tid - 3*HD];
    else if (tid < 5*HD) b2s[tid - 4*HD] = pb2[tid - 4*HD];
    __syncthreads();
    int row = blockIdx.x*8 + w;
    float p0 = pos[row*3], p1 = pos[row*3+1], p2 = pos[row*3+2];
    float h0, h1 = 0.f;
    {
        int k = lane;
        h0 = gelu_exact(p0*w1s[k] + p1*w1s[HD+k] + p2*w1s[2*HD+k] + b1s[k]);
    }
    if (lane < 16) {
        int k = 32 + lane;
        h1 = gelu_exact(p0*w1s[k] + p1*w1s[HD+k] + p2*w1s[2*HD+k] + b1s[k]);
    }
    float acc0 = b2s[lane];
    float acc1 = (lane < 16) ? b2s[32 + lane] : 0.f;
    #pragma unroll 8
    for (int k = 0; k < HD; k++) {
        float hk = (k < 32) ? __shfl_sync(0xffffffffu, h0, k)
                            : __shfl_sync(0xffffffffu, h1, k - 32);
        acc0 += hk * w2s[k*HD + lane];
        if (lane < 16) acc1 += hk * w2s[k*HD + 32 + lane];
    }
    pe[(size_t)row*HD + lane] = acc0;
    if (lane < 16) pe[(size_t)row*HD + 32 + lane] = acc1;
}

/* ------------ fp16 tensor-core GEMM: 128x64x32, A[m][k], B=W^T[n][k] -------
   smem strides 40 halves (conflict-free in half2: banks 20g+t / 4g+t).
   EPI 1: QKV -> q16/k16 (+pe on K) fp16 [bh][n][d]; v16t fp16 [bh][d][n]
   EPI 2: Wo  -> x1 = acc*mask + x (f32)
   EPI 3: MLP1-> hid16 = gelu fp16
   EPI 4: MLP2-> out = (acc + x1)*mask (f32)                                 */
#define GBM 128
#define GBN 64
#define GBK 32
#define APADH 40
#define BPADH 40

template<int EPI>
__global__ __launch_bounds__(256, 3)
void gemm_tc(const __half* __restrict__ A, const __half* __restrict__ Bt,
             const float* __restrict__ bias,
             int K, int Nc,
             const float* __restrict__ extra, const int* __restrict__ mask,
             float* __restrict__ Cf, __half* __restrict__ Ch,
             __half* __restrict__ Ck, __half* __restrict__ Cv) {
    __shared__ __half As[2][GBM*APADH];
    __shared__ __half Bs[2][GBN*BPADH];
    int tid = threadIdx.x, lane = tid & 31, w = tid >> 5;
    int g = lane >> 2, t = lane & 3;
    int wm = w >> 1, wn = w & 1;
    int bm = blockIdx.x * GBM, bn = blockIdx.y * GBN;

    float acc[2][4][4];
    #pragma unroll
    for (int mi = 0; mi < 2; mi++)
        #pragma unroll
        for (int nj = 0; nj < 4; nj++)
            #pragma unroll
            for (int r = 0; r < 4; r++) acc[mi][nj][r] = 0.f;

    int a_r = tid >> 2, a_c = (tid & 3) * 8;   /* +128 rows on second pass */
    int b_r = tid >> 2, b_c = (tid & 3) * 8;   /* 64 rows x 4 chunks = 256 */

    /* prologue: stage 0 */
    cpa16(&As[0][a_r*APADH + a_c], A + (size_t)(bm + a_r)*K + a_c);
    cpa16(&As[0][(a_r+64)*APADH + a_c], A + (size_t)(bm + a_r + 64)*K + a_c);
    cpa16(&Bs[0][b_r*BPADH + b_c], Bt + (size_t)(bn + b_r)*K + b_c);
    CP_COMMIT();

    int ntiles = K / GBK;
    for (int kt = 0; kt < ntiles; kt++) {
        __syncthreads();
        if (kt + 1 < ntiles) {
            int k0 = (kt + 1) * GBK, st = (kt + 1) & 1;
            cpa16(&As[st][a_r*APADH + a_c], A + (size_t)(bm + a_r)*K + k0 + a_c);
            cpa16(&As[st][(a_r+64)*APADH + a_c], A + (size_t)(bm + a_r + 64)*K + k0 + a_c);
            cpa16(&Bs[st][b_r*BPADH + b_c], Bt + (size_t)(bn + b_r)*K + k0 + b_c);
            CP_COMMIT();
            cp_wait<1>();
        } else {
            cp_wait<0>();
        }
        __syncthreads();
        const __half* as = As[kt & 1];
        const __half* bs = Bs[kt & 1];

        #pragma unroll
        for (int ks = 0; ks < 2; ks++) {
            int kb = ks*16 + 2*t;
            uint32_t af[2][4];
            #pragma unroll
            for (int mi = 0; mi < 2; mi++) {
                int rb = wm*32 + mi*16 + g;
                af[mi][0] = *(const uint32_t*)(as + rb*APADH + kb);
                af[mi][1] = *(const uint32_t*)(as + (rb+8)*APADH + kb);
                af[mi][2] = *(const uint32_t*)(as + rb*APADH + kb + 8);
                af[mi][3] = *(const uint32_t*)(as + (rb+8)*APADH + kb + 8);
            }
            #pragma unroll
            for (int nj = 0; nj < 4; nj++) {
                int nb = wn*32 + nj*8 + g;
                uint32_t b0 = *(const uint32_t*)(bs + nb*BPADH + kb);
                uint32_t b1 = *(const uint32_t*)(bs + nb*BPADH + kb + 8);
                mma16(acc[0][nj], af[0][0], af[0][1], af[0][2], af[0][3], b0, b1);
                mma16(acc[1][nj], af[1][0], af[1][1], af[1][2], af[1][3], b0, b1);
            }
        }
    }

    #pragma unroll
    for (int mi = 0; mi < 2; mi++) {
        #pragma unroll
        for (int half = 0; half < 2; half++) {
            int row = bm + wm*32 + mi*16 + g + half*8;
            #pragma unroll
            for (int nj = 0; nj < 4; nj++) {
                int col = bn + wn*32 + nj*8 + 2*t;
                float v0 = acc[mi][nj][half*2+0] + bias[col];
                float v1 = acc[mi][nj][half*2+1] + bias[col+1];
                if (EPI == 1) {
                    int sec = col / BDIM;
                    int c2  = col - sec*BDIM;
                    int d = c2 % HD, hh = c2 / HD;
                    int bb = row >> 11, n = row & (NSEQ-1);
                    if (sec == 2) {
                        __half* p = Cv + ((size_t)((bb*HEADS + hh)*HD + d))*NSEQ + n;
                        p[0]    = __float2half_rn(v0);
                        p[NSEQ] = __float2half_rn(v1);
                    } else {
                        if (sec == 1) {
                            v0 += extra[(size_t)row*HD + d];
                            v1 += extra[(size_t)row*HD + d + 1];
                        }
                        __half* base = (sec == 0) ? Ch : Ck;
                        __half* p = base + (((size_t)(bb*HEADS + hh))*NSEQ + n)*HD + d;
                        *(uint32_t*)p = h2pack(v0, v1);
                    }
                } else if (EPI == 2) {
                    float m = (float)mask[row];
                    v0 = v0*m + extra[(size_t)row*Nc + col];
                    v1 = v1*m + extra[(size_t)row*Nc + col + 1];
                    float* p = Cf + (size_t)row*Nc + col;
                    p[0] = v0; p[1] = v1;
                } else if (EPI == 3) {
                    *(uint32_t*)(Ch + (size_t)row*Nc + col) =
                        h2pack(gelu_exact(v0), gelu_exact(v1));
                } else {
                    float m = (float)mask[row];
                    v0 = (v0 + extra[(size_t)row*Nc + col])*m;
                    v1 = (v1 + extra[(size_t)row*Nc + col + 1])*m;
                    float* p = Cf + (size_t)row*Nc + col;
                    p[0] = v0; p[1] = v1;
                }
            }
        }
    }
}

/* ------------ flash attention (fp16 mma): 128 q-rows/block ------------
   8 warps x 16 rows; K fp16 [n][d] smem stride 56; V^T fp16 [d][n] stride 72;
   P fp16 warp-private stride 72; mask bias f32; all double-buffered.        */
#define KPADH 56
#define VTPADH 72
#define PPADH 72
#define BQ 128
#define NT (NSEQ/64)
/* halves offsets */
#define ATT_H_KS 0
#define ATT_H_VT (2*64*KPADH)                        /* 7168  */
#define ATT_H_PS (ATT_H_VT + 2*48*VTPADH)            /* 14080 */
#define ATT_H_END (ATT_H_PS + 8*16*PPADH)            /* 23296 halves */
#define ATT_MB_OFF ATT_H_END                         /* f32 x 128 after */
#define ATT_SMEM (ATT_H_END*2 + 2*64*4)              /* 47104 B */

__global__ __launch_bounds__(256, 2)
void attn_tc(const __half* __restrict__ Q, const __half* __restrict__ Kb,
             const __half* __restrict__ Vt, const float* __restrict__ mb,
             __half* __restrict__ O) {
    extern __shared__ __half smh[];
    __half* Ks  = smh + ATT_H_KS;
    __half* Vts = smh + ATT_H_VT;
    __half* Ps  = smh + ATT_H_PS;
    float*  MBs = (float*)(smh + ATT_MB_OFF);

    int bh = blockIdx.y, b = bh >> 3, h = bh & 7;
    int q0 = blockIdx.x * BQ;
    int tid = threadIdx.x, lane = tid & 31, w = tid >> 5;
    int g = lane >> 2, t = lane & 3;
    const __half* qp = Q  + (size_t)bh * NSEQ * HD;
    const __half* kp = Kb + (size_t)bh * NSEQ * HD;
    const __half* vp = Vt + (size_t)bh * NSEQ * HD;   /* [d][n] */
    const float* mbp = mb + b * NSEQ;

    /* stage Q into Ps region ([128][56] halves), extract fragments */
    #pragma unroll
    for (int i = 0; i < 3; i++) {
        int idx = tid + i*256;                /* 768 chunks of 16B */
        int r = idx / 6, c = (idx % 6) * 8;
        *(uint4*)(Ps + r*KPADH + c) = *(const uint4*)(qp + (size_t)(q0 + r)*HD + c);
    }
    __syncthreads();
    uint32_t qf[3][4];
    {
        int rq = w*16 + g;
        #pragma unroll
        for (int ks = 0; ks < 3; ks++) {
            int kb = ks*16 + 2*t;
            qf[ks][0] = *(const uint32_t*)(Ps + rq*KPADH + kb);
            qf[ks][1] = *(const uint32_t*)(Ps + (rq+8)*KPADH + kb);
            qf[ks][2] = *(const uint32_t*)(Ps + rq*KPADH + kb + 8);
            qf[ks][3] = *(const uint32_t*)(Ps + (rq+8)*KPADH + kb + 8);
        }
    }
    __syncthreads();   /* Ps reused for P */

    float o[6][4];
    #pragma unroll
    for (int nj = 0; nj < 6; nj++)
        #pragma unroll
        for (int r = 0; r < 4; r++) o[nj][r] = 0.f;
    float mA = -INFINITY, mB = -INFINITY, lA = 0.f, lB = 0.f;
    const float scale = 0.14433756729740643f;   /* 48^-0.5 */

    /* prologue: stage 0.  K tile: 64 rows x 6 chunks = 384.
       V^T tile: 48 rows x 8 chunks = 384. */
    {
        #pragma unroll
        for (int i = 0; i < 2; i++) {
            int idx = tid + i*256;
            if (idx < 384) {
                int r = idx / 6, c = (idx % 6) * 8;
                cpa16(Ks + r*KPADH + c, kp + (size_t)r*HD + c);
                int rv = idx >> 3, cv = (idx & 7) * 8;
                cpa16(Vts + rv*VTPADH + cv, vp + (size_t)rv*NSEQ + cv);
            }
        }
        if (tid < 64) cpa4(MBs + tid, mbp + tid);
        CP_COMMIT();
    }

    for (int kt = 0; kt < NT; kt++) {
        __syncthreads();
        if (kt + 1 < NT) {
            int st = (kt + 1) & 1, k0 = (kt + 1) * 64;
            #pragma unroll
            for (int i = 0; i < 2; i++) {
                int idx = tid + i*256;
                if (idx < 384) {
                    int r = idx / 6, c = (idx % 6) * 8;
                    cpa16(Ks + st*64*KPADH + r*KPADH + c, kp + (size_t)(k0 + r)*HD + c);
                    int rv = idx >> 3, cv = (idx & 7) * 8;
                    cpa16(Vts + st*48*VTPADH + rv*VTPADH + cv,
                          vp + (size_t)rv*NSEQ + k0 + cv);
                }
            }
            if (tid < 64) cpa4(MBs + st*64 + tid, mbp + k0 + tid);
            CP_COMMIT();
            cp_wait<1>();
        } else {
            cp_wait<0>();
        }
        __syncthreads();
        int st = kt & 1;
        const __half* Kst  = Ks + st*64*KPADH;
        const __half* Vst  = Vts + st*48*VTPADH;
        const float*  MBst = MBs + st*64;

        /* S = Q K^T : warp tile 16x64 */
        float s[8][4];
        #pragma unroll
        for (int nj = 0; nj < 8; nj++)
            #pragma unroll
            for (int r = 0; r < 4; r++) s[nj][r] = 0.f;
        #pragma unroll
        for (int ks = 0; ks < 3; ks++) {
            int kb = ks*16 + 2*t;
            #pragma unroll
            for (int nj = 0; nj < 8; nj++) {
                int nb = nj*8 + g;
                uint32_t b0 = *(const uint32_t*)(Kst + nb*KPADH + kb);
                uint32_t b1 = *(const uint32_t*)(Kst + nb*KPADH + kb + 8);
                mma16(s[nj], qf[ks][0], qf[ks][1], qf[ks][2], qf[ks][3], b0, b1);
            }
        }

        /* scale + mask bias, row max */
        float mxA = -INFINITY, mxB = -INFINITY;
        #pragma unroll
        for (int nj = 0; nj < 8; nj++) {
            float2 mbv = *(const float2*)(MBst + nj*8 + 2*t);
            s[nj][0] = s[nj][0]*scale + mbv.x;
            s[nj][1] = s[nj][1]*scale + mbv.y;
            s[nj][2] = s[nj][2]*scale + mbv.x;
            s[nj][3] = s[nj][3]*scale + mbv.y;
            mxA = fmaxf(mxA, fmaxf(s[nj][0], s[nj][1]));
            mxB = fmaxf(mxB, fmaxf(s[nj][2], s[nj][3]));
        }
        mxA = fmaxf(mxA, __shfl_xor_sync(0xffffffffu, mxA, 1));
        mxA = fmaxf(mxA, __shfl_xor_sync(0xffffffffu, mxA, 2));
        mxB = fmaxf(mxB, __shfl_xor_sync(0xffffffffu, mxB, 1));
        mxB = fmaxf(mxB, __shfl_xor_sync(0xffffffffu, mxB, 2));

        float mAn = fmaxf(mA, mxA), fA = __expf(mA - mAn);
        float mBn = fmaxf(mB, mxB), fB = __expf(mB - mBn);
        mA = mAn; mB = mBn;
        lA *= fA;  lB *= fB;

        /* P = exp(S - m) -> fp16 warp-private smem */
        __half* Pw = Ps + w*16*PPADH;
        #pragma unroll
        for (int nj = 0; nj < 8; nj++) {
            float p0 = __expf(s[nj][0] - mA);
            float p1 = __expf(s[nj][1] - mA);
            float p2 = __expf(s[nj][2] - mB);
            float p3 = __expf(s[nj][3] - mB);
            lA += p0 + p1; lB += p2 + p3;
            *(uint32_t*)(Pw + g*PPADH     + nj*8 + 2*t) = h2pack(p0, p1);
            *(uint32_t*)(Pw + (g+8)*PPADH + nj*8 + 2*t) = h2pack(p2, p3);
        }
        #pragma unroll
        for (int nj = 0; nj < 6; nj++) {
            o[nj][0] *= fA; o[nj][1] *= fA;
            o[nj][2] *= fB; o[nj][3] *= fB;
        }
        __syncwarp();

        /* O += P V : A = P[16][64], B = V^T[d][n] */
        #pragma unroll
        for (int ks = 0; ks < 4; ks++) {
            int kb = ks*16 + 2*t;
            uint32_t a0 = *(const uint32_t*)(Pw + g*PPADH + kb);
            uint32_t a1 = *(const uint32_t*)(Pw + (g+8)*PPADH + kb);
            uint32_t a2 = *(const uint32_t*)(Pw + g*PPADH + kb + 8);
            uint32_t a3 = *(const uint32_t*)(Pw + (g+8)*PPADH + kb + 8);
            #pragma unroll
            for (int nj = 0; nj < 6; nj++) {
                int nb = nj*8 + g;
                uint32_t b0 = *(const uint32_t*)(Vst + nb*VTPADH + kb);
                uint32_t b1 = *(const uint32_t*)(Vst + nb*VTPADH + kb + 8);
                mma16(o[nj], a0, a1, a2, a3, b0, b1);
            }
        }
    }

    /* epilogue */
    lA += __shfl_xor_sync(0xffffffffu, lA, 1);
    lA += __shfl_xor_sync(0xffffffffu, lA, 2);
    lB += __shfl_xor_sync(0xffffffffu, lB, 1);
    lB += __shfl_xor_sync(0xffffffffu, lB, 2);
    float invA = 1.0f / lA, invB = 1.0f / lB;
    int rA = q0 + w*16 + g, rB = rA + 8;
    #pragma unroll
    for (int nj = 0; nj < 6; nj++) {
        int cb = nj*8 + 2*t;
        *(uint32_t*)(O + ((size_t)(b*NSEQ + rA))*BDIM + h*HD + cb) =
            h2pack(o[nj][0]*invA, o[nj][1]*invA);
        *(uint32_t*)(O + ((size_t)(b*NSEQ + rB))*BDIM + h*HD + cb) =
            h2pack(o[nj][2]*invB, o[nj][3]*invB);
    }
}

/* ------------------------------ launch ------------------------------ */
extern "C" void kernel_launch(void* const* d_in, const int* in_sizes, int n_in,
                              void* d_out, int out_size) {
    const float* x    = (const float*)d_in[0];
    const float* pos  = (const float*)d_in[1];
    const void*  mask = d_in[2];
    const float* Wq   = (const float*)d_in[3];
    const float* bq   = (const float*)d_in[4];
    const float* Wk   = (const float*)d_in[5];
    const float* bk   = (const float*)d_in[6];
    const float* Wv   = (const float*)d_in[7];
    const float* bv   = (const float*)d_in[8];
    const float* pw1  = (const float*)d_in[9];
    const float* pb1  = (const float*)d_in[10];
    const float* pw2  = (const float*)d_in[11];
    const float* pb2  = (const float*)d_in[12];
    const float* Wo   = (const float*)d_in[13];
    const float* bo   = (const float*)d_in[14];
    const float* mw1  = (const float*)d_in[15];
    const float* mb1  = (const float*)d_in[16];
    const float* mw2  = (const float*)d_in[17];
    const float* mb2  = (const float*)d_in[18];
    const float* g1   = (const float*)d_in[19];
    const float* be1  = (const float*)d_in[20];
    const float* g2   = (const float*)d_in[21];
    const float* be2  = (const float*)d_in[22];
    float* out = (float*)d_out;

    void *ph, *pq, *pk, *pv, *patt, *phid, *pwq, *pwo, *pm1, *pm2;
    void *ppe, *px1, *pm, *pmb, *pbq;
    cudaGetSymbolAddress(&ph,  g_h16);
    cudaGetSymbolAddress(&pq,  g_q16);
    cudaGetSymbolAddress(&pk,  g_k16);
    cudaGetSymbolAddress(&pv,  g_v16t);
    cudaGetSymbolAddress(&patt,g_att16);
    cudaGetSymbolAddress(&phid,g_hid16);
    cudaGetSymbolAddress(&pwq, g_wqkvT);
    cudaGetSymbolAddress(&pwo, g_woT);
    cudaGetSymbolAddress(&pm1, g_mw1T);
    cudaGetSymbolAddress(&pm2, g_mw2T);
    cudaGetSymbolAddress(&ppe, g_pe);
    cudaGetSymbolAddress(&px1, g_x1);
    cudaGetSymbolAddress(&pm,  g_mask);
    cudaGetSymbolAddress(&pmb, g_mb);
    cudaGetSymbolAddress(&pbq, g_bqkv);
    __half* h16   = (__half*)ph;
    __half* q16   = (__half*)pq;
    __half* k16   = (__half*)pk;
    __half* v16t  = (__half*)pv;
    __half* att16 = (__half*)patt;
    __half* hid16 = (__half*)phid;
    __half* wqkvT = (__half*)pwq;
    __half* woT   = (__half*)pwo;
    __half* mw1T  = (__half*)pm1;
    __half* mw2T  = (__half*)pm2;
    float* pe   = (float*)ppe;
    float* x1   = (float*)px1;
    int*   msk  = (int*)pm;
    float* mbf  = (float*)pmb;
    float* bqkv = (float*)pbq;

    cudaFuncSetAttribute(attn_tc,
                         cudaFuncAttributeMaxDynamicSharedMemorySize, ATT_SMEM);

    /* 1. mask (+float bias) */
    mask_convert_kernel<<<1, 256>>>(mask, MROWS, msk, mbf);
    /* 2. transpose+convert weights to fp16 [n][k] */
    dim3 tb(32, 8);
    transpose_h_kernel<<<dim3(BDIM/32, BDIM/32), tb>>>(Wq, wqkvT,              BDIM, BDIM);
    transpose_h_kernel<<<dim3(BDIM/32, BDIM/32), tb>>>(Wk, wqkvT + BDIM*BDIM,  BDIM, BDIM);
    transpose_h_kernel<<<dim3(BDIM/32, BDIM/32), tb>>>(Wv, wqkvT + 2*BDIM*BDIM,BDIM, BDIM);
    transpose_h_kernel<<<dim3(BDIM/32, BDIM/32), tb>>>(Wo, woT,  BDIM, BDIM);
    transpose_h_kernel<<<dim3(MLPH/32, BDIM/32), tb>>>(mw1, mw1T, BDIM, MLPH);
    transpose_h_kernel<<<dim3(BDIM/32, MLPH/32), tb>>>(mw2, mw2T, MLPH, BDIM);
    pack_bias_kernel<<<(QKVN+255)/256, 256>>>(bq, bk, bv, bqkv);
    /* 3. LN1 -> fp16 */
    ln_kernel<<<MROWS, 128>>>(x, g1, be1, h16);
    /* 4. positional MLP */
    pe_kernel<<<MROWS/8, 256>>>(pos, pw1, pb1, pw2, pb2, pe);
    /* 5. fused QKV projection */
    dim3 gqkv(MROWS/GBM, QKVN/GBN);
    gemm_tc<1><<<gqkv, 256>>>(h16, wqkvT, bqkv, BDIM, QKVN, pe, nullptr,
                              nullptr, q16, k16, v16t);
    /* 6. attention */
    dim3 ga(NSEQ/BQ, NB*HEADS);
    attn_tc<<<ga, 256, ATT_SMEM>>>(q16, k16, v16t, mbf, att16);
    /* 7. Wo + mask + residual -> x1 (f32) */
    dim3 gwo(MROWS/GBM, BDIM/GBN);
    gemm_tc<2><<<gwo, 256>>>(att16, woT, bo, BDIM, BDIM, x, msk,
                             x1, nullptr, nullptr, nullptr);
    /* 8. LN2 -> fp16 */
    ln_kernel<<<MROWS, 128>>>(x1, g2, be2, h16);
    /* 9. MLP1 + gelu -> fp16 */
    dim3 gm1(MROWS/GBM, MLPH/GBN);
    gemm_tc<3><<<gm1, 256>>>(h16, mw1T, mb1, BDIM, MLPH, nullptr, nullptr,
                             nullptr, hid16, nullptr, nullptr);
    /* 10. MLP2 + residual + mask -> out (f32) */
    gemm_tc<4><<<gwo, 256>>>(hid16, mw2T, mb2, MLPH, BDIM, x1, msk,
                             out, nullptr, nullptr, nullptr);
}

// round 7
// speedup vs baseline: 1.6126x; 1.1079x over previous
#include <cuda_runtime.h>
#include <cuda_fp16.h>
#include <math.h>
#include <stdint.h>

#define BDIM 384
#define HEADS 8
#define HD 48
#define NSEQ 2048
#define NB 4
#define MROWS (NB*NSEQ)      /* 8192 */
#define MLPH 1536
#define QKVN (3*BDIM)        /* 1152 */

/* ------------ scratch (device globals; no allocation allowed) ------------ */
__device__ __half g_h16 [MROWS*BDIM];
__device__ __half g_q16 [MROWS*BDIM];
__device__ __half g_k16 [MROWS*BDIM];
__device__ __half g_v16t[MROWS*BDIM];          /* V^T: [bh][d][n] */
__device__ __half g_att16[MROWS*BDIM];
__device__ __half g_hid16[MROWS*MLPH];
__device__ __half g_wqkvT[QKVN*BDIM];
__device__ __half g_woT  [BDIM*BDIM];
__device__ __half g_mw1T [MLPH*BDIM];
__device__ __half g_mw2T [BDIM*MLPH];
__device__ float  g_pe[MROWS*HD];
__device__ float  g_x1[MROWS*BDIM];
__device__ int    g_mask[MROWS];
__device__ float  g_mb [MROWS];
__device__ float  g_bqkv[QKVN];

__device__ __forceinline__ float gelu_exact(float x) {
    return 0.5f * x * (1.0f + erff(x * 0.70710678118654752f));
}
__device__ __forceinline__ float ex2(float x) {
    float y; asm("ex2.approx.f32 %0, %1;" : "=f"(y) : "f"(x)); return y;
}

/* m16n8k16 fp16 mma, fp32 accumulate. regs are packed half2. */
__device__ __forceinline__ void mma16(float* c,
                                      uint32_t a0, uint32_t a1, uint32_t a2, uint32_t a3,
                                      uint32_t b0, uint32_t b1) {
    asm volatile(
      "mma.sync.aligned.m16n8k16.row.col.f32.f16.f16.f32 "
      "{%0,%1,%2,%3},{%4,%5,%6,%7},{%8,%9},{%0,%1,%2,%3};"
      : "+f"(c[0]), "+f"(c[1]), "+f"(c[2]), "+f"(c[3])
      : "r"(a0), "r"(a1), "r"(a2), "r"(a3), "r"(b0), "r"(b1));
}

__device__ __forceinline__ void ldsm4(uint32_t& r0, uint32_t& r1,
                                      uint32_t& r2, uint32_t& r3, uint32_t a) {
    asm volatile("ldmatrix.sync.aligned.m8n8.x4.shared.b16 {%0,%1,%2,%3}, [%4];"
                 : "=r"(r0), "=r"(r1), "=r"(r2), "=r"(r3) : "r"(a));
}
__device__ __forceinline__ uint32_t s2u(const void* p) {
    return (uint32_t)__cvta_generic_to_shared(p);
}
__device__ __forceinline__ void cpa16(void* dst, const void* src) {
    uint32_t d = s2u(dst);
    asm volatile("cp.async.ca.shared.global [%0], [%1], 16;" :: "r"(d), "l"(src));
}
__device__ __forceinline__ void cpa4(void* dst, const void* src) {
    uint32_t d = s2u(dst);
    asm volatile("cp.async.ca.shared.global [%0], [%1], 4;" :: "r"(d), "l"(src));
}
#define CP_COMMIT() asm volatile("cp.async.commit_group;")
template<int N> __device__ __forceinline__ void cp_wait() {
    asm volatile("cp.async.wait_group %0;" :: "n"(N));
}
__device__ __forceinline__ uint32_t h2pack(float a, float b) {
    __half2 h = __floats2half2_rn(a, b);
    return *(uint32_t*)&h;
}

/* ------------ mask dtype sniffing + conversion (+ float bias) ------------ */
__global__ void mask_convert_kernel(const void* __restrict__ mptr, int n,
                                    int* __restrict__ out, float* __restrict__ fb) {
    const unsigned char* b = (const unsigned char*)mptr;
    __shared__ int f32flag, nm4flag;
    if (threadIdx.x == 0) { f32flag = 0; nm4flag = 0; }
    __syncthreads();
    int lf = 0, ln4 = 0;
    for (int i = threadIdx.x; i < n; i += blockDim.x) {
        unsigned char c = b[i];
        if (c == 0x3Fu && (i & 3) == 3) lf = 1;
        if (c != 0u   && (i & 3) != 0) ln4 = 1;
    }
    if (lf)  atomicOr(&f32flag, 1);
    if (ln4) atomicOr(&nm4flag, 1);
    __syncthreads();
    int mode = f32flag ? 2 : (nm4flag ? 0 : 1);
    for (int i = threadIdx.x; i < n; i += blockDim.x) {
        int v;
        if      (mode == 0) v = (b[i] != 0);
        else if (mode == 1) v = (((const int*)mptr)[i]   != 0);
        else                v = (((const float*)mptr)[i] != 0.0f);
        out[i] = v;
        fb[i]  = v ? 0.0f : -1e30f;
    }
}

/* ------------ ALL weight transposes f32[K][N] -> fp16[N][K] in ONE launch -- */
__global__ void transpose_all_kernel(const float* __restrict__ Wq,
                                     const float* __restrict__ Wk,
                                     const float* __restrict__ Wv,
                                     const float* __restrict__ Wo,
                                     const float* __restrict__ mw1,
                                     const float* __restrict__ mw2,
                                     __half* __restrict__ wqkvT, __half* __restrict__ woT,
                                     __half* __restrict__ mw1T, __half* __restrict__ mw2T) {
    __shared__ float tile[32][33];
    int tIdx = blockIdx.x;
    const float* W; __half* Wt; int K, N;
    if (tIdx < 432) {                        /* Wq/Wk/Wv: 144 tiles each */
        int seg = tIdx / 144;
        W  = (seg == 0) ? Wq : (seg == 1) ? Wk : Wv;
        Wt = wqkvT + (size_t)seg * BDIM * BDIM;
        K = BDIM; N = BDIM; tIdx -= seg * 144;
    } else if (tIdx < 576) { W = Wo;  Wt = woT;  K = BDIM; N = BDIM; tIdx -= 432; }
    else if   (tIdx < 1152) { W = mw1; Wt = mw1T; K = BDIM; N = MLPH; tIdx -= 576; }
    else                    { W = mw2; Wt = mw2T; K = MLPH; N = BDIM; tIdx -= 1152; }
    int nt = N / 32;
    int n0 = (tIdx % nt) * 32, k0 = (tIdx / nt) * 32;
    int tx = threadIdx.x, ty = threadIdx.y;          /* 32 x 8 */
    #pragma unroll
    for (int i = 0; i < 32; i += 8)
        tile[ty+i][tx] = W[(size_t)(k0+ty+i)*N + n0+tx];
    __syncthreads();
    #pragma unroll
    for (int i = 0; i < 32; i += 8)
        Wt[(size_t)(n0+ty+i)*K + k0+tx] = __float2half_rn(tile[tx][ty+i]);
}

__global__ void pack_bias_kernel(const float* __restrict__ bq, const float* __restrict__ bk,
                                 const float* __restrict__ bv, float* __restrict__ bp) {
    int i = blockIdx.x*256 + threadIdx.x;
    if (i < QKVN) {
        int sec = i / BDIM, c = i % BDIM;
        bp[i] = (sec == 0) ? bq[c] : (sec == 1) ? bk[c] : bv[c];
    }
}

/* ------------ LayerNorm over 384 cols -> fp16 ------------ */
__device__ __forceinline__ float warp_sum(float v) {
    #pragma unroll
    for (int o = 16; o; o >>= 1) v += __shfl_xor_sync(0xffffffffu, v, o);
    return v;
}

__global__ void ln_kernel(const float* __restrict__ X,
                          const float* __restrict__ g,
                          const float* __restrict__ be,
                          __half* __restrict__ Y) {
    int row = blockIdx.x;
    const float* x = X + (size_t)row * BDIM;
    __half*      y = Y + (size_t)row * BDIM;
    int t = threadIdx.x;
    float v0 = x[t], v1 = x[t + 128], v2 = x[t + 256];
    float s  = v0 + v1 + v2;
    float sq = v0*v0 + v1*v1 + v2*v2;
    s = warp_sum(s); sq = warp_sum(sq);
    __shared__ float ss[4], sqq[4];
    int w = t >> 5, lane = t & 31;
    if (lane == 0) { ss[w] = s; sqq[w] = sq; }
    __syncthreads();
    float S  = ss[0] + ss[1] + ss[2] + ss[3];
    float SQ = sqq[0] + sqq[1] + sqq[2] + sqq[3];
    float mean = S * (1.0f / BDIM);
    float var  = SQ * (1.0f / BDIM) - mean * mean;
    float rstd = rsqrtf(var + 1e-5f);
    y[t      ] = __float2half_rn((v0 - mean) * rstd * g[t      ] + be[t      ]);
    y[t + 128] = __float2half_rn((v1 - mean) * rstd * g[t + 128] + be[t + 128]);
    y[t + 256] = __float2half_rn((v2 - mean) * rstd * g[t + 256] + be[t + 256]);
}

/* ------------ positional MLP: one warp per row ------------ */
__global__ __launch_bounds__(256)
void pe_kernel(const float* __restrict__ pos,
               const float* __restrict__ pw1, const float* __restrict__ pb1,
               const float* __restrict__ pw2, const float* __restrict__ pb2,
               float* __restrict__ pe) {
    __shared__ float w2s[HD*HD];
    __shared__ float w1s[3*HD], b1s[HD], b2s[HD];
    int tid = threadIdx.x, lane = tid & 31, w = tid >> 5;
    for (int i = tid; i < HD*HD; i += 256) w2s[i] = pw2[i];
    if (tid < 3*HD) w1s[tid] = pw1[tid];
    else if (tid < 4*HD) b1s[tid - 3*HD] = pb1[tid - 3*HD];
    else if (tid < 5*HD) b2s[tid - 4*HD] = pb2[tid - 4*HD];
    __syncthreads();
    int row = blockIdx.x*8 + w;
    float p0 = pos[row*3], p1 = pos[row*3+1], p2 = pos[row*3+2];
    float h0, h1 = 0.f;
    {
        int k = lane;
        h0 = gelu_exact(p0*w1s[k] + p1*w1s[HD+k] + p2*w1s[2*HD+k] + b1s[k]);
    }
    if (lane < 16) {
        int k = 32 + lane;
        h1 = gelu_exact(p0*w1s[k] + p1*w1s[HD+k] + p2*w1s[2*HD+k] + b1s[k]);
    }
    float acc0 = b2s[lane];
    float acc1 = (lane < 16) ? b2s[32 + lane] : 0.f;
    #pragma unroll 8
    for (int k = 0; k < HD; k++) {
        float hk = (k < 32) ? __shfl_sync(0xffffffffu, h0, k)
                            : __shfl_sync(0xffffffffu, h1, k - 32);
        acc0 += hk * w2s[k*HD + lane];
        if (lane < 16) acc1 += hk * w2s[k*HD + 32 + lane];
    }
    pe[(size_t)row*HD + lane] = acc0;
    if (lane < 16) pe[(size_t)row*HD + 32 + lane] = acc1;
}

/* ------------ fp16 tensor-core GEMM: 128x64x32, ldmatrix fragments -------- */
#define GBM 128
#define GBN 64
#define GBK 32
#define APADH 40
#define BPADH 40

template<int EPI>
__global__ __launch_bounds__(256, 3)
void gemm_tc(const __half* __restrict__ A, const __half* __restrict__ Bt,
             const float* __restrict__ bias,
             int K, int Nc,
             const float* __restrict__ extra, const int* __restrict__ mask,
             float* __restrict__ Cf, __half* __restrict__ Ch,
             __half* __restrict__ Ck, __half* __restrict__ Cv) {
    __shared__ __half As[2][GBM*APADH];
    __shared__ __half Bs[2][GBN*BPADH];
    int tid = threadIdx.x, lane = tid & 31, w = tid >> 5;
    int g = lane >> 2, t = lane & 3;
    int wm = w >> 1, wn = w & 1;
    int bm = blockIdx.x * GBM, bn = blockIdx.y * GBN;
    int mlow = (lane >> 3) & 1, mhigh = lane >> 4, rr = lane & 7;

    float acc[2][4][4];
    #pragma unroll
    for (int mi = 0; mi < 2; mi++)
        #pragma unroll
        for (int nj = 0; nj < 4; nj++)
            #pragma unroll
            for (int r = 0; r < 4; r++) acc[mi][nj][r] = 0.f;

    int a_r = tid >> 2, a_c = (tid & 3) * 8;
    int b_r = tid >> 2, b_c = (tid & 3) * 8;

    /* ldmatrix per-lane address offsets (bytes) */
    uint32_t As_u = s2u(&As[0][0]);
    uint32_t Bs_u = s2u(&Bs[0][0]);
    uint32_t aoff0 = ((wm*32 + mlow*8 + rr)*APADH + mhigh*8)*2;
    uint32_t aoff1 = aoff0 + 16*APADH*2;
    uint32_t boff0 = ((wn*32 + mhigh*8 + rr)*BPADH + mlow*8)*2;
    uint32_t boff1 = boff0 + 16*BPADH*2;

    /* prologue: stage 0 */
    cpa16(&As[0][a_r*APADH + a_c], A + (size_t)(bm + a_r)*K + a_c);
    cpa16(&As[0][(a_r+64)*APADH + a_c], A + (size_t)(bm + a_r + 64)*K + a_c);
    cpa16(&Bs[0][b_r*BPADH + b_c], Bt + (size_t)(bn + b_r)*K + b_c);
    CP_COMMIT();

    int ntiles = K / GBK;
    for (int kt = 0; kt < ntiles; kt++) {
        __syncthreads();
        if (kt + 1 < ntiles) {
            int k0 = (kt + 1) * GBK, st = (kt + 1) & 1;
            cpa16(&As[st][a_r*APADH + a_c], A + (size_t)(bm + a_r)*K + k0 + a_c);
            cpa16(&As[st][(a_r+64)*APADH + a_c], A + (size_t)(bm + a_r + 64)*K + k0 + a_c);
            cpa16(&Bs[st][b_r*BPADH + b_c], Bt + (size_t)(bn + b_r)*K + k0 + b_c);
            CP_COMMIT();
            cp_wait<1>();
        } else {
            cp_wait<0>();
        }
        __syncthreads();
        uint32_t asb = As_u + (kt & 1)*(GBM*APADH*2);
        uint32_t bsb = Bs_u + (kt & 1)*(GBN*BPADH*2);

        #pragma unroll
        for (int ks = 0; ks < 2; ks++) {
            uint32_t kbb = ks*32;       /* 16 halves = 32 B */
            uint32_t af0[4], af1[4], bb0[4], bb1[4];
            ldsm4(af0[0], af0[1], af0[2], af0[3], asb + aoff0 + kbb);
            ldsm4(af1[0], af1[1], af1[2], af1[3], asb + aoff1 + kbb);
            ldsm4(bb0[0], bb0[1], bb0[2], bb0[3], bsb + boff0 + kbb);
            ldsm4(bb1[0], bb1[1], bb1[2], bb1[3], bsb + boff1 + kbb);
            mma16(acc[0][0], af0[0], af0[1], af0[2], af0[3], bb0[0], bb0[1]);
            mma16(acc[0][1], af0[0], af0[1], af0[2], af0[3], bb0[2], bb0[3]);
            mma16(acc[0][2], af0[0], af0[1], af0[2], af0[3], bb1[0], bb1[1]);
            mma16(acc[0][3], af0[0], af0[1], af0[2], af0[3], bb1[2], bb1[3]);
            mma16(acc[1][0], af1[0], af1[1], af1[2], af1[3], bb0[0], bb0[1]);
            mma16(acc[1][1], af1[0], af1[1], af1[2], af1[3], bb0[2], bb0[3]);
            mma16(acc[1][2], af1[0], af1[1], af1[2], af1[3], bb1[0], bb1[1]);
            mma16(acc[1][3], af1[0], af1[1], af1[2], af1[3], bb1[2], bb1[3]);
        }
    }

    #pragma unroll
    for (int mi = 0; mi < 2; mi++) {
        #pragma unroll
        for (int half = 0; half < 2; half++) {
            int row = bm + wm*32 + mi*16 + g + half*8;
            #pragma unroll
            for (int nj = 0; nj < 4; nj++) {
                int col = bn + wn*32 + nj*8 + 2*t;
                float v0 = acc[mi][nj][half*2+0] + bias[col];
                float v1 = acc[mi][nj][half*2+1] + bias[col+1];
                if (EPI == 1) {
                    int sec = col / BDIM;
                    int c2  = col - sec*BDIM;
                    int d = c2 % HD, hh = c2 / HD;
                    int bb = row >> 11, n = row & (NSEQ-1);
                    if (sec == 2) {
                        __half* p = Cv + ((size_t)((bb*HEADS + hh)*HD + d))*NSEQ + n;
                        p[0]    = __float2half_rn(v0);
                        p[NSEQ] = __float2half_rn(v1);
                    } else {
                        if (sec == 1) {
                            v0 += extra[(size_t)row*HD + d];
                            v1 += extra[(size_t)row*HD + d + 1];
                        }
                        __half* base = (sec == 0) ? Ch : Ck;
                        __half* p = base + (((size_t)(bb*HEADS + hh))*NSEQ + n)*HD + d;
                        *(uint32_t*)p = h2pack(v0, v1);
                    }
                } else if (EPI == 2) {
                    float m = (float)mask[row];
                    v0 = v0*m + extra[(size_t)row*Nc + col];
                    v1 = v1*m + extra[(size_t)row*Nc + col + 1];
                    float* p = Cf + (size_t)row*Nc + col;
                    p[0] = v0; p[1] = v1;
                } else if (EPI == 3) {
                    *(uint32_t*)(Ch + (size_t)row*Nc + col) =
                        h2pack(gelu_exact(v0), gelu_exact(v1));
                } else {
                    float m = (float)mask[row];
                    v0 = (v0 + extra[(size_t)row*Nc + col])*m;
                    v1 = (v1 + extra[(size_t)row*Nc + col + 1])*m;
                    float* p = Cf + (size_t)row*Nc + col;
                    p[0] = v0; p[1] = v1;
                }
            }
        }
    }
}

/* ------------ flash attention (fp16 mma + ldmatrix, exp2 softmax) -------- */
#define KPADH 56
#define VTPADH 72
#define PPADH 72
#define BQ 128
#define NT (NSEQ/64)
#define ATT_H_KS 0
#define ATT_H_VT (2*64*KPADH)                        /* 7168  */
#define ATT_H_PS (ATT_H_VT + 2*48*VTPADH)            /* 14080 */
#define ATT_H_END (ATT_H_PS + 8*16*PPADH)            /* 23296 halves */
#define ATT_MB_OFF ATT_H_END
#define ATT_SMEM (ATT_H_END*2 + 2*64*4)              /* 47104 B */

__global__ __launch_bounds__(256, 2)
void attn_tc(const __half* __restrict__ Q, const __half* __restrict__ Kb,
             const __half* __restrict__ Vt, const float* __restrict__ mb,
             __half* __restrict__ O) {
    extern __shared__ __half smh[];
    __half* Ks  = smh + ATT_H_KS;
    __half* Vts = smh + ATT_H_VT;
    __half* Ps  = smh + ATT_H_PS;
    float*  MBs = (float*)(smh + ATT_MB_OFF);

    int bh = blockIdx.y, b = bh >> 3, h = bh & 7;
    int q0 = blockIdx.x * BQ;
    int tid = threadIdx.x, lane = tid & 31, w = tid >> 5;
    int g = lane >> 2, t = lane & 3;
    int mlow = (lane >> 3) & 1, mhigh = lane >> 4, rr = lane & 7;
    const __half* qp = Q  + (size_t)bh * NSEQ * HD;
    const __half* kp = Kb + (size_t)bh * NSEQ * HD;
    const __half* vp = Vt + (size_t)bh * NSEQ * HD;   /* [d][n] */
    const float* mbp = mb + b * NSEQ;

    uint32_t Ks_u = s2u(Ks), Vt_u = s2u(Vts), Ps_u = s2u(Ps);
    uint32_t koff = ((mhigh*8 + rr)*KPADH + mlow*8)*2;           /* + njp*16 rows + kb */
    uint32_t voff = ((mhigh*8 + rr)*VTPADH + mlow*8)*2;
    uint32_t poff = Ps_u + (size_t)0 + ((mlow*8 + rr)*PPADH + mhigh*8)*2 + w*16*PPADH*2;
    uint32_t qoff = Ps_u + ((w*16 + mlow*8 + rr)*KPADH + mhigh*8)*2;

    /* stage Q into Ps region ([128][56] halves), extract fragments via ldmatrix */
    #pragma unroll
    for (int i = 0; i < 3; i++) {
        int idx = tid + i*256;
        int r = idx / 6, c = (idx % 6) * 8;
        *(uint4*)(Ps + r*KPADH + c) = *(const uint4*)(qp + (size_t)(q0 + r)*HD + c);
    }
    __syncthreads();
    uint32_t qf[3][4];
    #pragma unroll
    for (int ks = 0; ks < 3; ks++)
        ldsm4(qf[ks][0], qf[ks][1], qf[ks][2], qf[ks][3], qoff + ks*32);
    __syncthreads();   /* Ps reused for P */

    float o[6][4];
    #pragma unroll
    for (int nj = 0; nj < 6; nj++)
        #pragma unroll
        for (int r = 0; r < 4; r++) o[nj][r] = 0.f;
    float mA = -INFINITY, mB = -INFINITY, lA = 0.f, lB = 0.f;
    const float scale2 = 0.14433756729740643f * 1.4426950408889634f; /* /sqrt(48)*log2e */

    /* prologue: stage 0 */
    {
        #pragma unroll
        for (int i = 0; i < 2; i++) {
            int idx = tid + i*256;
            if (idx < 384) {
                int r = idx / 6, c = (idx % 6) * 8;
                cpa16(Ks + r*KPADH + c, kp + (size_t)r*HD + c);
                int rv = idx >> 3, cv = (idx & 7) * 8;
                cpa16(Vts + rv*VTPADH + cv, vp + (size_t)rv*NSEQ + cv);
            }
        }
        if (tid < 64) cpa4(MBs + tid, mbp + tid);
        CP_COMMIT();
    }

    for (int kt = 0; kt < NT; kt++) {
        __syncthreads();
        if (kt + 1 < NT) {
            int st = (kt + 1) & 1, k0 = (kt + 1) * 64;
            #pragma unroll
            for (int i = 0; i < 2; i++) {
                int idx = tid + i*256;
                if (idx < 384) {
                    int r = idx / 6, c = (idx % 6) * 8;
                    cpa16(Ks + st*64*KPADH + r*KPADH + c, kp + (size_t)(k0 + r)*HD + c);
                    int rv = idx >> 3, cv = (idx & 7) * 8;
                    cpa16(Vts + st*48*VTPADH + rv*VTPADH + cv,
                          vp + (size_t)rv*NSEQ + k0 + cv);
                }
            }
            if (tid < 64) cpa4(MBs + st*64 + tid, mbp + k0 + tid);
            CP_COMMIT();
            cp_wait<1>();
        } else {
            cp_wait<0>();
        }
        __syncthreads();
        int st = kt & 1;
        uint32_t Kst_u = Ks_u + st*64*KPADH*2;
        uint32_t Vst_u = Vt_u + st*48*VTPADH*2;
        const float* MBst = MBs + st*64;

        /* S = Q K^T : warp tile 16x64, ldmatrix K fragments */
        float s[8][4];
        #pragma unroll
        for (int nj = 0; nj < 8; nj++)
            #pragma unroll
            for (int r = 0; r < 4; r++) s[nj][r] = 0.f;
        #pragma unroll
        for (int ks = 0; ks < 3; ks++) {
            uint32_t kbb = ks*32;
            #pragma unroll
            for (int njp = 0; njp < 4; njp++) {
                uint32_t b0, b1, b2, b3;
                ldsm4(b0, b1, b2, b3, Kst_u + koff + njp*16*KPADH*2 + kbb);
                mma16(s[2*njp],   qf[ks][0], qf[ks][1], qf[ks][2], qf[ks][3], b0, b1);
                mma16(s[2*njp+1], qf[ks][0], qf[ks][1], qf[ks][2], qf[ks][3], b2, b3);
            }
        }

        /* scale (exp2 domain) + mask bias, row max */
        float mxA = -INFINITY, mxB = -INFINITY;
        #pragma unroll
        for (int nj = 0; nj < 8; nj++) {
            float2 mbv = *(const float2*)(MBst + nj*8 + 2*t);
            s[nj][0] = s[nj][0]*scale2 + mbv.x;
            s[nj][1] = s[nj][1]*scale2 + mbv.y;
            s[nj][2] = s[nj][2]*scale2 + mbv.x;
            s[nj][3] = s[nj][3]*scale2 + mbv.y;
            mxA = fmaxf(mxA, fmaxf(s[nj][0], s[nj][1]));
            mxB = fmaxf(mxB, fmaxf(s[nj][2], s[nj][3]));
        }
        mxA = fmaxf(mxA, __shfl_xor_sync(0xffffffffu, mxA, 1));
        mxA = fmaxf(mxA, __shfl_xor_sync(0xffffffffu, mxA, 2));
        mxB = fmaxf(mxB, __shfl_xor_sync(0xffffffffu, mxB, 1));
        mxB = fmaxf(mxB, __shfl_xor_sync(0xffffffffu, mxB, 2));

        float mAn = fmaxf(mA, mxA), fA = ex2(mA - mAn);
        float mBn = fmaxf(mB, mxB), fB = ex2(mB - mBn);
        mA = mAn; mB = mBn;
        lA *= fA;  lB *= fB;

        /* P = exp2(S - m) -> fp16 warp-private smem */
        __half* Pw = Ps + w*16*PPADH;
        #pragma unroll
        for (int nj = 0; nj < 8; nj++) {
            float p0 = ex2(s[nj][0] - mA);
            float p1 = ex2(s[nj][1] - mA);
            float p2 = ex2(s[nj][2] - mB);
            float p3 = ex2(s[nj][3] - mB);
            lA += p0 + p1; lB += p2 + p3;
            *(uint32_t*)(Pw + g*PPADH     + nj*8 + 2*t) = h2pack(p0, p1);
            *(uint32_t*)(Pw + (g+8)*PPADH + nj*8 + 2*t) = h2pack(p2, p3);
        }
        #pragma unroll
        for (int nj = 0; nj < 6; nj++) {
            o[nj][0] *= fA; o[nj][1] *= fA;
            o[nj][2] *= fB; o[nj][3] *= fB;
        }
        __syncwarp();

        /* O += P V : ldmatrix P (A-type) and V^T (B-type) */
        #pragma unroll
        for (int ks = 0; ks < 4; ks++) {
            uint32_t kbb = ks*32;
            uint32_t a0, a1, a2, a3;
            ldsm4(a0, a1, a2, a3, poff + kbb);
            #pragma unroll
            for (int njp = 0; njp < 3; njp++) {
                uint32_t b0, b1, b2, b3;
                ldsm4(b0, b1, b2, b3, Vst_u + voff + njp*16*VTPADH*2 + kbb);
                mma16(o[2*njp],   a0, a1, a2, a3, b0, b1);
                mma16(o[2*njp+1], a0, a1, a2, a3, b2, b3);
            }
        }
    }

    /* epilogue */
    lA += __shfl_xor_sync(0xffffffffu, lA, 1);
    lA += __shfl_xor_sync(0xffffffffu, lA, 2);
    lB += __shfl_xor_sync(0xffffffffu, lB, 1);
    lB += __shfl_xor_sync(0xffffffffu, lB, 2);
    float invA = 1.0f / lA, invB = 1.0f / lB;
    int rA = q0 + w*16 + g, rB = rA + 8;
    #pragma unroll
    for (int nj = 0; nj < 6; nj++) {
        int cb = nj*8 + 2*t;
        *(uint32_t*)(O + ((size_t)(b*NSEQ + rA))*BDIM + h*HD + cb) =
            h2pack(o[nj][0]*invA, o[nj][1]*invA);
        *(uint32_t*)(O + ((size_t)(b*NSEQ + rB))*BDIM + h*HD + cb) =
            h2pack(o[nj][2]*invB, o[nj][3]*invB);
    }
}

/* ------------------------------ launch ------------------------------ */
extern "C" void kernel_launch(void* const* d_in, const int* in_sizes, int n_in,
                              void* d_out, int out_size) {
    const float* x    = (const float*)d_in[0];
    const float* pos  = (const float*)d_in[1];
    const void*  mask = d_in[2];
    const float* Wq   = (const float*)d_in[3];
    const float* bq   = (const float*)d_in[4];
    const float* Wk   = (const float*)d_in[5];
    const float* bk   = (const float*)d_in[6];
    const float* Wv   = (const float*)d_in[7];
    const float* bv   = (const float*)d_in[8];
    const float* pw1  = (const float*)d_in[9];
    const float* pb1  = (const float*)d_in[10];
    const float* pw2  = (const float*)d_in[11];
    const float* pb2  = (const float*)d_in[12];
    const float* Wo   = (const float*)d_in[13];
    const float* bo   = (const float*)d_in[14];
    const float* mw1  = (const float*)d_in[15];
    const float* mb1  = (const float*)d_in[16];
    const float* mw2  = (const float*)d_in[17];
    const float* mb2  = (const float*)d_in[18];
    const float* g1   = (const float*)d_in[19];
    const float* be1  = (const float*)d_in[20];
    const float* g2   = (const float*)d_in[21];
    const float* be2  = (const float*)d_in[22];
    float* out = (float*)d_out;

    void *ph, *pq, *pk, *pv, *patt, *phid, *pwq, *pwo, *pm1, *pm2;
    void *ppe, *px1, *pm, *pmb, *pbq;
    cudaGetSymbolAddress(&ph,  g_h16);
    cudaGetSymbolAddress(&pq,  g_q16);
    cudaGetSymbolAddress(&pk,  g_k16);
    cudaGetSymbolAddress(&pv,  g_v16t);
    cudaGetSymbolAddress(&patt,g_att16);
    cudaGetSymbolAddress(&phid,g_hid16);
    cudaGetSymbolAddress(&pwq, g_wqkvT);
    cudaGetSymbolAddress(&pwo, g_woT);
    cudaGetSymbolAddress(&pm1, g_mw1T);
    cudaGetSymbolAddress(&pm2, g_mw2T);
    cudaGetSymbolAddress(&ppe, g_pe);
    cudaGetSymbolAddress(&px1, g_x1);
    cudaGetSymbolAddress(&pm,  g_mask);
    cudaGetSymbolAddress(&pmb, g_mb);
    cudaGetSymbolAddress(&pbq, g_bqkv);
    __half* h16   = (__half*)ph;
    __half* q16   = (__half*)pq;
    __half* k16   = (__half*)pk;
    __half* v16t  = (__half*)pv;
    __half* att16 = (__half*)patt;
    __half* hid16 = (__half*)phid;
    __half* wqkvT = (__half*)pwq;
    __half* woT   = (__half*)pwo;
    __half* mw1T  = (__half*)pm1;
    __half* mw2T  = (__half*)pm2;
    float* pe   = (float*)ppe;
    float* x1   = (float*)px1;
    int*   msk  = (int*)pm;
    float* mbf  = (float*)pmb;
    float* bqkv = (float*)pbq;

    cudaFuncSetAttribute(attn_tc,
                         cudaFuncAttributeMaxDynamicSharedMemorySize, ATT_SMEM);

    /* 1. mask (+float bias) */
    mask_convert_kernel<<<1, 256>>>(mask, MROWS, msk, mbf);
    /* 2. all weight transposes in one launch + bias pack */
    transpose_all_kernel<<<1728, dim3(32, 8)>>>(Wq, Wk, Wv, Wo, mw1, mw2,
                                                wqkvT, woT, mw1T, mw2T);
    pack_bias_kernel<<<(QKVN+255)/256, 256>>>(bq, bk, bv, bqkv);
    /* 3. LN1 -> fp16 */
    ln_kernel<<<MROWS, 128>>>(x, g1, be1, h16);
    /* 4. positional MLP */
    pe_kernel<<<MROWS/8, 256>>>(pos, pw1, pb1, pw2, pb2, pe);
    /* 5. fused QKV projection */
    dim3 gqkv(MROWS/GBM, QKVN/GBN);
    gemm_tc<1><<<gqkv, 256>>>(h16, wqkvT, bqkv, BDIM, QKVN, pe, nullptr,
                              nullptr, q16, k16, v16t);
    /* 6. attention */
    dim3 ga(NSEQ/BQ, NB*HEADS);
    attn_tc<<<ga, 256, ATT_SMEM>>>(q16, k16, v16t, mbf, att16);
    /* 7. Wo + mask + residual -> x1 (f32) */
    dim3 gwo(MROWS/GBM, BDIM/GBN);
    gemm_tc<2><<<gwo, 256>>>(att16, woT, bo, BDIM, BDIM, x, msk,
                             x1, nullptr, nullptr, nullptr);
    /* 8. LN2 -> fp16 */
    ln_kernel<<<MROWS, 128>>>(x1, g2, be2, h16);
    /* 9. MLP1 + gelu -> fp16 */
    dim3 gm1(MROWS/GBM, MLPH/GBN);
    gemm_tc<3><<<gm1, 256>>>(h16, mw1T, mb1, BDIM, MLPH, nullptr, nullptr,
                             nullptr, hid16, nullptr, nullptr);
    /* 10. MLP2 + residual + mask -> out (f32) */
    gemm_tc<4><<<gwo, 256>>>(hid16, mw2T, mb2, MLPH, BDIM, x1, msk,
                             out, nullptr, nullptr, nullptr);
}

// round 8
// speedup vs baseline: 1.6545x; 1.0260x over previous
#include <cuda_runtime.h>
#include <cuda_fp16.h>
#include <math.h>
#include <stdint.h>

#define BDIM 384
#define HEADS 8
#define HD 48
#define NSEQ 2048
#define NB 4
#define MROWS (NB*NSEQ)      /* 8192 */
#define MLPH 1536
#define QKVN (3*BDIM)        /* 1152 */

/* ------------ scratch (device globals; no allocation allowed) ------------ */
__device__ __half g_h16 [MROWS*BDIM];
__device__ __half g_q16 [MROWS*BDIM];
__device__ __half g_k16 [MROWS*BDIM];
__device__ __half g_v16t[MROWS*BDIM];          /* V^T: [bh][d][n] */
__device__ __half g_att16[MROWS*BDIM];
__device__ __half g_hid16[MROWS*MLPH];
__device__ __half g_wqkvT[QKVN*BDIM];
__device__ __half g_woT  [BDIM*BDIM];
__device__ __half g_mw1T [MLPH*BDIM];
__device__ __half g_mw2T [BDIM*MLPH];
__device__ float  g_pe[MROWS*HD];
__device__ float  g_x1[MROWS*BDIM];
__device__ int    g_mask[MROWS];
__device__ float  g_mb [MROWS];
__device__ float  g_bqkv[QKVN];

__device__ __forceinline__ float gelu_exact(float x) {
    return 0.5f * x * (1.0f + erff(x * 0.70710678118654752f));
}
__device__ __forceinline__ float ex2(float x) {
    float y; asm("ex2.approx.f32 %0, %1;" : "=f"(y) : "f"(x)); return y;
}

/* m16n8k16 fp16 mma, fp32 accumulate. regs are packed half2. */
__device__ __forceinline__ void mma16(float* c,
                                      uint32_t a0, uint32_t a1, uint32_t a2, uint32_t a3,
                                      uint32_t b0, uint32_t b1) {
    asm volatile(
      "mma.sync.aligned.m16n8k16.row.col.f32.f16.f16.f32 "
      "{%0,%1,%2,%3},{%4,%5,%6,%7},{%8,%9},{%0,%1,%2,%3};"
      : "+f"(c[0]), "+f"(c[1]), "+f"(c[2]), "+f"(c[3])
      : "r"(a0), "r"(a1), "r"(a2), "r"(a3), "r"(b0), "r"(b1));
}

__device__ __forceinline__ void ldsm4(uint32_t& r0, uint32_t& r1,
                                      uint32_t& r2, uint32_t& r3, uint32_t a) {
    asm volatile("ldmatrix.sync.aligned.m8n8.x4.shared.b16 {%0,%1,%2,%3}, [%4];"
                 : "=r"(r0), "=r"(r1), "=r"(r2), "=r"(r3) : "r"(a));
}
__device__ __forceinline__ void stsm4(uint32_t a, uint32_t r0, uint32_t r1,
                                      uint32_t r2, uint32_t r3) {
    asm volatile("stmatrix.sync.aligned.m8n8.x4.shared.b16 [%0], {%1,%2,%3,%4};"
                 :: "r"(a), "r"(r0), "r"(r1), "r"(r2), "r"(r3));
}
__device__ __forceinline__ uint32_t s2u(const void* p) {
    return (uint32_t)__cvta_generic_to_shared(p);
}
__device__ __forceinline__ void cpa16(void* dst, const void* src) {
    uint32_t d = s2u(dst);
    asm volatile("cp.async.ca.shared.global [%0], [%1], 16;" :: "r"(d), "l"(src));
}
__device__ __forceinline__ void cpa4(void* dst, const void* src) {
    uint32_t d = s2u(dst);
    asm volatile("cp.async.ca.shared.global [%0], [%1], 4;" :: "r"(d), "l"(src));
}
#define CP_COMMIT() asm volatile("cp.async.commit_group;")
template<int N> __device__ __forceinline__ void cp_wait() {
    asm volatile("cp.async.wait_group %0;" :: "n"(N));
}
__device__ __forceinline__ uint32_t h2pack(float a, float b) {
    __half2 h = __floats2half2_rn(a, b);
    return *(uint32_t*)&h;
}

/* ------------ mask dtype sniffing + conversion (+ float bias) ------------ */
__global__ void mask_convert_kernel(const void* __restrict__ mptr, int n,
                                    int* __restrict__ out, float* __restrict__ fb) {
    const unsigned char* b = (const unsigned char*)mptr;
    __shared__ int f32flag, nm4flag;
    if (threadIdx.x == 0) { f32flag = 0; nm4flag = 0; }
    __syncthreads();
    int lf = 0, ln4 = 0;
    for (int i = threadIdx.x; i < n; i += blockDim.x) {
        unsigned char c = b[i];
        if (c == 0x3Fu && (i & 3) == 3) lf = 1;
        if (c != 0u   && (i & 3) != 0) ln4 = 1;
    }
    if (lf)  atomicOr(&f32flag, 1);
    if (ln4) atomicOr(&nm4flag, 1);
    __syncthreads();
    int mode = f32flag ? 2 : (nm4flag ? 0 : 1);
    for (int i = threadIdx.x; i < n; i += blockDim.x) {
        int v;
        if      (mode == 0) v = (b[i] != 0);
        else if (mode == 1) v = (((const int*)mptr)[i]   != 0);
        else                v = (((const float*)mptr)[i] != 0.0f);
        out[i] = v;
        fb[i]  = v ? 0.0f : -1e30f;
    }
}

/* ------------ ALL weight transposes f32[K][N] -> fp16[N][K] in ONE launch -- */
__global__ void transpose_all_kernel(const float* __restrict__ Wq,
                                     const float* __restrict__ Wk,
                                     const float* __restrict__ Wv,
                                     const float* __restrict__ Wo,
                                     const float* __restrict__ mw1,
                                     const float* __restrict__ mw2,
                                     __half* __restrict__ wqkvT, __half* __restrict__ woT,
                                     __half* __restrict__ mw1T, __half* __restrict__ mw2T) {
    __shared__ float tile[32][33];
    int tIdx = blockIdx.x;
    const float* W; __half* Wt; int K, N;
    if (tIdx < 432) {
        int seg = tIdx / 144;
        W  = (seg == 0) ? Wq : (seg == 1) ? Wk : Wv;
        Wt = wqkvT + (size_t)seg * BDIM * BDIM;
        K = BDIM; N = BDIM; tIdx -= seg * 144;
    } else if (tIdx < 576) { W = Wo;  Wt = woT;  K = BDIM; N = BDIM; tIdx -= 432; }
    else if   (tIdx < 1152) { W = mw1; Wt = mw1T; K = BDIM; N = MLPH; tIdx -= 576; }
    else                    { W = mw2; Wt = mw2T; K = MLPH; N = BDIM; tIdx -= 1152; }
    int nt = N / 32;
    int n0 = (tIdx % nt) * 32, k0 = (tIdx / nt) * 32;
    int tx = threadIdx.x, ty = threadIdx.y;          /* 32 x 8 */
    #pragma unroll
    for (int i = 0; i < 32; i += 8)
        tile[ty+i][tx] = W[(size_t)(k0+ty+i)*N + n0+tx];
    __syncthreads();
    #pragma unroll
    for (int i = 0; i < 32; i += 8)
        Wt[(size_t)(n0+ty+i)*K + k0+tx] = __float2half_rn(tile[tx][ty+i]);
}

__global__ void pack_bias_kernel(const float* __restrict__ bq, const float* __restrict__ bk,
                                 const float* __restrict__ bv, float* __restrict__ bp) {
    int i = blockIdx.x*256 + threadIdx.x;
    if (i < QKVN) {
        int sec = i / BDIM, c = i % BDIM;
        bp[i] = (sec == 0) ? bq[c] : (sec == 1) ? bk[c] : bv[c];
    }
}

/* ------------ LayerNorm over 384 cols -> fp16 ------------ */
__device__ __forceinline__ float warp_sum(float v) {
    #pragma unroll
    for (int o = 16; o; o >>= 1) v += __shfl_xor_sync(0xffffffffu, v, o);
    return v;
}

__global__ void ln_kernel(const float* __restrict__ X,
                          const float* __restrict__ g,
                          const float* __restrict__ be,
                          __half* __restrict__ Y) {
    int row = blockIdx.x;
    const float* x = X + (size_t)row * BDIM;
    __half*      y = Y + (size_t)row * BDIM;
    int t = threadIdx.x;
    float v0 = x[t], v1 = x[t + 128], v2 = x[t + 256];
    float s  = v0 + v1 + v2;
    float sq = v0*v0 + v1*v1 + v2*v2;
    s = warp_sum(s); sq = warp_sum(sq);
    __shared__ float ss[4], sqq[4];
    int w = t >> 5, lane = t & 31;
    if (lane == 0) { ss[w] = s; sqq[w] = sq; }
    __syncthreads();
    float S  = ss[0] + ss[1] + ss[2] + ss[3];
    float SQ = sqq[0] + sqq[1] + sqq[2] + sqq[3];
    float mean = S * (1.0f / BDIM);
    float var  = SQ * (1.0f / BDIM) - mean * mean;
    float rstd = rsqrtf(var + 1e-5f);
    y[t      ] = __float2half_rn((v0 - mean) * rstd * g[t      ] + be[t      ]);
    y[t + 128] = __float2half_rn((v1 - mean) * rstd * g[t + 128] + be[t + 128]);
    y[t + 256] = __float2half_rn((v2 - mean) * rstd * g[t + 256] + be[t + 256]);
}

/* ------------ positional MLP: one warp per row ------------ */
__global__ __launch_bounds__(256)
void pe_kernel(const float* __restrict__ pos,
               const float* __restrict__ pw1, const float* __restrict__ pb1,
               const float* __restrict__ pw2, const float* __restrict__ pb2,
               float* __restrict__ pe) {
    __shared__ float w2s[HD*HD];
    __shared__ float w1s[3*HD], b1s[HD], b2s[HD];
    int tid = threadIdx.x, lane = tid & 31, w = tid >> 5;
    for (int i = tid; i < HD*HD; i += 256) w2s[i] = pw2[i];
    if (tid < 3*HD) w1s[tid] = pw1[tid];
    else if (tid < 4*HD) b1s[tid - 3*HD] = pb1[tid - 3*HD];
    else if (tid < 5*HD) b2s[tid - 4*HD] = pb2[tid - 4*HD];
    __syncthreads();
    int row = blockIdx.x*8 + w;
    float p0 = pos[row*3], p1 = pos[row*3+1], p2 = pos[row*3+2];
    float h0, h1 = 0.f;
    {
        int k = lane;
        h0 = gelu_exact(p0*w1s[k] + p1*w1s[HD+k] + p2*w1s[2*HD+k] + b1s[k]);
    }
    if (lane < 16) {
        int k = 32 + lane;
        h1 = gelu_exact(p0*w1s[k] + p1*w1s[HD+k] + p2*w1s[2*HD+k] + b1s[k]);
    }
    float acc0 = b2s[lane];
    float acc1 = (lane < 16) ? b2s[32 + lane] : 0.f;
    #pragma unroll 8
    for (int k = 0; k < HD; k++) {
        float hk = (k < 32) ? __shfl_sync(0xffffffffu, h0, k)
                            : __shfl_sync(0xffffffffu, h1, k - 32);
        acc0 += hk * w2s[k*HD + lane];
        if (lane < 16) acc1 += hk * w2s[k*HD + 32 + lane];
    }
    pe[(size_t)row*HD + lane] = acc0;
    if (lane < 16) pe[(size_t)row*HD + 32 + lane] = acc1;
}

/* ------------ fp16 GEMM: 128x64x32, 3-stage cp.async, 1 barrier/iter ----- */
#define GBM 128
#define GBN 64
#define GBK 32
#define APADH 40
#define BPADH 40
#define AST (GBM*APADH)
#define BST (GBN*BPADH)

template<int EPI>
__global__ __launch_bounds__(256, 3)
void gemm_tc(const __half* __restrict__ A, const __half* __restrict__ Bt,
             const float* __restrict__ bias,
             int K, int Nc,
             const float* __restrict__ extra, const int* __restrict__ mask,
             float* __restrict__ Cf, __half* __restrict__ Ch,
             __half* __restrict__ Ck, __half* __restrict__ Cv) {
    __shared__ __half As[3*AST];
    __shared__ __half Bs[3*BST];
    int tid = threadIdx.x, lane = tid & 31, w = tid >> 5;
    int g = lane >> 2, t = lane & 3;
    int wm = w >> 1, wn = w & 1;
    int bm = blockIdx.x * GBM, bn = blockIdx.y * GBN;
    int mlow = (lane >> 3) & 1, mhigh = lane >> 4, rr = lane & 7;

    float acc[2][4][4];
    #pragma unroll
    for (int mi = 0; mi < 2; mi++)
        #pragma unroll
        for (int nj = 0; nj < 4; nj++)
            #pragma unroll
            for (int r = 0; r < 4; r++) acc[mi][nj][r] = 0.f;

    int a_r = tid >> 2, a_c = (tid & 3) * 8;
    int b_r = tid >> 2, b_c = (tid & 3) * 8;

    uint32_t As_u = s2u(As);
    uint32_t Bs_u = s2u(Bs);
    uint32_t aoff0 = ((wm*32 + mlow*8 + rr)*APADH + mhigh*8)*2;
    uint32_t aoff1 = aoff0 + 16*APADH*2;
    uint32_t boff0 = ((wn*32 + mhigh*8 + rr)*BPADH + mlow*8)*2;
    uint32_t boff1 = boff0 + 16*BPADH*2;

    int ntiles = K / GBK;
    /* prologue: issue tiles 0 and 1 */
    #pragma unroll
    for (int p = 0; p < 2; p++) {
        int k0 = p * GBK;
        cpa16(&As[p*AST + a_r*APADH + a_c], A + (size_t)(bm + a_r)*K + k0 + a_c);
        cpa16(&As[p*AST + (a_r+64)*APADH + a_c], A + (size_t)(bm + a_r + 64)*K + k0 + a_c);
        cpa16(&Bs[p*BST + b_r*BPADH + b_c], Bt + (size_t)(bn + b_r)*K + k0 + b_c);
        CP_COMMIT();
    }

    int st = 0;
    for (int kt = 0; kt < ntiles; kt++) {
        cp_wait<1>();
        __syncthreads();
        if (kt + 2 < ntiles) {
            int k0 = (kt + 2) * GBK;
            int sn = st + 2; if (sn >= 3) sn -= 3;
            cpa16(&As[sn*AST + a_r*APADH + a_c], A + (size_t)(bm + a_r)*K + k0 + a_c);
            cpa16(&As[sn*AST + (a_r+64)*APADH + a_c], A + (size_t)(bm + a_r + 64)*K + k0 + a_c);
            cpa16(&Bs[sn*BST + b_r*BPADH + b_c], Bt + (size_t)(bn + b_r)*K + k0 + b_c);
        }
        CP_COMMIT();

        uint32_t asb = As_u + st*(AST*2);
        uint32_t bsb = Bs_u + st*(BST*2);
        #pragma unroll
        for (int ks = 0; ks < 2; ks++) {
            uint32_t kbb = ks*32;
            uint32_t af0[4], af1[4], bb0[4], bb1[4];
            ldsm4(af0[0], af0[1], af0[2], af0[3], asb + aoff0 + kbb);
            ldsm4(af1[0], af1[1], af1[2], af1[3], asb + aoff1 + kbb);
            ldsm4(bb0[0], bb0[1], bb0[2], bb0[3], bsb + boff0 + kbb);
            ldsm4(bb1[0], bb1[1], bb1[2], bb1[3], bsb + boff1 + kbb);
            mma16(acc[0][0], af0[0], af0[1], af0[2], af0[3], bb0[0], bb0[1]);
            mma16(acc[0][1], af0[0], af0[1], af0[2], af0[3], bb0[2], bb0[3]);
            mma16(acc[0][2], af0[0], af0[1], af0[2], af0[3], bb1[0], bb1[1]);
            mma16(acc[0][3], af0[0], af0[1], af0[2], af0[3], bb1[2], bb1[3]);
            mma16(acc[1][0], af1[0], af1[1], af1[2], af1[3], bb0[0], bb0[1]);
            mma16(acc[1][1], af1[0], af1[1], af1[2], af1[3], bb0[2], bb0[3]);
            mma16(acc[1][2], af1[0], af1[1], af1[2], af1[3], bb1[0], bb1[1]);
            mma16(acc[1][3], af1[0], af1[1], af1[2], af1[3], bb1[2], bb1[3]);
        }
        if (++st == 3) st = 0;
    }

    #pragma unroll
    for (int mi = 0; mi < 2; mi++) {
        #pragma unroll
        for (int half = 0; half < 2; half++) {
            int row = bm + wm*32 + mi*16 + g + half*8;
            #pragma unroll
            for (int nj = 0; nj < 4; nj++) {
                int col = bn + wn*32 + nj*8 + 2*t;
                float v0 = acc[mi][nj][half*2+0] + bias[col];
                float v1 = acc[mi][nj][half*2+1] + bias[col+1];
                if (EPI == 1) {
                    int sec = col / BDIM;
                    int c2  = col - sec*BDIM;
                    int d = c2 % HD, hh = c2 / HD;
                    int bb = row >> 11, n = row & (NSEQ-1);
                    if (sec == 2) {
                        __half* p = Cv + ((size_t)((bb*HEADS + hh)*HD + d))*NSEQ + n;
                        p[0]    = __float2half_rn(v0);
                        p[NSEQ] = __float2half_rn(v1);
                    } else {
                        if (sec == 1) {
                            v0 += extra[(size_t)row*HD + d];
                            v1 += extra[(size_t)row*HD + d + 1];
                        }
                        __half* base = (sec == 0) ? Ch : Ck;
                        __half* p = base + (((size_t)(bb*HEADS + hh))*NSEQ + n)*HD + d;
                        *(uint32_t*)p = h2pack(v0, v1);
                    }
                } else if (EPI == 2) {
                    float m = (float)mask[row];
                    v0 = v0*m + extra[(size_t)row*Nc + col];
                    v1 = v1*m + extra[(size_t)row*Nc + col + 1];
                    float* p = Cf + (size_t)row*Nc + col;
                    p[0] = v0; p[1] = v1;
                } else if (EPI == 3) {
                    *(uint32_t*)(Ch + (size_t)row*Nc + col) =
                        h2pack(gelu_exact(v0), gelu_exact(v1));
                } else {
                    float m = (float)mask[row];
                    v0 = (v0 + extra[(size_t)row*Nc + col])*m;
                    v1 = (v1 + extra[(size_t)row*Nc + col + 1])*m;
                    float* p = Cf + (size_t)row*Nc + col;
                    p[0] = v0; p[1] = v1;
                }
            }
        }
    }
}

/* ------- flash attention: fp16 mma + ldmatrix/stmatrix, 3-stage, 1 barrier - */
#define KPADH 56
#define VTPADH 72
#define PPADH 72
#define BQ 128
#define NT (NSEQ/64)
#define KST (64*KPADH)
#define VST (48*VTPADH)
#define ATT_H_KS 0
#define ATT_H_VT (3*KST)                             /* 10752 */
#define ATT_H_PS (ATT_H_VT + 3*VST)                  /* 21120 */
#define ATT_H_END (ATT_H_PS + 8*16*PPADH)            /* 30336 halves */
#define ATT_MB_OFF ATT_H_END
#define ATT_SMEM (ATT_H_END*2 + 3*64*4)              /* 61440 B */

__global__ __launch_bounds__(256, 2)
void attn_tc(const __half* __restrict__ Q, const __half* __restrict__ Kb,
             const __half* __restrict__ Vt, const float* __restrict__ mb,
             __half* __restrict__ O) {
    extern __shared__ __half smh[];
    __half* Ks  = smh + ATT_H_KS;
    __half* Vts = smh + ATT_H_VT;
    __half* Ps  = smh + ATT_H_PS;
    float*  MBs = (float*)(smh + ATT_MB_OFF);

    int bh = blockIdx.y, b = bh >> 3, h = bh & 7;
    int q0 = blockIdx.x * BQ;
    int tid = threadIdx.x, lane = tid & 31, w = tid >> 5;
    int g = lane >> 2, t = lane & 3;
    int mlow = (lane >> 3) & 1, mhigh = lane >> 4, rr = lane & 7;
    const __half* qp = Q  + (size_t)bh * NSEQ * HD;
    const __half* kp = Kb + (size_t)bh * NSEQ * HD;
    const __half* vp = Vt + (size_t)bh * NSEQ * HD;   /* [d][n] */
    const float* mbp = mb + b * NSEQ;

    uint32_t Ks_u = s2u(Ks), Vt_u = s2u(Vts), Ps_u = s2u(Ps);
    uint32_t koff = ((mhigh*8 + rr)*KPADH + mlow*8)*2;
    uint32_t voff = ((mhigh*8 + rr)*VTPADH + mlow*8)*2;
    uint32_t poff = Ps_u + ((mlow*8 + rr)*PPADH + mhigh*8)*2 + w*16*PPADH*2;
    uint32_t qoff = Ps_u + ((w*16 + mlow*8 + rr)*KPADH + mhigh*8)*2;

    /* prologue FIRST: issue K/V/MB tiles 0 and 1 (overlaps Q staging) */
    #pragma unroll
    for (int p = 0; p < 2; p++) {
        int k0 = p * 64;
        #pragma unroll
        for (int i = 0; i < 2; i++) {
            int idx = tid + i*256;
            if (idx < 384) {
                int r = idx / 6, c = (idx % 6) * 8;
                cpa16(Ks + p*KST + r*KPADH + c, kp + (size_t)(k0 + r)*HD + c);
                int rv = idx >> 3, cv = (idx & 7) * 8;
                cpa16(Vts + p*VST + rv*VTPADH + cv, vp + (size_t)rv*NSEQ + k0 + cv);
            }
        }
        if (tid < 64) cpa4(MBs + p*64 + tid, mbp + k0 + tid);
        CP_COMMIT();
    }

    /* stage Q into Ps region ([128][56] halves), extract fragments */
    #pragma unroll
    for (int i = 0; i < 3; i++) {
        int idx = tid + i*256;
        int r = idx / 6, c = (idx % 6) * 8;
        *(uint4*)(Ps + r*KPADH + c) = *(const uint4*)(qp + (size_t)(q0 + r)*HD + c);
    }
    __syncthreads();
    uint32_t qf[3][4];
    #pragma unroll
    for (int ks = 0; ks < 3; ks++)
        ldsm4(qf[ks][0], qf[ks][1], qf[ks][2], qf[ks][3], qoff + ks*32);
    /* NOTE: Ps reused for P; first overwrite happens after the mainloop's
       first __syncthreads, so no extra barrier needed here beyond this one: */
    __syncthreads();

    float o[6][4];
    #pragma unroll
    for (int nj = 0; nj < 6; nj++)
        #pragma unroll
        for (int r = 0; r < 4; r++) o[nj][r] = 0.f;
    float mA = -INFINITY, mB = -INFINITY, lA = 0.f, lB = 0.f;
    const float scale2 = 0.14433756729740643f * 1.4426950408889634f;

    int st = 0;
    for (int kt = 0; kt < NT; kt++) {
        cp_wait<1>();
        __syncthreads();
        if (kt + 2 < NT) {
            int k0 = (kt + 2) * 64;
            int sn = st + 2; if (sn >= 3) sn -= 3;
            #pragma unroll
            for (int i = 0; i < 2; i++) {
                int idx = tid + i*256;
                if (idx < 384) {
                    int r = idx / 6, c = (idx % 6) * 8;
                    cpa16(Ks + sn*KST + r*KPADH + c, kp + (size_t)(k0 + r)*HD + c);
                    int rv = idx >> 3, cv = (idx & 7) * 8;
                    cpa16(Vts + sn*VST + rv*VTPADH + cv, vp + (size_t)rv*NSEQ + k0 + cv);
                }
            }
            if (tid < 64) cpa4(MBs + sn*64 + tid, mbp + k0 + tid);
        }
        CP_COMMIT();

        uint32_t Kst_u = Ks_u + st*KST*2;
        uint32_t Vst_u = Vt_u + st*VST*2;
        const float* MBst = MBs + st*64;

        /* S = Q K^T : warp tile 16x64 */
        float s[8][4];
        #pragma unroll
        for (int nj = 0; nj < 8; nj++)
            #pragma unroll
            for (int r = 0; r < 4; r++) s[nj][r] = 0.f;
        #pragma unroll
        for (int ks = 0; ks < 3; ks++) {
            uint32_t kbb = ks*32;
            #pragma unroll
            for (int njp = 0; njp < 4; njp++) {
                uint32_t b0, b1, b2, b3;
                ldsm4(b0, b1, b2, b3, Kst_u + koff + njp*16*KPADH*2 + kbb);
                mma16(s[2*njp],   qf[ks][0], qf[ks][1], qf[ks][2], qf[ks][3], b0, b1);
                mma16(s[2*njp+1], qf[ks][0], qf[ks][1], qf[ks][2], qf[ks][3], b2, b3);
            }
        }

        /* scale (exp2 domain) + mask bias, row max */
        float mxA = -INFINITY, mxB = -INFINITY;
        #pragma unroll
        for (int nj = 0; nj < 8; nj++) {
            float2 mbv = *(const float2*)(MBst + nj*8 + 2*t);
            s[nj][0] = s[nj][0]*scale2 + mbv.x;
            s[nj][1] = s[nj][1]*scale2 + mbv.y;
            s[nj][2] = s[nj][2]*scale2 + mbv.x;
            s[nj][3] = s[nj][3]*scale2 + mbv.y;
            mxA = fmaxf(mxA, fmaxf(s[nj][0], s[nj][1]));
            mxB = fmaxf(mxB, fmaxf(s[nj][2], s[nj][3]));
        }
        mxA = fmaxf(mxA, __shfl_xor_sync(0xffffffffu, mxA, 1));
        mxA = fmaxf(mxA, __shfl_xor_sync(0xffffffffu, mxA, 2));
        mxB = fmaxf(mxB, __shfl_xor_sync(0xffffffffu, mxB, 1));
        mxB = fmaxf(mxB, __shfl_xor_sync(0xffffffffu, mxB, 2));

        float mAn = fmaxf(mA, mxA), fA = ex2(mA - mAn);
        float mBn = fmaxf(mB, mxB), fB = ex2(mB - mBn);
        mA = mAn; mB = mBn;
        lA *= fA;  lB *= fB;

        /* P = exp2(S - m) -> fp16 warp-private smem via stmatrix.x4 */
        #pragma unroll
        for (int nj = 0; nj < 8; nj++) {
            s[nj][0] = ex2(s[nj][0] - mA);
            s[nj][1] = ex2(s[nj][1] - mA);
            s[nj][2] = ex2(s[nj][2] - mB);
            s[nj][3] = ex2(s[nj][3] - mB);
            lA += s[nj][0] + s[nj][1]; lB += s[nj][2] + s[nj][3];
        }
        #pragma unroll
        for (int j = 0; j < 4; j++) {
            stsm4(poff + j*32,
                  h2pack(s[2*j][0],   s[2*j][1]),
                  h2pack(s[2*j][2],   s[2*j][3]),
                  h2pack(s[2*j+1][0], s[2*j+1][1]),
                  h2pack(s[2*j+1][2], s[2*j+1][3]));
        }
        #pragma unroll
        for (int nj = 0; nj < 6; nj++) {
            o[nj][0] *= fA; o[nj][1] *= fA;
            o[nj][2] *= fB; o[nj][3] *= fB;
        }
        __syncwarp();

        /* O += P V */
        #pragma unroll
        for (int ks = 0; ks < 4; ks++) {
            uint32_t kbb = ks*32;
            uint32_t a0, a1, a2, a3;
            ldsm4(a0, a1, a2, a3, poff + kbb);
            #pragma unroll
            for (int njp = 0; njp < 3; njp++) {
                uint32_t b0, b1, b2, b3;
                ldsm4(b0, b1, b2, b3, Vst_u + voff + njp*16*VTPADH*2 + kbb);
                mma16(o[2*njp],   a0, a1, a2, a3, b0, b1);
                mma16(o[2*njp+1], a0, a1, a2, a3, b2, b3);
            }
        }
        if (++st == 3) st = 0;
    }

    /* epilogue */
    lA += __shfl_xor_sync(0xffffffffu, lA, 1);
    lA += __shfl_xor_sync(0xffffffffu, lA, 2);
    lB += __shfl_xor_sync(0xffffffffu, lB, 1);
    lB += __shfl_xor_sync(0xffffffffu, lB, 2);
    float invA = 1.0f / lA, invB = 1.0f / lB;
    int rA = q0 + w*16 + g, rB = rA + 8;
    #pragma unroll
    for (int nj = 0; nj < 6; nj++) {
        int cb = nj*8 + 2*t;
        *(uint32_t*)(O + ((size_t)(b*NSEQ + rA))*BDIM + h*HD + cb) =
            h2pack(o[nj][0]*invA, o[nj][1]*invA);
        *(uint32_t*)(O + ((size_t)(b*NSEQ + rB))*BDIM + h*HD + cb) =
            h2pack(o[nj][2]*invB, o[nj][3]*invB);
    }
}

/* ------------------------------ launch ------------------------------ */
extern "C" void kernel_launch(void* const* d_in, const int* in_sizes, int n_in,
                              void* d_out, int out_size) {
    const float* x    = (const float*)d_in[0];
    const float* pos  = (const float*)d_in[1];
    const void*  mask = d_in[2];
    const float* Wq   = (const float*)d_in[3];
    const float* bq   = (const float*)d_in[4];
    const float* Wk   = (const float*)d_in[5];
    const float* bk   = (const float*)d_in[6];
    const float* Wv   = (const float*)d_in[7];
    const float* bv   = (const float*)d_in[8];
    const float* pw1  = (const float*)d_in[9];
    const float* pb1  = (const float*)d_in[10];
    const float* pw2  = (const float*)d_in[11];
    const float* pb2  = (const float*)d_in[12];
    const float* Wo   = (const float*)d_in[13];
    const float* bo   = (const float*)d_in[14];
    const float* mw1  = (const float*)d_in[15];
    const float* mb1  = (const float*)d_in[16];
    const float* mw2  = (const float*)d_in[17];
    const float* mb2  = (const float*)d_in[18];
    const float* g1   = (const float*)d_in[19];
    const float* be1  = (const float*)d_in[20];
    const float* g2   = (const float*)d_in[21];
    const float* be2  = (const float*)d_in[22];
    float* out = (float*)d_out;

    void *ph, *pq, *pk, *pv, *patt, *phid, *pwq, *pwo, *pm1, *pm2;
    void *ppe, *px1, *pm, *pmb, *pbq;
    cudaGetSymbolAddress(&ph,  g_h16);
    cudaGetSymbolAddress(&pq,  g_q16);
    cudaGetSymbolAddress(&pk,  g_k16);
    cudaGetSymbolAddress(&pv,  g_v16t);
    cudaGetSymbolAddress(&patt,g_att16);
    cudaGetSymbolAddress(&phid,g_hid16);
    cudaGetSymbolAddress(&pwq, g_wqkvT);
    cudaGetSymbolAddress(&pwo, g_woT);
    cudaGetSymbolAddress(&pm1, g_mw1T);
    cudaGetSymbolAddress(&pm2, g_mw2T);
    cudaGetSymbolAddress(&ppe, g_pe);
    cudaGetSymbolAddress(&px1, g_x1);
    cudaGetSymbolAddress(&pm,  g_mask);
    cudaGetSymbolAddress(&pmb, g_mb);
    cudaGetSymbolAddress(&pbq, g_bqkv);
    __half* h16   = (__half*)ph;
    __half* q16   = (__half*)pq;
    __half* k16   = (__half*)pk;
    __half* v16t  = (__half*)pv;
    __half* att16 = (__half*)patt;
    __half* hid16 = (__half*)phid;
    __half* wqkvT = (__half*)pwq;
    __half* woT   = (__half*)pwo;
    __half* mw1T  = (__half*)pm1;
    __half* mw2T  = (__half*)pm2;
    float* pe   = (float*)ppe;
    float* x1   = (float*)px1;
    int*   msk  = (int*)pm;
    float* mbf  = (float*)pmb;
    float* bqkv = (float*)pbq;

    cudaFuncSetAttribute(attn_tc,
                         cudaFuncAttributeMaxDynamicSharedMemorySize, ATT_SMEM);

    /* 1. mask (+float bias) */
    mask_convert_kernel<<<1, 256>>>(mask, MROWS, msk, mbf);
    /* 2. all weight transposes in one launch + bias pack */
    transpose_all_kernel<<<1728, dim3(32, 8)>>>(Wq, Wk, Wv, Wo, mw1, mw2,
                                                wqkvT, woT, mw1T, mw2T);
    pack_bias_kernel<<<(QKVN+255)/256, 256>>>(bq, bk, bv, bqkv);
    /* 3. LN1 -> fp16 */
    ln_kernel<<<MROWS, 128>>>(x, g1, be1, h16);
    /* 4. positional MLP */
    pe_kernel<<<MROWS/8, 256>>>(pos, pw1, pb1, pw2, pb2, pe);
    /* 5. fused QKV projection */
    dim3 gqkv(MROWS/GBM, QKVN/GBN);
    gemm_tc<1><<<gqkv, 256>>>(h16, wqkvT, bqkv, BDIM, QKVN, pe, nullptr,
                              nullptr, q16, k16, v16t);
    /* 6. attention */
    dim3 ga(NSEQ/BQ, NB*HEADS);
    attn_tc<<<ga, 256, ATT_SMEM>>>(q16, k16, v16t, mbf, att16);
    /* 7. Wo + mask + residual -> x1 (f32) */
    dim3 gwo(MROWS/GBM, BDIM/GBN);
    gemm_tc<2><<<gwo, 256>>>(att16, woT, bo, BDIM, BDIM, x, msk,
                             x1, nullptr, nullptr, nullptr);
    /* 8. LN2 -> fp16 */
    ln_kernel<<<MROWS, 128>>>(x1, g2, be2, h16);
    /* 9. MLP1 + gelu -> fp16 */
    dim3 gm1(MROWS/GBM, MLPH/GBN);
    gemm_tc<3><<<gm1, 256>>>(h16, mw1T, mb1, BDIM, MLPH, nullptr, nullptr,
                             nullptr, hid16, nullptr, nullptr);
    /* 10. MLP2 + residual + mask -> out (f32) */
    gemm_tc<4><<<gwo, 256>>>(hid16, mw2T, mb2, MLPH, BDIM, x1, msk,
                             out, nullptr, nullptr, nullptr);
}

// round 9
// speedup vs baseline: 1.6682x; 1.0082x over previous
#include <cuda_runtime.h>
#include <cuda_fp16.h>
#include <math.h>
#include <stdint.h>

#define BDIM 384
#define HEADS 8
#define HD 48
#define NSEQ 2048
#define NB 4
#define MROWS (NB*NSEQ)      /* 8192 */
#define MLPH 1536
#define QKVN (3*BDIM)        /* 1152 */

/* ------------ scratch (device globals; no allocation allowed) ------------ */
__device__ __half g_h16 [MROWS*BDIM];
__device__ __half g_q16 [MROWS*BDIM];
__device__ __half g_k16 [MROWS*BDIM];
__device__ __half g_v16t[MROWS*BDIM];          /* V^T: [bh][d][n] */
__device__ __half g_att16[MROWS*BDIM];
__device__ __half g_hid16[MROWS*MLPH];
__device__ __half g_wqkvT[QKVN*BDIM];
__device__ __half g_woT  [BDIM*BDIM];
__device__ __half g_mw1T [MLPH*BDIM];
__device__ __half g_mw2T [BDIM*MLPH];
__device__ float  g_pe[MROWS*HD];
__device__ float  g_x1[MROWS*BDIM];
__device__ int    g_mask[MROWS];
__device__ float  g_mb [MROWS];
__device__ float  g_bqkv[QKVN];

__device__ __forceinline__ float gelu_exact(float x) {
    return 0.5f * x * (1.0f + erff(x * 0.70710678118654752f));
}
__device__ __forceinline__ float ex2(float x) {
    float y; asm("ex2.approx.f32 %0, %1;" : "=f"(y) : "f"(x)); return y;
}
__device__ __forceinline__ uint32_t h2ex2(uint32_t x) {
    uint32_t y; asm("ex2.approx.f16x2 %0, %1;" : "=r"(y) : "r"(x)); return y;
}

/* m16n8k16 fp16 mma, fp32 accumulate. regs are packed half2. */
__device__ __forceinline__ void mma16(float* c,
                                      uint32_t a0, uint32_t a1, uint32_t a2, uint32_t a3,
                                      uint32_t b0, uint32_t b1) {
    asm volatile(
      "mma.sync.aligned.m16n8k16.row.col.f32.f16.f16.f32 "
      "{%0,%1,%2,%3},{%4,%5,%6,%7},{%8,%9},{%0,%1,%2,%3};"
      : "+f"(c[0]), "+f"(c[1]), "+f"(c[2]), "+f"(c[3])
      : "r"(a0), "r"(a1), "r"(a2), "r"(a3), "r"(b0), "r"(b1));
}

__device__ __forceinline__ void ldsm4(uint32_t& r0, uint32_t& r1,
                                      uint32_t& r2, uint32_t& r3, uint32_t a) {
    asm volatile("ldmatrix.sync.aligned.m8n8.x4.shared.b16 {%0,%1,%2,%3}, [%4];"
                 : "=r"(r0), "=r"(r1), "=r"(r2), "=r"(r3) : "r"(a));
}
__device__ __forceinline__ void ldsm2(uint32_t& r0, uint32_t& r1, uint32_t a) {
    asm volatile("ldmatrix.sync.aligned.m8n8.x2.shared.b16 {%0,%1}, [%2];"
                 : "=r"(r0), "=r"(r1) : "r"(a));
}
__device__ __forceinline__ void stsm4(uint32_t a, uint32_t r0, uint32_t r1,
                                      uint32_t r2, uint32_t r3) {
    asm volatile("stmatrix.sync.aligned.m8n8.x4.shared.b16 [%0], {%1,%2,%3,%4};"
                 :: "r"(a), "r"(r0), "r"(r1), "r"(r2), "r"(r3));
}
__device__ __forceinline__ uint32_t s2u(const void* p) {
    return (uint32_t)__cvta_generic_to_shared(p);
}
__device__ __forceinline__ void cpa16(void* dst, const void* src) {
    uint32_t d = s2u(dst);
    asm volatile("cp.async.ca.shared.global [%0], [%1], 16;" :: "r"(d), "l"(src));
}
__device__ __forceinline__ void cpa4(void* dst, const void* src) {
    uint32_t d = s2u(dst);
    asm volatile("cp.async.ca.shared.global [%0], [%1], 4;" :: "r"(d), "l"(src));
}
#define CP_COMMIT() asm volatile("cp.async.commit_group;")
template<int N> __device__ __forceinline__ void cp_wait() {
    asm volatile("cp.async.wait_group %0;" :: "n"(N));
}
__device__ __forceinline__ uint32_t h2pack(float a, float b) {
    __half2 h = __floats2half2_rn(a, b);
    return *(uint32_t*)&h;
}

/* ------------ mask dtype sniffing + conversion (+ float bias) ------------ */
__global__ void mask_convert_kernel(const void* __restrict__ mptr, int n,
                                    int* __restrict__ out, float* __restrict__ fb) {
    const unsigned char* b = (const unsigned char*)mptr;
    __shared__ int f32flag, nm4flag;
    if (threadIdx.x == 0) { f32flag = 0; nm4flag = 0; }
    __syncthreads();
    int lf = 0, ln4 = 0;
    for (int i = threadIdx.x; i < n; i += blockDim.x) {
        unsigned char c = b[i];
        if (c == 0x3Fu && (i & 3) == 3) lf = 1;
        if (c != 0u   && (i & 3) != 0) ln4 = 1;
    }
    if (lf)  atomicOr(&f32flag, 1);
    if (ln4) atomicOr(&nm4flag, 1);
    __syncthreads();
    int mode = f32flag ? 2 : (nm4flag ? 0 : 1);
    for (int i = threadIdx.x; i < n; i += blockDim.x) {
        int v;
        if      (mode == 0) v = (b[i] != 0);
        else if (mode == 1) v = (((const int*)mptr)[i]   != 0);
        else                v = (((const float*)mptr)[i] != 0.0f);
        out[i] = v;
        fb[i]  = v ? 0.0f : -1e30f;
    }
}

/* ------------ ALL weight transposes f32[K][N] -> fp16[N][K] in ONE launch -- */
__global__ void transpose_all_kernel(const float* __restrict__ Wq,
                                     const float* __restrict__ Wk,
                                     const float* __restrict__ Wv,
                                     const float* __restrict__ Wo,
                                     const float* __restrict__ mw1,
                                     const float* __restrict__ mw2,
                                     __half* __restrict__ wqkvT, __half* __restrict__ woT,
                                     __half* __restrict__ mw1T, __half* __restrict__ mw2T) {
    __shared__ float tile[32][33];
    int tIdx = blockIdx.x;
    const float* W; __half* Wt; int K, N;
    if (tIdx < 432) {
        int seg = tIdx / 144;
        W  = (seg == 0) ? Wq : (seg == 1) ? Wk : Wv;
        Wt = wqkvT + (size_t)seg * BDIM * BDIM;
        K = BDIM; N = BDIM; tIdx -= seg * 144;
    } else if (tIdx < 576) { W = Wo;  Wt = woT;  K = BDIM; N = BDIM; tIdx -= 432; }
    else if   (tIdx < 1152) { W = mw1; Wt = mw1T; K = BDIM; N = MLPH; tIdx -= 576; }
    else                    { W = mw2; Wt = mw2T; K = MLPH; N = BDIM; tIdx -= 1152; }
    int nt = N / 32;
    int n0 = (tIdx % nt) * 32, k0 = (tIdx / nt) * 32;
    int tx = threadIdx.x, ty = threadIdx.y;          /* 32 x 8 */
    #pragma unroll
    for (int i = 0; i < 32; i += 8)
        tile[ty+i][tx] = W[(size_t)(k0+ty+i)*N + n0+tx];
    __syncthreads();
    #pragma unroll
    for (int i = 0; i < 32; i += 8)
        Wt[(size_t)(n0+ty+i)*K + k0+tx] = __float2half_rn(tile[tx][ty+i]);
}

__global__ void pack_bias_kernel(const float* __restrict__ bq, const float* __restrict__ bk,
                                 const float* __restrict__ bv, float* __restrict__ bp) {
    int i = blockIdx.x*256 + threadIdx.x;
    if (i < QKVN) {
        int sec = i / BDIM, c = i % BDIM;
        bp[i] = (sec == 0) ? bq[c] : (sec == 1) ? bk[c] : bv[c];
    }
}

/* ------------ LayerNorm: one warp per row, no smem, no barriers ------------ */
__global__ __launch_bounds__(256)
void ln_kernel(const float* __restrict__ X,
               const float* __restrict__ g,
               const float* __restrict__ be,
               __half* __restrict__ Y) {
    int tid = threadIdx.x, lane = tid & 31, w = tid >> 5;
    int row = blockIdx.x*8 + w;
    const float* x = X + (size_t)row * BDIM;
    __half*      y = Y + (size_t)row * BDIM;
    float v[12];
    float s = 0.f, sq = 0.f;
    #pragma unroll
    for (int i = 0; i < 12; i++) {
        v[i] = x[lane + 32*i];
        s += v[i]; sq += v[i]*v[i];
    }
    #pragma unroll
    for (int o = 16; o; o >>= 1) {
        s  += __shfl_xor_sync(0xffffffffu, s,  o);
        sq += __shfl_xor_sync(0xffffffffu, sq, o);
    }
    float mean = s * (1.0f / BDIM);
    float var  = sq * (1.0f / BDIM) - mean * mean;
    float rstd = rsqrtf(var + 1e-5f);
    #pragma unroll
    for (int i = 0; i < 12; i++) {
        int c = lane + 32*i;
        y[c] = __float2half_rn((v[i] - mean) * rstd * g[c] + be[c]);
    }
}

/* ------------ positional MLP: one warp per row ------------ */
__global__ __launch_bounds__(256)
void pe_kernel(const float* __restrict__ pos,
               const float* __restrict__ pw1, const float* __restrict__ pb1,
               const float* __restrict__ pw2, const float* __restrict__ pb2,
               float* __restrict__ pe) {
    __shared__ float w2s[HD*HD];
    __shared__ float w1s[3*HD], b1s[HD], b2s[HD];
    int tid = threadIdx.x, lane = tid & 31, w = tid >> 5;
    for (int i = tid; i < HD*HD; i += 256) w2s[i] = pw2[i];
    if (tid < 3*HD) w1s[tid] = pw1[tid];
    else if (tid < 4*HD) b1s[tid - 3*HD] = pb1[tid - 3*HD];
    else if (tid < 5*HD) b2s[tid - 4*HD] = pb2[tid - 4*HD];
    __syncthreads();
    int row = blockIdx.x*8 + w;
    float p0 = pos[row*3], p1 = pos[row*3+1], p2 = pos[row*3+2];
    float h0, h1 = 0.f;
    {
        int k = lane;
        h0 = gelu_exact(p0*w1s[k] + p1*w1s[HD+k] + p2*w1s[2*HD+k] + b1s[k]);
    }
    if (lane < 16) {
        int k = 32 + lane;
        h1 = gelu_exact(p0*w1s[k] + p1*w1s[HD+k] + p2*w1s[2*HD+k] + b1s[k]);
    }
    float acc0 = b2s[lane];
    float acc1 = (lane < 16) ? b2s[32 + lane] : 0.f;
    #pragma unroll 8
    for (int k = 0; k < HD; k++) {
        float hk = (k < 32) ? __shfl_sync(0xffffffffu, h0, k)
                            : __shfl_sync(0xffffffffu, h1, k - 32);
        acc0 += hk * w2s[k*HD + lane];
        if (lane < 16) acc1 += hk * w2s[k*HD + 32 + lane];
    }
    pe[(size_t)row*HD + lane] = acc0;
    if (lane < 16) pe[(size_t)row*HD + 32 + lane] = acc1;
}

/* ------------ fp16 GEMM: 128x64x32, 3-stage cp.async, 1 barrier/iter ----- */
#define GBM 128
#define GBN 64
#define GBK 32
#define APADH 40
#define BPADH 40
#define AST (GBM*APADH)
#define BST (GBN*BPADH)

template<int EPI>
__global__ __launch_bounds__(256, 3)
void gemm_tc(const __half* __restrict__ A, const __half* __restrict__ Bt,
             const float* __restrict__ bias,
             int K, int Nc,
             const float* __restrict__ extra, const int* __restrict__ mask,
             float* __restrict__ Cf, __half* __restrict__ Ch,
             __half* __restrict__ Ck, __half* __restrict__ Cv) {
    __shared__ __half As[3*AST];
    __shared__ __half Bs[3*BST];
    int tid = threadIdx.x, lane = tid & 31, w = tid >> 5;
    int g = lane >> 2, t = lane & 3;
    int wm = w >> 1, wn = w & 1;
    int bm = blockIdx.x * GBM, bn = blockIdx.y * GBN;
    int mlow = (lane >> 3) & 1, mhigh = lane >> 4, rr = lane & 7;

    float acc[2][4][4];
    #pragma unroll
    for (int mi = 0; mi < 2; mi++)
        #pragma unroll
        for (int nj = 0; nj < 4; nj++)
            #pragma unroll
            for (int r = 0; r < 4; r++) acc[mi][nj][r] = 0.f;

    int a_r = tid >> 2, a_c = (tid & 3) * 8;
    int b_r = tid >> 2, b_c = (tid & 3) * 8;

    uint32_t As_u = s2u(As);
    uint32_t Bs_u = s2u(Bs);
    uint32_t aoff0 = ((wm*32 + mlow*8 + rr)*APADH + mhigh*8)*2;
    uint32_t aoff1 = aoff0 + 16*APADH*2;
    uint32_t boff0 = ((wn*32 + mhigh*8 + rr)*BPADH + mlow*8)*2;
    uint32_t boff1 = boff0 + 16*BPADH*2;

    int ntiles = K / GBK;
    #pragma unroll
    for (int p = 0; p < 2; p++) {
        int k0 = p * GBK;
        cpa16(&As[p*AST + a_r*APADH + a_c], A + (size_t)(bm + a_r)*K + k0 + a_c);
        cpa16(&As[p*AST + (a_r+64)*APADH + a_c], A + (size_t)(bm + a_r + 64)*K + k0 + a_c);
        cpa16(&Bs[p*BST + b_r*BPADH + b_c], Bt + (size_t)(bn + b_r)*K + k0 + b_c);
        CP_COMMIT();
    }

    int st = 0;
    for (int kt = 0; kt < ntiles; kt++) {
        cp_wait<1>();
        __syncthreads();
        if (kt + 2 < ntiles) {
            int k0 = (kt + 2) * GBK;
            int sn = st + 2; if (sn >= 3) sn -= 3;
            cpa16(&As[sn*AST + a_r*APADH + a_c], A + (size_t)(bm + a_r)*K + k0 + a_c);
            cpa16(&As[sn*AST + (a_r+64)*APADH + a_c], A + (size_t)(bm + a_r + 64)*K + k0 + a_c);
            cpa16(&Bs[sn*BST + b_r*BPADH + b_c], Bt + (size_t)(bn + b_r)*K + k0 + b_c);
        }
        CP_COMMIT();

        uint32_t asb = As_u + st*(AST*2);
        uint32_t bsb = Bs_u + st*(BST*2);
        #pragma unroll
        for (int ks = 0; ks < 2; ks++) {
            uint32_t kbb = ks*32;
            uint32_t af0[4], af1[4], bb0[4], bb1[4];
            ldsm4(af0[0], af0[1], af0[2], af0[3], asb + aoff0 + kbb);
            ldsm4(af1[0], af1[1], af1[2], af1[3], asb + aoff1 + kbb);
            ldsm4(bb0[0], bb0[1], bb0[2], bb0[3], bsb + boff0 + kbb);
            ldsm4(bb1[0], bb1[1], bb1[2], bb1[3], bsb + boff1 + kbb);
            mma16(acc[0][0], af0[0], af0[1], af0[2], af0[3], bb0[0], bb0[1]);
            mma16(acc[0][1], af0[0], af0[1], af0[2], af0[3], bb0[2], bb0[3]);
            mma16(acc[0][2], af0[0], af0[1], af0[2], af0[3], bb1[0], bb1[1]);
            mma16(acc[0][3], af0[0], af0[1], af0[2], af0[3], bb1[2], bb1[3]);
            mma16(acc[1][0], af1[0], af1[1], af1[2], af1[3], bb0[0], bb0[1]);
            mma16(acc[1][1], af1[0], af1[1], af1[2], af1[3], bb0[2], bb0[3]);
            mma16(acc[1][2], af1[0], af1[1], af1[2], af1[3], bb1[0], bb1[1]);
            mma16(acc[1][3], af1[0], af1[1], af1[2], af1[3], bb1[2], bb1[3]);
        }
        if (++st == 3) st = 0;
    }

    #pragma unroll
    for (int mi = 0; mi < 2; mi++) {
        #pragma unroll
        for (int half = 0; half < 2; half++) {
            int row = bm + wm*32 + mi*16 + g + half*8;
            #pragma unroll
            for (int nj = 0; nj < 4; nj++) {
                int col = bn + wn*32 + nj*8 + 2*t;
                float v0 = acc[mi][nj][half*2+0] + bias[col];
                float v1 = acc[mi][nj][half*2+1] + bias[col+1];
                if (EPI == 1) {
                    int sec = col / BDIM;
                    int c2  = col - sec*BDIM;
                    int d = c2 % HD, hh = c2 / HD;
                    int bb = row >> 11, n = row & (NSEQ-1);
                    if (sec == 2) {
                        __half* p = Cv + ((size_t)((bb*HEADS + hh)*HD + d))*NSEQ + n;
                        p[0]    = __float2half_rn(v0);
                        p[NSEQ] = __float2half_rn(v1);
                    } else {
                        if (sec == 1) {
                            v0 += extra[(size_t)row*HD + d];
                            v1 += extra[(size_t)row*HD + d + 1];
                        }
                        __half* base = (sec == 0) ? Ch : Ck;
                        __half* p = base + (((size_t)(bb*HEADS + hh))*NSEQ + n)*HD + d;
                        *(uint32_t*)p = h2pack(v0, v1);
                    }
                } else if (EPI == 2) {
                    float m = (float)mask[row];
                    v0 = v0*m + extra[(size_t)row*Nc + col];
                    v1 = v1*m + extra[(size_t)row*Nc + col + 1];
                    float* p = Cf + (size_t)row*Nc + col;
                    p[0] = v0; p[1] = v1;
                } else if (EPI == 3) {
                    *(uint32_t*)(Ch + (size_t)row*Nc + col) =
                        h2pack(gelu_exact(v0), gelu_exact(v1));
                } else {
                    float m = (float)mask[row];
                    v0 = (v0 + extra[(size_t)row*Nc + col])*m;
                    v1 = (v1 + extra[(size_t)row*Nc + col + 1])*m;
                    float* p = Cf + (size_t)row*Nc + col;
                    p[0] = v0; p[1] = v1;
                }
            }
        }
    }
}

/* ------- flash attention: f16x2 ex2 softmax + l via ones-row mma ---------- */
#define KPADH 56
#define VTPADH 72
#define PPADH 72
#define BQ 128
#define NT (NSEQ/64)
#define KST (64*KPADH)
#define VST (56*VTPADH)                              /* rows 48..55 = ones/zeros */
#define ATT_H_KS 0
#define ATT_H_VT (3*KST)                             /* 10752 */
#define ATT_H_PS (ATT_H_VT + 3*VST)                  /* 22848 */
#define ATT_H_END (ATT_H_PS + 8*16*PPADH)            /* 32064 halves */
#define ATT_MB_OFF ATT_H_END
#define ATT_SMEM (ATT_H_END*2 + 3*64*4)              /* 64896 B */

__global__ __launch_bounds__(256, 2)
void attn_tc(const __half* __restrict__ Q, const __half* __restrict__ Kb,
             const __half* __restrict__ Vt, const float* __restrict__ mb,
             __half* __restrict__ O) {
    extern __shared__ __half smh[];
    __half* Ks  = smh + ATT_H_KS;
    __half* Vts = smh + ATT_H_VT;
    __half* Ps  = smh + ATT_H_PS;
    float*  MBs = (float*)(smh + ATT_MB_OFF);

    int bh = blockIdx.y, b = bh >> 3, h = bh & 7;
    int q0 = blockIdx.x * BQ;
    int tid = threadIdx.x, lane = tid & 31, w = tid >> 5;
    int g = lane >> 2, t = lane & 3;
    int mlow = (lane >> 3) & 1, mhigh = lane >> 4, rr = lane & 7;
    const __half* qp = Q  + (size_t)bh * NSEQ * HD;
    const __half* kp = Kb + (size_t)bh * NSEQ * HD;
    const __half* vp = Vt + (size_t)bh * NSEQ * HD;   /* [d][n] */
    const float* mbp = mb + b * NSEQ;

    uint32_t Ks_u = s2u(Ks), Vt_u = s2u(Vts), Ps_u = s2u(Ps);
    uint32_t koff = ((mhigh*8 + rr)*KPADH + mlow*8)*2;
    uint32_t voff = ((mhigh*8 + rr)*VTPADH + mlow*8)*2;
    uint32_t loff = ((48 + rr)*VTPADH + mlow*8)*2;    /* ones-row ldsm.x2 */
    uint32_t poff = Ps_u + ((mlow*8 + rr)*PPADH + mhigh*8)*2 + w*16*PPADH*2;
    uint32_t qoff = Ps_u + ((w*16 + mlow*8 + rr)*KPADH + mhigh*8)*2;

    /* prologue FIRST: issue K/V/MB tiles 0 and 1 (overlaps Q staging) */
    #pragma unroll
    for (int p = 0; p < 2; p++) {
        int k0 = p * 64;
        #pragma unroll
        for (int i = 0; i < 2; i++) {
            int idx = tid + i*256;
            if (idx < 384) {
                int r = idx / 6, c = (idx % 6) * 8;
                cpa16(Ks + p*KST + r*KPADH + c, kp + (size_t)(k0 + r)*HD + c);
                int rv = idx >> 3, cv = (idx & 7) * 8;
                cpa16(Vts + p*VST + rv*VTPADH + cv, vp + (size_t)rv*NSEQ + k0 + cv);
            }
        }
        if (tid < 64) cpa4(MBs + p*64 + tid, mbp + k0 + tid);
        CP_COMMIT();
    }

    /* init ones/zeros rows 48..55 of V^T stages (never touched by cp.async) */
    {
        const __half one = __float2half(1.0f), zero = __float2half(0.0f);
        for (int idx = tid; idx < 3*8*64; idx += 256) {
            int stg = idx / 512, rem = idx - stg*512;
            int rw = 48 + rem / 64, cc = rem % 64;
            Vts[stg*VST + rw*VTPADH + cc] = (rw == 48) ? one : zero;
        }
    }

    /* stage Q into Ps region ([128][56] halves), extract fragments */
    #pragma unroll
    for (int i = 0; i < 3; i++) {
        int idx = tid + i*256;
        int r = idx / 6, c = (idx % 6) * 8;
        *(uint4*)(Ps + r*KPADH + c) = *(const uint4*)(qp + (size_t)(q0 + r)*HD + c);
    }
    __syncthreads();
    uint32_t qf[3][4];
    #pragma unroll
    for (int ks = 0; ks < 3; ks++)
        ldsm4(qf[ks][0], qf[ks][1], qf[ks][2], qf[ks][3], qoff + ks*32);
    __syncthreads();

    float o[6][4];
    #pragma unroll
    for (int nj = 0; nj < 6; nj++)
        #pragma unroll
        for (int r = 0; r < 4; r++) o[nj][r] = 0.f;
    float l4[4] = {0.f, 0.f, 0.f, 0.f};
    float mA = -INFINITY, mB = -INFINITY;
    const float scale2 = 0.14433756729740643f * 1.4426950408889634f;

    int st = 0;
    for (int kt = 0; kt < NT; kt++) {
        cp_wait<1>();
        __syncthreads();
        if (kt + 2 < NT) {
            int k0 = (kt + 2) * 64;
            int sn = st + 2; if (sn >= 3) sn -= 3;
            #pragma unroll
            for (int i = 0; i < 2; i++) {
                int idx = tid + i*256;
                if (idx < 384) {
                    int r = idx / 6, c = (idx % 6) * 8;
                    cpa16(Ks + sn*KST + r*KPADH + c, kp + (size_t)(k0 + r)*HD + c);
                    int rv = idx >> 3, cv = (idx & 7) * 8;
                    cpa16(Vts + sn*VST + rv*VTPADH + cv, vp + (size_t)rv*NSEQ + k0 + cv);
                }
            }
            if (tid < 64) cpa4(MBs + sn*64 + tid, mbp + k0 + tid);
        }
        CP_COMMIT();

        uint32_t Kst_u = Ks_u + st*KST*2;
        uint32_t Vst_u = Vt_u + st*VST*2;
        const float* MBst = MBs + st*64;

        /* S = Q K^T : warp tile 16x64 */
        float s[8][4];
        #pragma unroll
        for (int nj = 0; nj < 8; nj++)
            #pragma unroll
            for (int r = 0; r < 4; r++) s[nj][r] = 0.f;
        #pragma unroll
        for (int ks = 0; ks < 3; ks++) {
            uint32_t kbb = ks*32;
            #pragma unroll
            for (int njp = 0; njp < 4; njp++) {
                uint32_t b0, b1, b2, b3;
                ldsm4(b0, b1, b2, b3, Kst_u + koff + njp*16*KPADH*2 + kbb);
                mma16(s[2*njp],   qf[ks][0], qf[ks][1], qf[ks][2], qf[ks][3], b0, b1);
                mma16(s[2*njp+1], qf[ks][0], qf[ks][1], qf[ks][2], qf[ks][3], b2, b3);
            }
        }

        /* scale (exp2 domain) + mask bias, row max */
        float mxA = -INFINITY, mxB = -INFINITY;
        #pragma unroll
        for (int nj = 0; nj < 8; nj++) {
            float2 mbv = *(const float2*)(MBst + nj*8 + 2*t);
            s[nj][0] = s[nj][0]*scale2 + mbv.x;
            s[nj][1] = s[nj][1]*scale2 + mbv.y;
            s[nj][2] = s[nj][2]*scale2 + mbv.x;
            s[nj][3] = s[nj][3]*scale2 + mbv.y;
            mxA = fmaxf(mxA, fmaxf(s[nj][0], s[nj][1]));
            mxB = fmaxf(mxB, fmaxf(s[nj][2], s[nj][3]));
        }
        mxA = fmaxf(mxA, __shfl_xor_sync(0xffffffffu, mxA, 1));
        mxA = fmaxf(mxA, __shfl_xor_sync(0xffffffffu, mxA, 2));
        mxB = fmaxf(mxB, __shfl_xor_sync(0xffffffffu, mxB, 1));
        mxB = fmaxf(mxB, __shfl_xor_sync(0xffffffffu, mxB, 2));

        float mAn = fmaxf(mA, mxA), fA = ex2(mA - mAn);
        float mBn = fmaxf(mB, mxB), fB = ex2(mB - mBn);
        mA = mAn; mB = mBn;

        /* P = exp2(S - m) via f16x2 MUFU, straight into stmatrix */
        #pragma unroll
        for (int j = 0; j < 4; j++) {
            uint32_t r0 = h2ex2(h2pack(s[2*j][0]   - mA, s[2*j][1]   - mA));
            uint32_t r1 = h2ex2(h2pack(s[2*j][2]   - mB, s[2*j][3]   - mB));
            uint32_t r2 = h2ex2(h2pack(s[2*j+1][0] - mA, s[2*j+1][1] - mA));
            uint32_t r3 = h2ex2(h2pack(s[2*j+1][2] - mB, s[2*j+1][3] - mB));
            stsm4(poff + j*32, r0, r1, r2, r3);
        }
        /* rescale output + l accumulators */
        #pragma unroll
        for (int nj = 0; nj < 6; nj++) {
            o[nj][0] *= fA; o[nj][1] *= fA;
            o[nj][2] *= fB; o[nj][3] *= fB;
        }
        l4[0] *= fA; l4[2] *= fB;
        __syncwarp();

        /* O += P V ; l += P · ones (row 48 of V^T stage) */
        #pragma unroll
        for (int ks = 0; ks < 4; ks++) {
            uint32_t kbb = ks*32;
            uint32_t a0, a1, a2, a3;
            ldsm4(a0, a1, a2, a3, poff + kbb);
            #pragma unroll
            for (int njp = 0; njp < 3; njp++) {
                uint32_t b0, b1, b2, b3;
                ldsm4(b0, b1, b2, b3, Vst_u + voff + njp*16*VTPADH*2 + kbb);
                mma16(o[2*njp],   a0, a1, a2, a3, b0, b1);
                mma16(o[2*njp+1], a0, a1, a2, a3, b2, b3);
            }
            uint32_t c0, c1;
            ldsm2(c0, c1, Vst_u + loff + kbb);
            mma16(l4, a0, a1, a2, a3, c0, c1);
        }
        if (++st == 3) st = 0;
    }

    /* epilogue: l lives in column 48 -> lane t==0 of each quad */
    float lA = __shfl_sync(0xffffffffu, l4[0], lane & 28);
    float lB = __shfl_sync(0xffffffffu, l4[2], lane & 28);
    float invA = 1.0f / lA, invB = 1.0f / lB;
    int rA = q0 + w*16 + g, rB = rA + 8;
    #pragma unroll
    for (int nj = 0; nj < 6; nj++) {
        int cb = nj*8 + 2*t;
        *(uint32_t*)(O + ((size_t)(b*NSEQ + rA))*BDIM + h*HD + cb) =
            h2pack(o[nj][0]*invA, o[nj][1]*invA);
        *(uint32_t*)(O + ((size_t)(b*NSEQ + rB))*BDIM + h*HD + cb) =
            h2pack(o[nj][2]*invB, o[nj][3]*invB);
    }
}

/* ------------------------------ launch ------------------------------ */
extern "C" void kernel_launch(void* const* d_in, const int* in_sizes, int n_in,
                              void* d_out, int out_size) {
    const float* x    = (const float*)d_in[0];
    const float* pos  = (const float*)d_in[1];
    const void*  mask = d_in[2];
    const float* Wq   = (const float*)d_in[3];
    const float* bq   = (const float*)d_in[4];
    const float* Wk   = (const float*)d_in[5];
    const float* bk   = (const float*)d_in[6];
    const float* Wv   = (const float*)d_in[7];
    const float* bv   = (const float*)d_in[8];
    const float* pw1  = (const float*)d_in[9];
    const float* pb1  = (const float*)d_in[10];
    const float* pw2  = (const float*)d_in[11];
    const float* pb2  = (const float*)d_in[12];
    const float* Wo   = (const float*)d_in[13];
    const float* bo   = (const float*)d_in[14];
    const float* mw1  = (const float*)d_in[15];
    const float* mb1  = (const float*)d_in[16];
    const float* mw2  = (const float*)d_in[17];
    const float* mb2  = (const float*)d_in[18];
    const float* g1   = (const float*)d_in[19];
    const float* be1  = (const float*)d_in[20];
    const float* g2   = (const float*)d_in[21];
    const float* be2  = (const float*)d_in[22];
    float* out = (float*)d_out;

    void *ph, *pq, *pk, *pv, *patt, *phid, *pwq, *pwo, *pm1, *pm2;
    void *ppe, *px1, *pm, *pmb, *pbq;
    cudaGetSymbolAddress(&ph,  g_h16);
    cudaGetSymbolAddress(&pq,  g_q16);
    cudaGetSymbolAddress(&pk,  g_k16);
    cudaGetSymbolAddress(&pv,  g_v16t);
    cudaGetSymbolAddress(&patt,g_att16);
    cudaGetSymbolAddress(&phid,g_hid16);
    cudaGetSymbolAddress(&pwq, g_wqkvT);
    cudaGetSymbolAddress(&pwo, g_woT);
    cudaGetSymbolAddress(&pm1, g_mw1T);
    cudaGetSymbolAddress(&pm2, g_mw2T);
    cudaGetSymbolAddress(&ppe, g_pe);
    cudaGetSymbolAddress(&px1, g_x1);
    cudaGetSymbolAddress(&pm,  g_mask);
    cudaGetSymbolAddress(&pmb, g_mb);
    cudaGetSymbolAddress(&pbq, g_bqkv);
    __half* h16   = (__half*)ph;
    __half* q16   = (__half*)pq;
    __half* k16   = (__half*)pk;
    __half* v16t  = (__half*)pv;
    __half* att16 = (__half*)patt;
    __half* hid16 = (__half*)phid;
    __half* wqkvT = (__half*)pwq;
    __half* woT   = (__half*)pwo;
    __half* mw1T  = (__half*)pm1;
    __half* mw2T  = (__half*)pm2;
    float* pe   = (float*)ppe;
    float* x1   = (float*)px1;
    int*   msk  = (int*)pm;
    float* mbf  = (float*)pmb;
    float* bqkv = (float*)pbq;

    cudaFuncSetAttribute(attn_tc,
                         cudaFuncAttributeMaxDynamicSharedMemorySize, ATT_SMEM);

    /* 1. mask (+float bias) */
    mask_convert_kernel<<<1, 256>>>(mask, MROWS, msk, mbf);
    /* 2. all weight transposes in one launch + bias pack */
    transpose_all_kernel<<<1728, dim3(32, 8)>>>(Wq, Wk, Wv, Wo, mw1, mw2,
                                                wqkvT, woT, mw1T, mw2T);
    pack_bias_kernel<<<(QKVN+255)/256, 256>>>(bq, bk, bv, bqkv);
    /* 3. LN1 -> fp16 */
    ln_kernel<<<MROWS/8, 256>>>(x, g1, be1, h16);
    /* 4. positional MLP */
    pe_kernel<<<MROWS/8, 256>>>(pos, pw1, pb1, pw2, pb2, pe);
    /* 5. fused QKV projection */
    dim3 gqkv(MROWS/GBM, QKVN/GBN);
    gemm_tc<1><<<gqkv, 256>>>(h16, wqkvT, bqkv, BDIM, QKVN, pe, nullptr,
                              nullptr, q16, k16, v16t);
    /* 6. attention */
    dim3 ga(NSEQ/BQ, NB*HEADS);
    attn_tc<<<ga, 256, ATT_SMEM>>>(q16, k16, v16t, mbf, att16);
    /* 7. Wo + mask + residual -> x1 (f32) */
    dim3 gwo(MROWS/GBM, BDIM/GBN);
    gemm_tc<2><<<gwo, 256>>>(att16, woT, bo, BDIM, BDIM, x, msk,
                             x1, nullptr, nullptr, nullptr);
    /* 8. LN2 -> fp16 */
    ln_kernel<<<MROWS/8, 256>>>(x1, g2, be2, h16);
    /* 9. MLP1 + gelu -> fp16 */
    dim3 gm1(MROWS/GBM, MLPH/GBN);
    gemm_tc<3><<<gm1, 256>>>(h16, mw1T, mb1, BDIM, MLPH, nullptr, nullptr,
                             nullptr, hid16, nullptr, nullptr);
    /* 10. MLP2 + residual + mask -> out (f32) */
    gemm_tc<4><<<gwo, 256>>>(hid16, mw2T, mb2, MLPH, BDIM, x1, msk,
                             out, nullptr, nullptr, nullptr);
}

// round 10
// speedup vs baseline: 1.7284x; 1.0361x over previous
#include <cuda_runtime.h>
#include <cuda_fp16.h>
#include <math.h>
#include <stdint.h>

#define BDIM 384
#define HEADS 8
#define HD 48
#define NSEQ 2048
#define NB 4
#define MROWS (NB*NSEQ)      /* 8192 */
#define MLPH 1536
#define QKVN (3*BDIM)        /* 1152 */

/* ------------ scratch (device globals; no allocation allowed) ------------ */
__device__ __half g_h16 [MROWS*BDIM];
__device__ __half g_q16 [MROWS*BDIM];
__device__ __half g_k16 [MROWS*BDIM];
__device__ __half g_v16t[MROWS*BDIM];          /* V^T: [bh][d][n] */
__device__ __half g_att16[MROWS*BDIM];
__device__ __half g_hid16[MROWS*MLPH];
__device__ __half g_wqkvT[QKVN*BDIM];
__device__ __half g_woT  [BDIM*BDIM];
__device__ __half g_mw1T [MLPH*BDIM];
__device__ __half g_mw2T [BDIM*MLPH];
__device__ float  g_pe[MROWS*HD];
__device__ float  g_x1[MROWS*BDIM];
__device__ int    g_mask[MROWS];
__device__ float  g_mb [MROWS];
__device__ float  g_bqkv[QKVN];

__device__ __forceinline__ float gelu_exact(float x) {
    return 0.5f * x * (1.0f + erff(x * 0.70710678118654752f));
}
__device__ __forceinline__ float ex2(float x) {
    float y; asm("ex2.approx.f32 %0, %1;" : "=f"(y) : "f"(x)); return y;
}
__device__ __forceinline__ uint32_t h2ex2(uint32_t x) {
    uint32_t y; asm("ex2.approx.f16x2 %0, %1;" : "=r"(y) : "r"(x)); return y;
}

/* m16n8k16 fp16 mma, fp32 accumulate. regs are packed half2. */
__device__ __forceinline__ void mma16(float* c,
                                      uint32_t a0, uint32_t a1, uint32_t a2, uint32_t a3,
                                      uint32_t b0, uint32_t b1) {
    asm volatile(
      "mma.sync.aligned.m16n8k16.row.col.f32.f16.f16.f32 "
      "{%0,%1,%2,%3},{%4,%5,%6,%7},{%8,%9},{%0,%1,%2,%3};"
      : "+f"(c[0]), "+f"(c[1]), "+f"(c[2]), "+f"(c[3])
      : "r"(a0), "r"(a1), "r"(a2), "r"(a3), "r"(b0), "r"(b1));
}

__device__ __forceinline__ void ldsm4(uint32_t& r0, uint32_t& r1,
                                      uint32_t& r2, uint32_t& r3, uint32_t a) {
    asm volatile("ldmatrix.sync.aligned.m8n8.x4.shared.b16 {%0,%1,%2,%3}, [%4];"
                 : "=r"(r0), "=r"(r1), "=r"(r2), "=r"(r3) : "r"(a));
}
__device__ __forceinline__ void ldsm2(uint32_t& r0, uint32_t& r1, uint32_t a) {
    asm volatile("ldmatrix.sync.aligned.m8n8.x2.shared.b16 {%0,%1}, [%2];"
                 : "=r"(r0), "=r"(r1) : "r"(a));
}
__device__ __forceinline__ uint32_t s2u(const void* p) {
    return (uint32_t)__cvta_generic_to_shared(p);
}
__device__ __forceinline__ void cpa16(void* dst, const void* src) {
    uint32_t d = s2u(dst);
    asm volatile("cp.async.ca.shared.global [%0], [%1], 16;" :: "r"(d), "l"(src));
}
__device__ __forceinline__ void cpa4(void* dst, const void* src) {
    uint32_t d = s2u(dst);
    asm volatile("cp.async.ca.shared.global [%0], [%1], 4;" :: "r"(d), "l"(src));
}
#define CP_COMMIT() asm volatile("cp.async.commit_group;")
template<int N> __device__ __forceinline__ void cp_wait() {
    asm volatile("cp.async.wait_group %0;" :: "n"(N));
}
__device__ __forceinline__ uint32_t h2pack(float a, float b) {
    __half2 h = __floats2half2_rn(a, b);
    return *(uint32_t*)&h;
}

/* ------------ mask dtype sniffing + conversion (+ float bias) ------------ */
__global__ void mask_convert_kernel(const void* __restrict__ mptr, int n,
                                    int* __restrict__ out, float* __restrict__ fb) {
    const unsigned char* b = (const unsigned char*)mptr;
    __shared__ int f32flag, nm4flag;
    if (threadIdx.x == 0) { f32flag = 0; nm4flag = 0; }
    __syncthreads();
    int lf = 0, ln4 = 0;
    for (int i = threadIdx.x; i < n; i += blockDim.x) {
        unsigned char c = b[i];
        if (c == 0x3Fu && (i & 3) == 3) lf = 1;
        if (c != 0u   && (i & 3) != 0) ln4 = 1;
    }
    if (lf)  atomicOr(&f32flag, 1);
    if (ln4) atomicOr(&nm4flag, 1);
    __syncthreads();
    int mode = f32flag ? 2 : (nm4flag ? 0 : 1);
    for (int i = threadIdx.x; i < n; i += blockDim.x) {
        int v;
        if      (mode == 0) v = (b[i] != 0);
        else if (mode == 1) v = (((const int*)mptr)[i]   != 0);
        else                v = (((const float*)mptr)[i] != 0.0f);
        out[i] = v;
        fb[i]  = v ? 0.0f : -1e30f;
    }
}

/* ------------ ALL weight transposes f32[K][N] -> fp16[N][K] in ONE launch -- */
__global__ void transpose_all_kernel(const float* __restrict__ Wq,
                                     const float* __restrict__ Wk,
                                     const float* __restrict__ Wv,
                                     const float* __restrict__ Wo,
                                     const float* __restrict__ mw1,
                                     const float* __restrict__ mw2,
                                     __half* __restrict__ wqkvT, __half* __restrict__ woT,
                                     __half* __restrict__ mw1T, __half* __restrict__ mw2T) {
    __shared__ float tile[32][33];
    int tIdx = blockIdx.x;
    const float* W; __half* Wt; int K, N;
    if (tIdx < 432) {
        int seg = tIdx / 144;
        W  = (seg == 0) ? Wq : (seg == 1) ? Wk : Wv;
        Wt = wqkvT + (size_t)seg * BDIM * BDIM;
        K = BDIM; N = BDIM; tIdx -= seg * 144;
    } else if (tIdx < 576) { W = Wo;  Wt = woT;  K = BDIM; N = BDIM; tIdx -= 432; }
    else if   (tIdx < 1152) { W = mw1; Wt = mw1T; K = BDIM; N = MLPH; tIdx -= 576; }
    else                    { W = mw2; Wt = mw2T; K = MLPH; N = BDIM; tIdx -= 1152; }
    int nt = N / 32;
    int n0 = (tIdx % nt) * 32, k0 = (tIdx / nt) * 32;
    int tx = threadIdx.x, ty = threadIdx.y;          /* 32 x 8 */
    #pragma unroll
    for (int i = 0; i < 32; i += 8)
        tile[ty+i][tx] = W[(size_t)(k0+ty+i)*N + n0+tx];
    __syncthreads();
    #pragma unroll
    for (int i = 0; i < 32; i += 8)
        Wt[(size_t)(n0+ty+i)*K + k0+tx] = __float2half_rn(tile[tx][ty+i]);
}

__global__ void pack_bias_kernel(const float* __restrict__ bq, const float* __restrict__ bk,
                                 const float* __restrict__ bv, float* __restrict__ bp) {
    int i = blockIdx.x*256 + threadIdx.x;
    if (i < QKVN) {
        int sec = i / BDIM, c = i % BDIM;
        bp[i] = (sec == 0) ? bq[c] : (sec == 1) ? bk[c] : bv[c];
    }
}

/* ------------ LayerNorm: one warp per row, no smem, no barriers ------------ */
__global__ __launch_bounds__(256)
void ln_kernel(const float* __restrict__ X,
               const float* __restrict__ g,
               const float* __restrict__ be,
               __half* __restrict__ Y) {
    int tid = threadIdx.x, lane = tid & 31, w = tid >> 5;
    int row = blockIdx.x*8 + w;
    const float* x = X + (size_t)row * BDIM;
    __half*      y = Y + (size_t)row * BDIM;
    float v[12];
    float s = 0.f, sq = 0.f;
    #pragma unroll
    for (int i = 0; i < 12; i++) {
        v[i] = x[lane + 32*i];
        s += v[i]; sq += v[i]*v[i];
    }
    #pragma unroll
    for (int o = 16; o; o >>= 1) {
        s  += __shfl_xor_sync(0xffffffffu, s,  o);
        sq += __shfl_xor_sync(0xffffffffu, sq, o);
    }
    float mean = s * (1.0f / BDIM);
    float var  = sq * (1.0f / BDIM) - mean * mean;
    float rstd = rsqrtf(var + 1e-5f);
    #pragma unroll
    for (int i = 0; i < 12; i++) {
        int c = lane + 32*i;
        y[c] = __float2half_rn((v[i] - mean) * rstd * g[c] + be[c]);
    }
}

/* ------------ positional MLP: one warp per row ------------ */
__global__ __launch_bounds__(256)
void pe_kernel(const float* __restrict__ pos,
               const float* __restrict__ pw1, const float* __restrict__ pb1,
               const float* __restrict__ pw2, const float* __restrict__ pb2,
               float* __restrict__ pe) {
    __shared__ float w2s[HD*HD];
    __shared__ float w1s[3*HD], b1s[HD], b2s[HD];
    int tid = threadIdx.x, lane = tid & 31, w = tid >> 5;
    for (int i = tid; i < HD*HD; i += 256) w2s[i] = pw2[i];
    if (tid < 3*HD) w1s[tid] = pw1[tid];
    else if (tid < 4*HD) b1s[tid - 3*HD] = pb1[tid - 3*HD];
    else if (tid < 5*HD) b2s[tid - 4*HD] = pb2[tid - 4*HD];
    __syncthreads();
    int row = blockIdx.x*8 + w;
    float p0 = pos[row*3], p1 = pos[row*3+1], p2 = pos[row*3+2];
    float h0, h1 = 0.f;
    {
        int k = lane;
        h0 = gelu_exact(p0*w1s[k] + p1*w1s[HD+k] + p2*w1s[2*HD+k] + b1s[k]);
    }
    if (lane < 16) {
        int k = 32 + lane;
        h1 = gelu_exact(p0*w1s[k] + p1*w1s[HD+k] + p2*w1s[2*HD+k] + b1s[k]);
    }
    float acc0 = b2s[lane];
    float acc1 = (lane < 16) ? b2s[32 + lane] : 0.f;
    #pragma unroll 8
    for (int k = 0; k < HD; k++) {
        float hk = (k < 32) ? __shfl_sync(0xffffffffu, h0, k)
                            : __shfl_sync(0xffffffffu, h1, k - 32);
        acc0 += hk * w2s[k*HD + lane];
        if (lane < 16) acc1 += hk * w2s[k*HD + 32 + lane];
    }
    pe[(size_t)row*HD + lane] = acc0;
    if (lane < 16) pe[(size_t)row*HD + 32 + lane] = acc1;
}

/* ------------ fp16 GEMM: 128x128x32, 3-stage cp.async, 1 barrier/iter ----
   8 warps: wm=w>>1 (32 m-rows), wn=w&1 (64 n-cols); warp tile 32x64.        */
#define GBM 128
#define GBN 128
#define GBK 32
#define APADH 40
#define BPADH 40
#define AST (GBM*APADH)
#define BST (GBN*BPADH)
#define GEMM_SMEM (3*(AST+BST)*2)     /* 61440 B */

template<int EPI>
__global__ __launch_bounds__(256, 2)
void gemm_tc(const __half* __restrict__ A, const __half* __restrict__ Bt,
             const float* __restrict__ bias,
             int K, int Nc,
             const float* __restrict__ extra, const int* __restrict__ mask,
             float* __restrict__ Cf, __half* __restrict__ Ch,
             __half* __restrict__ Ck, __half* __restrict__ Cv) {
    extern __shared__ __half gsm[];
    __half* As = gsm;
    __half* Bs = gsm + 3*AST;
    int tid = threadIdx.x, lane = tid & 31, w = tid >> 5;
    int g = lane >> 2, t = lane & 3;
    int wm = w >> 1, wn = w & 1;
    int bm = blockIdx.x * GBM, bn = blockIdx.y * GBN;
    int mlow = (lane >> 3) & 1, mhigh = lane >> 4, rr = lane & 7;

    float acc[2][8][4];
    #pragma unroll
    for (int mi = 0; mi < 2; mi++)
        #pragma unroll
        for (int nj = 0; nj < 8; nj++)
            #pragma unroll
            for (int r = 0; r < 4; r++) acc[mi][nj][r] = 0.f;

    int a_r = tid >> 2, a_c = (tid & 3) * 8;   /* 64 rows per pass, 2 passes */
    int b_r = tid >> 2, b_c = (tid & 3) * 8;

    uint32_t As_u = s2u(As);
    uint32_t Bs_u = s2u(Bs);
    uint32_t aoff0 = ((wm*32 + mlow*8 + rr)*APADH + mhigh*8)*2;
    uint32_t aoff1 = aoff0 + 16*APADH*2;
    uint32_t boffb = ((wn*64 + mhigh*8 + rr)*BPADH + mlow*8)*2;

    int ntiles = K / GBK;
    #pragma unroll
    for (int p = 0; p < 2; p++) {
        int k0 = p * GBK;
        cpa16(&As[p*AST + a_r*APADH + a_c], A + (size_t)(bm + a_r)*K + k0 + a_c);
        cpa16(&As[p*AST + (a_r+64)*APADH + a_c], A + (size_t)(bm + a_r + 64)*K + k0 + a_c);
        cpa16(&Bs[p*BST + b_r*BPADH + b_c], Bt + (size_t)(bn + b_r)*K + k0 + b_c);
        cpa16(&Bs[p*BST + (b_r+64)*BPADH + b_c], Bt + (size_t)(bn + b_r + 64)*K + k0 + b_c);
        CP_COMMIT();
    }

    int st = 0;
    for (int kt = 0; kt < ntiles; kt++) {
        cp_wait<1>();
        __syncthreads();
        if (kt + 2 < ntiles) {
            int k0 = (kt + 2) * GBK;
            int sn = st + 2; if (sn >= 3) sn -= 3;
            cpa16(&As[sn*AST + a_r*APADH + a_c], A + (size_t)(bm + a_r)*K + k0 + a_c);
            cpa16(&As[sn*AST + (a_r+64)*APADH + a_c], A + (size_t)(bm + a_r + 64)*K + k0 + a_c);
            cpa16(&Bs[sn*BST + b_r*BPADH + b_c], Bt + (size_t)(bn + b_r)*K + k0 + b_c);
            cpa16(&Bs[sn*BST + (b_r+64)*BPADH + b_c], Bt + (size_t)(bn + b_r + 64)*K + k0 + b_c);
        }
        CP_COMMIT();

        uint32_t asb = As_u + st*(AST*2);
        uint32_t bsb = Bs_u + st*(BST*2);
        #pragma unroll
        for (int ks = 0; ks < 2; ks++) {
            uint32_t kbb = ks*32;
            uint32_t af0[4], af1[4];
            ldsm4(af0[0], af0[1], af0[2], af0[3], asb + aoff0 + kbb);
            ldsm4(af1[0], af1[1], af1[2], af1[3], asb + aoff1 + kbb);
            #pragma unroll
            for (int njp = 0; njp < 4; njp++) {
                uint32_t b0, b1, b2, b3;
                ldsm4(b0, b1, b2, b3, bsb + boffb + njp*16*BPADH*2 + kbb);
                mma16(acc[0][2*njp],   af0[0], af0[1], af0[2], af0[3], b0, b1);
                mma16(acc[0][2*njp+1], af0[0], af0[1], af0[2], af0[3], b2, b3);
                mma16(acc[1][2*njp],   af1[0], af1[1], af1[2], af1[3], b0, b1);
                mma16(acc[1][2*njp+1], af1[0], af1[1], af1[2], af1[3], b2, b3);
            }
        }
        if (++st == 3) st = 0;
    }

    #pragma unroll
    for (int mi = 0; mi < 2; mi++) {
        #pragma unroll
        for (int half = 0; half < 2; half++) {
            int row = bm + wm*32 + mi*16 + g + half*8;
            #pragma unroll
            for (int nj = 0; nj < 8; nj++) {
                int col = bn + wn*64 + nj*8 + 2*t;
                float v0 = acc[mi][nj][half*2+0] + bias[col];
                float v1 = acc[mi][nj][half*2+1] + bias[col+1];
                if (EPI == 1) {
                    int sec = col / BDIM;
                    int c2  = col - sec*BDIM;
                    int d = c2 % HD, hh = c2 / HD;
                    int bb = row >> 11, n = row & (NSEQ-1);
                    if (sec == 2) {
                        __half* p = Cv + ((size_t)((bb*HEADS + hh)*HD + d))*NSEQ + n;
                        p[0]    = __float2half_rn(v0);
                        p[NSEQ] = __float2half_rn(v1);
                    } else {
                        if (sec == 1) {
                            v0 += extra[(size_t)row*HD + d];
                            v1 += extra[(size_t)row*HD + d + 1];
                        }
                        __half* base = (sec == 0) ? Ch : Ck;
                        __half* p = base + (((size_t)(bb*HEADS + hh))*NSEQ + n)*HD + d;
                        *(uint32_t*)p = h2pack(v0, v1);
                    }
                } else if (EPI == 2) {
                    float m = (float)mask[row];
                    v0 = v0*m + extra[(size_t)row*Nc + col];
                    v1 = v1*m + extra[(size_t)row*Nc + col + 1];
                    float* p = Cf + (size_t)row*Nc + col;
                    p[0] = v0; p[1] = v1;
                } else if (EPI == 3) {
                    *(uint32_t*)(Ch + (size_t)row*Nc + col) =
                        h2pack(gelu_exact(v0), gelu_exact(v1));
                } else {
                    float m = (float)mask[row];
                    v0 = (v0 + extra[(size_t)row*Nc + col])*m;
                    v1 = (v1 + extra[(size_t)row*Nc + col + 1])*m;
                    float* p = Cf + (size_t)row*Nc + col;
                    p[0] = v0; p[1] = v1;
                }
            }
        }
    }
}

/* ------- flash attention: register-direct P (no P smem round-trip) -------- */
#define KPADH 56
#define VTPADH 72
#define BQ 128
#define NT (NSEQ/64)
#define KST (64*KPADH)
#define VST (56*VTPADH)                              /* rows 48..55 = ones/zeros */
#define ATT_H_KS 0
#define ATT_H_VT (3*KST)                             /* 10752 */
#define ATT_H_QS (ATT_H_VT + 3*VST)                  /* 22848 */
#define ATT_H_END (ATT_H_QS + 128*KPADH)             /* 30016 halves */
#define ATT_MB_OFF ATT_H_END
#define ATT_SMEM (ATT_H_END*2 + 3*64*4)              /* 60800 B */

__global__ __launch_bounds__(256, 2)
void attn_tc(const __half* __restrict__ Q, const __half* __restrict__ Kb,
             const __half* __restrict__ Vt, const float* __restrict__ mb,
             __half* __restrict__ O) {
    extern __shared__ __half smh[];
    __half* Ks  = smh + ATT_H_KS;
    __half* Vts = smh + ATT_H_VT;
    __half* Qs  = smh + ATT_H_QS;
    float*  MBs = (float*)(smh + ATT_MB_OFF);

    int bh = blockIdx.y, b = bh >> 3, h = bh & 7;
    int q0 = blockIdx.x * BQ;
    int tid = threadIdx.x, lane = tid & 31, w = tid >> 5;
    int g = lane >> 2, t = lane & 3;
    int mlow = (lane >> 3) & 1, mhigh = lane >> 4, rr = lane & 7;
    const __half* qp = Q  + (size_t)bh * NSEQ * HD;
    const __half* kp = Kb + (size_t)bh * NSEQ * HD;
    const __half* vp = Vt + (size_t)bh * NSEQ * HD;   /* [d][n] */
    const float* mbp = mb + b * NSEQ;

    uint32_t Ks_u = s2u(Ks), Vt_u = s2u(Vts), Qs_u = s2u(Qs);
    uint32_t koff = ((mhigh*8 + rr)*KPADH + mlow*8)*2;
    uint32_t voff = ((mhigh*8 + rr)*VTPADH + mlow*8)*2;
    uint32_t loff = ((48 + rr)*VTPADH + mlow*8)*2;    /* ones-row ldsm.x2 */
    uint32_t qoff = Qs_u + ((w*16 + mlow*8 + rr)*KPADH + mhigh*8)*2;

    /* prologue FIRST: issue K/V/MB tiles 0 and 1 (overlaps Q staging) */
    #pragma unroll
    for (int p = 0; p < 2; p++) {
        int k0 = p * 64;
        #pragma unroll
        for (int i = 0; i < 2; i++) {
            int idx = tid + i*256;
            if (idx < 384) {
                int r = idx / 6, c = (idx % 6) * 8;
                cpa16(Ks + p*KST + r*KPADH + c, kp + (size_t)(k0 + r)*HD + c);
                int rv = idx >> 3, cv = (idx & 7) * 8;
                cpa16(Vts + p*VST + rv*VTPADH + cv, vp + (size_t)rv*NSEQ + k0 + cv);
            }
        }
        if (tid < 64) cpa4(MBs + p*64 + tid, mbp + k0 + tid);
        CP_COMMIT();
    }

    /* init ones/zeros rows 48..55 of V^T stages (never touched by cp.async) */
    {
        const __half one = __float2half(1.0f), zero = __float2half(0.0f);
        for (int idx = tid; idx < 3*8*64; idx += 256) {
            int stg = idx / 512, rem = idx - stg*512;
            int rw = 48 + rem / 64, cc = rem % 64;
            Vts[stg*VST + rw*VTPADH + cc] = (rw == 48) ? one : zero;
        }
    }

    /* stage Q ([128][56] halves), extract fragments via ldmatrix */
    #pragma unroll
    for (int i = 0; i < 3; i++) {
        int idx = tid + i*256;
        int r = idx / 6, c = (idx % 6) * 8;
        *(uint4*)(Qs + r*KPADH + c) = *(const uint4*)(qp + (size_t)(q0 + r)*HD + c);
    }
    __syncthreads();
    uint32_t qf[3][4];
    #pragma unroll
    for (int ks = 0; ks < 3; ks++)
        ldsm4(qf[ks][0], qf[ks][1], qf[ks][2], qf[ks][3], qoff + ks*32);

    float o[6][4];
    #pragma unroll
    for (int nj = 0; nj < 6; nj++)
        #pragma unroll
        for (int r = 0; r < 4; r++) o[nj][r] = 0.f;
    float l4[4] = {0.f, 0.f, 0.f, 0.f};
    float mA = -INFINITY, mB = -INFINITY;
    const float scale2 = 0.14433756729740643f * 1.4426950408889634f;

    int st = 0;
    for (int kt = 0; kt < NT; kt++) {
        cp_wait<1>();
        __syncthreads();
        if (kt + 2 < NT) {
            int k0 = (kt + 2) * 64;
            int sn = st + 2; if (sn >= 3) sn -= 3;
            #pragma unroll
            for (int i = 0; i < 2; i++) {
                int idx = tid + i*256;
                if (idx < 384) {
                    int r = idx / 6, c = (idx % 6) * 8;
                    cpa16(Ks + sn*KST + r*KPADH + c, kp + (size_t)(k0 + r)*HD + c);
                    int rv = idx >> 3, cv = (idx & 7) * 8;
                    cpa16(Vts + sn*VST + rv*VTPADH + cv, vp + (size_t)rv*NSEQ + k0 + cv);
                }
            }
            if (tid < 64) cpa4(MBs + sn*64 + tid, mbp + k0 + tid);
        }
        CP_COMMIT();

        uint32_t Kst_u = Ks_u + st*KST*2;
        uint32_t Vst_u = Vt_u + st*VST*2;
        const float* MBst = MBs + st*64;

        /* S = Q K^T : warp tile 16x64 */
        float s[8][4];
        #pragma unroll
        for (int nj = 0; nj < 8; nj++)
            #pragma unroll
            for (int r = 0; r < 4; r++) s[nj][r] = 0.f;
        #pragma unroll
        for (int ks = 0; ks < 3; ks++) {
            uint32_t kbb = ks*32;
            #pragma unroll
            for (int njp = 0; njp < 4; njp++) {
                uint32_t b0, b1, b2, b3;
                ldsm4(b0, b1, b2, b3, Kst_u + koff + njp*16*KPADH*2 + kbb);
                mma16(s[2*njp],   qf[ks][0], qf[ks][1], qf[ks][2], qf[ks][3], b0, b1);
                mma16(s[2*njp+1], qf[ks][0], qf[ks][1], qf[ks][2], qf[ks][3], b2, b3);
            }
        }

        /* scale (exp2 domain) + mask bias, row max */
        float mxA = -INFINITY, mxB = -INFINITY;
        #pragma unroll
        for (int nj = 0; nj < 8; nj++) {
            float2 mbv = *(const float2*)(MBst + nj*8 + 2*t);
            s[nj][0] = s[nj][0]*scale2 + mbv.x;
            s[nj][1] = s[nj][1]*scale2 + mbv.y;
            s[nj][2] = s[nj][2]*scale2 + mbv.x;
            s[nj][3] = s[nj][3]*scale2 + mbv.y;
            mxA = fmaxf(mxA, fmaxf(s[nj][0], s[nj][1]));
            mxB = fmaxf(mxB, fmaxf(s[nj][2], s[nj][3]));
        }
        mxA = fmaxf(mxA, __shfl_xor_sync(0xffffffffu, mxA, 1));
        mxA = fmaxf(mxA, __shfl_xor_sync(0xffffffffu, mxA, 2));
        mxB = fmaxf(mxB, __shfl_xor_sync(0xffffffffu, mxB, 1));
        mxB = fmaxf(mxB, __shfl_xor_sync(0xffffffffu, mxB, 2));

        float mAn = fmaxf(mA, mxA), fA = ex2(mA - mAn);
        float mBn = fmaxf(mB, mxB), fB = ex2(mB - mBn);
        mA = mAn; mB = mBn;

        /* rescale output + l accumulators */
        #pragma unroll
        for (int nj = 0; nj < 6; nj++) {
            o[nj][0] *= fA; o[nj][1] *= fA;
            o[nj][2] *= fB; o[nj][3] *= fB;
        }
        l4[0] *= fA; l4[2] *= fB;

        /* P = exp2(S-m) REGISTER-DIRECT into PV mma (S C-frag == PV A-frag):
           a0=(g,2t)  a1=(g+8,2t)  a2=(g,2t+8)  a3=(g+8,2t+8) for k-chunk ks:
           a0=s[2ks][0,1] a1=s[2ks][2,3] a2=s[2ks+1][0,1] a3=s[2ks+1][2,3]  */
        #pragma unroll
        for (int ks = 0; ks < 4; ks++) {
            uint32_t kbb = ks*32;
            uint32_t a0 = h2ex2(h2pack(s[2*ks][0]   - mA, s[2*ks][1]   - mA));
            uint32_t a1 = h2ex2(h2pack(s[2*ks][2]   - mB, s[2*ks][3]   - mB));
            uint32_t a2 = h2ex2(h2pack(s[2*ks+1][0] - mA, s[2*ks+1][1] - mA));
            uint32_t a3 = h2ex2(h2pack(s[2*ks+1][2] - mB, s[2*ks+1][3] - mB));
            #pragma unroll
            for (int njp = 0; njp < 3; njp++) {
                uint32_t b0, b1, b2, b3;
                ldsm4(b0, b1, b2, b3, Vst_u + voff + njp*16*VTPADH*2 + kbb);
                mma16(o[2*njp],   a0, a1, a2, a3, b0, b1);
                mma16(o[2*njp+1], a0, a1, a2, a3, b2, b3);
            }
            uint32_t c0, c1;
            ldsm2(c0, c1, Vst_u + loff + kbb);
            mma16(l4, a0, a1, a2, a3, c0, c1);
        }
        if (++st == 3) st = 0;
    }

    /* epilogue: l lives in column 48 -> lane t==0 of each quad */
    float lA = __shfl_sync(0xffffffffu, l4[0], lane & 28);
    float lB = __shfl_sync(0xffffffffu, l4[2], lane & 28);
    float invA = 1.0f / lA, invB = 1.0f / lB;
    int rA = q0 + w*16 + g, rB = rA + 8;
    #pragma unroll
    for (int nj = 0; nj < 6; nj++) {
        int cb = nj*8 + 2*t;
        *(uint32_t*)(O + ((size_t)(b*NSEQ + rA))*BDIM + h*HD + cb) =
            h2pack(o[nj][0]*invA, o[nj][1]*invA);
        *(uint32_t*)(O + ((size_t)(b*NSEQ + rB))*BDIM + h*HD + cb) =
            h2pack(o[nj][2]*invB, o[nj][3]*invB);
    }
}

/* ------------------------------ launch ------------------------------ */
extern "C" void kernel_launch(void* const* d_in, const int* in_sizes, int n_in,
                              void* d_out, int out_size) {
    const float* x    = (const float*)d_in[0];
    const float* pos  = (const float*)d_in[1];
    const void*  mask = d_in[2];
    const float* Wq   = (const float*)d_in[3];
    const float* bq   = (const float*)d_in[4];
    const float* Wk   = (const float*)d_in[5];
    const float* bk   = (const float*)d_in[6];
    const float* Wv   = (const float*)d_in[7];
    const float* bv   = (const float*)d_in[8];
    const float* pw1  = (const float*)d_in[9];
    const float* pb1  = (const float*)d_in[10];
    const float* pw2  = (const float*)d_in[11];
    const float* pb2  = (const float*)d_in[12];
    const float* Wo   = (const float*)d_in[13];
    const float* bo   = (const float*)d_in[14];
    const float* mw1  = (const float*)d_in[15];
    const float* mb1  = (const float*)d_in[16];
    const float* mw2  = (const float*)d_in[17];
    const float* mb2  = (const float*)d_in[18];
    const float* g1   = (const float*)d_in[19];
    const float* be1  = (const float*)d_in[20];
    const float* g2   = (const float*)d_in[21];
    const float* be2  = (const float*)d_in[22];
    float* out = (float*)d_out;

    void *ph, *pq, *pk, *pv, *patt, *phid, *pwq, *pwo, *pm1, *pm2;
    void *ppe, *px1, *pm, *pmb, *pbq;
    cudaGetSymbolAddress(&ph,  g_h16);
    cudaGetSymbolAddress(&pq,  g_q16);
    cudaGetSymbolAddress(&pk,  g_k16);
    cudaGetSymbolAddress(&pv,  g_v16t);
    cudaGetSymbolAddress(&patt,g_att16);
    cudaGetSymbolAddress(&phid,g_hid16);
    cudaGetSymbolAddress(&pwq, g_wqkvT);
    cudaGetSymbolAddress(&pwo, g_woT);
    cudaGetSymbolAddress(&pm1, g_mw1T);
    cudaGetSymbolAddress(&pm2, g_mw2T);
    cudaGetSymbolAddress(&ppe, g_pe);
    cudaGetSymbolAddress(&px1, g_x1);
    cudaGetSymbolAddress(&pm,  g_mask);
    cudaGetSymbolAddress(&pmb, g_mb);
    cudaGetSymbolAddress(&pbq, g_bqkv);
    __half* h16   = (__half*)ph;
    __half* q16   = (__half*)pq;
    __half* k16   = (__half*)pk;
    __half* v16t  = (__half*)pv;
    __half* att16 = (__half*)patt;
    __half* hid16 = (__half*)phid;
    __half* wqkvT = (__half*)pwq;
    __half* woT   = (__half*)pwo;
    __half* mw1T  = (__half*)pm1;
    __half* mw2T  = (__half*)pm2;
    float* pe   = (float*)ppe;
    float* x1   = (float*)px1;
    int*   msk  = (int*)pm;
    float* mbf  = (float*)pmb;
    float* bqkv = (float*)pbq;

    cudaFuncSetAttribute(attn_tc,
                         cudaFuncAttributeMaxDynamicSharedMemorySize, ATT_SMEM);
    cudaFuncSetAttribute(gemm_tc<1>,
                         cudaFuncAttributeMaxDynamicSharedMemorySize, GEMM_SMEM);
    cudaFuncSetAttribute(gemm_tc<2>,
                         cudaFuncAttributeMaxDynamicSharedMemorySize, GEMM_SMEM);
    cudaFuncSetAttribute(gemm_tc<3>,
                         cudaFuncAttributeMaxDynamicSharedMemorySize, GEMM_SMEM);
    cudaFuncSetAttribute(gemm_tc<4>,
                         cudaFuncAttributeMaxDynamicSharedMemorySize, GEMM_SMEM);

    /* 1. mask (+float bias) */
    mask_convert_kernel<<<1, 256>>>(mask, MROWS, msk, mbf);
    /* 2. all weight transposes in one launch + bias pack */
    transpose_all_kernel<<<1728, dim3(32, 8)>>>(Wq, Wk, Wv, Wo, mw1, mw2,
                                                wqkvT, woT, mw1T, mw2T);
    pack_bias_kernel<<<(QKVN+255)/256, 256>>>(bq, bk, bv, bqkv);
    /* 3. LN1 -> fp16 */
    ln_kernel<<<MROWS/8, 256>>>(x, g1, be1, h16);
    /* 4. positional MLP */
    pe_kernel<<<MROWS/8, 256>>>(pos, pw1, pb1, pw2, pb2, pe);
    /* 5. fused QKV projection */
    dim3 gqkv(MROWS/GBM, QKVN/GBN);
    gemm_tc<1><<<gqkv, 256, GEMM_SMEM>>>(h16, wqkvT, bqkv, BDIM, QKVN, pe, nullptr,
                                         nullptr, q16, k16, v16t);
    /* 6. attention */
    dim3 ga(NSEQ/BQ, NB*HEADS);
    attn_tc<<<ga, 256, ATT_SMEM>>>(q16, k16, v16t, mbf, att16);
    /* 7. Wo + mask + residual -> x1 (f32) */
    dim3 gwo(MROWS/GBM, BDIM/GBN);
    gemm_tc<2><<<gwo, 256, GEMM_SMEM>>>(att16, woT, bo, BDIM, BDIM, x, msk,
                                        x1, nullptr, nullptr, nullptr);
    /* 8. LN2 -> fp16 */
    ln_kernel<<<MROWS/8, 256>>>(x1, g2, be2, h16);
    /* 9. MLP1 + gelu -> fp16 */
    dim3 gm1(MROWS/GBM, MLPH/GBN);
    gemm_tc<3><<<gm1, 256, GEMM_SMEM>>>(h16, mw1T, mb1, BDIM, MLPH, nullptr, nullptr,
                                        nullptr, hid16, nullptr, nullptr);
    /* 10. MLP2 + residual + mask -> out (f32) */
    gemm_tc<4><<<gwo, 256, GEMM_SMEM>>>(hid16, mw2T, mb2, MLPH, BDIM, x1, msk,
                                        out, nullptr, nullptr, nullptr);
}

// round 11
// speedup vs baseline: 1.9435x; 1.1245x over previous
#include <cuda_runtime.h>
#include <cuda_fp16.h>
#include <math.h>
#include <stdint.h>

#define BDIM 384
#define HEADS 8
#define HD 48
#define NSEQ 2048
#define NB 4
#define MROWS (NB*NSEQ)      /* 8192 */
#define MLPH 1536
#define QKVN (3*BDIM)        /* 1152 */
#define SCALE2F (0.14433756729740643f * 1.4426950408889634f)  /* 48^-0.5 * log2e */

/* ------------ scratch (device globals; no allocation allowed) ------------ */
__device__ __half g_h16 [MROWS*BDIM];
__device__ __half g_q16 [MROWS*BDIM];
__device__ __half g_k16 [MROWS*BDIM];
__device__ __half g_v16t[MROWS*BDIM];          /* V^T: [bh][d][n] */
__device__ __half g_att16[MROWS*BDIM];
__device__ __half g_hid16[MROWS*MLPH];
__device__ __half g_wqkvT[QKVN*BDIM];
__device__ __half g_woT  [BDIM*BDIM];
__device__ __half g_mw1T [MLPH*BDIM];
__device__ __half g_mw2T [BDIM*MLPH];
__device__ float  g_pe[MROWS*HD];
__device__ float  g_x1[MROWS*BDIM];
__device__ int    g_mask[MROWS];
__device__ float  g_mb [MROWS];
__device__ float  g_bqkv[QKVN];

__device__ __forceinline__ float gelu_exact(float x) {
    return 0.5f * x * (1.0f + erff(x * 0.70710678118654752f));
}
__device__ __forceinline__ float ex2(float x) {
    float y; asm("ex2.approx.f32 %0, %1;" : "=f"(y) : "f"(x)); return y;
}
__device__ __forceinline__ uint32_t h2ex2(uint32_t x) {
    uint32_t y; asm("ex2.approx.f16x2 %0, %1;" : "=r"(y) : "r"(x)); return y;
}

/* m16n8k16 fp16 mma, fp32 accumulate. regs are packed half2. */
__device__ __forceinline__ void mma16(float* c,
                                      uint32_t a0, uint32_t a1, uint32_t a2, uint32_t a3,
                                      uint32_t b0, uint32_t b1) {
    asm volatile(
      "mma.sync.aligned.m16n8k16.row.col.f32.f16.f16.f32 "
      "{%0,%1,%2,%3},{%4,%5,%6,%7},{%8,%9},{%0,%1,%2,%3};"
      : "+f"(c[0]), "+f"(c[1]), "+f"(c[2]), "+f"(c[3])
      : "r"(a0), "r"(a1), "r"(a2), "r"(a3), "r"(b0), "r"(b1));
}

__device__ __forceinline__ void ldsm4(uint32_t& r0, uint32_t& r1,
                                      uint32_t& r2, uint32_t& r3, uint32_t a) {
    asm volatile("ldmatrix.sync.aligned.m8n8.x4.shared.b16 {%0,%1,%2,%3}, [%4];"
                 : "=r"(r0), "=r"(r1), "=r"(r2), "=r"(r3) : "r"(a));
}
__device__ __forceinline__ void ldsm2(uint32_t& r0, uint32_t& r1, uint32_t a) {
    asm volatile("ldmatrix.sync.aligned.m8n8.x2.shared.b16 {%0,%1}, [%2];"
                 : "=r"(r0), "=r"(r1) : "r"(a));
}
__device__ __forceinline__ uint32_t s2u(const void* p) {
    return (uint32_t)__cvta_generic_to_shared(p);
}
__device__ __forceinline__ void cpa16(void* dst, const void* src) {
    uint32_t d = s2u(dst);
    asm volatile("cp.async.ca.shared.global [%0], [%1], 16;" :: "r"(d), "l"(src));
}
__device__ __forceinline__ void cpa4(void* dst, const void* src) {
    uint32_t d = s2u(dst);
    asm volatile("cp.async.ca.shared.global [%0], [%1], 4;" :: "r"(d), "l"(src));
}
#define CP_COMMIT() asm volatile("cp.async.commit_group;")
template<int N> __device__ __forceinline__ void cp_wait() {
    asm volatile("cp.async.wait_group %0;" :: "n"(N));
}
__device__ __forceinline__ uint32_t h2pack(float a, float b) {
    __half2 h = __floats2half2_rn(a, b);
    return *(uint32_t*)&h;
}

/* ======================= fused prep kernel bodies ======================= */

/* LayerNorm: one warp per row, vectorized float4 */
__device__ __forceinline__ void ln_body(const float* __restrict__ X,
                                        const float* __restrict__ g,
                                        const float* __restrict__ be,
                                        __half* __restrict__ Y, int blk) {
    int tid = threadIdx.x, lane = tid & 31, w = tid >> 5;
    int row = blk*8 + w;
    const float* x = X + (size_t)row * BDIM;
    __half*      y = Y + (size_t)row * BDIM;
    float4 v[3];
    float s = 0.f, sq = 0.f;
    #pragma unroll
    for (int i = 0; i < 3; i++) {
        v[i] = *(const float4*)(x + lane*4 + i*128);
        s  += v[i].x + v[i].y + v[i].z + v[i].w;
        sq += v[i].x*v[i].x + v[i].y*v[i].y + v[i].z*v[i].z + v[i].w*v[i].w;
    }
    #pragma unroll
    for (int o = 16; o; o >>= 1) {
        s  += __shfl_xor_sync(0xffffffffu, s,  o);
        sq += __shfl_xor_sync(0xffffffffu, sq, o);
    }
    float mean = s * (1.0f / BDIM);
    float var  = sq * (1.0f / BDIM) - mean * mean;
    float rstd = rsqrtf(var + 1e-5f);
    #pragma unroll
    for (int i = 0; i < 3; i++) {
        int c = lane*4 + i*128;
        float4 gg = *(const float4*)(g + c);
        float4 bb = *(const float4*)(be + c);
        uint2 st;
        st.x = h2pack((v[i].x - mean)*rstd*gg.x + bb.x,
                      (v[i].y - mean)*rstd*gg.y + bb.y);
        st.y = h2pack((v[i].z - mean)*rstd*gg.z + bb.z,
                      (v[i].w - mean)*rstd*gg.w + bb.w);
        *(uint2*)(y + c) = st;
    }
}

/* positional MLP: one warp per row; sh = 2544 floats */
__device__ __forceinline__ void pe_body(float* sh,
                                        const float* __restrict__ pos,
                                        const float* __restrict__ pw1,
                                        const float* __restrict__ pb1,
                                        const float* __restrict__ pw2,
                                        const float* __restrict__ pb2,
                                        float* __restrict__ pe, int blk) {
    float* w2s = sh;            /* 2304 */
    float* w1s = sh + 2304;     /* 144 */
    float* b1s = sh + 2448;     /* 48 */
    float* b2s = sh + 2496;     /* 48 */
    int tid = threadIdx.x, lane = tid & 31, w = tid >> 5;
    for (int i = tid; i < HD*HD; i += 256) w2s[i] = pw2[i];
    if (tid < 3*HD) w1s[tid] = pw1[tid];
    else if (tid < 4*HD) b1s[tid - 3*HD] = pb1[tid - 3*HD];
    else if (tid < 5*HD) b2s[tid - 4*HD] = pb2[tid - 4*HD];
    __syncthreads();
    int row = blk*8 + w;
    float p0 = pos[row*3], p1 = pos[row*3+1], p2 = pos[row*3+2];
    float h0, h1 = 0.f;
    {
        int k = lane;
        h0 = gelu_exact(p0*w1s[k] + p1*w1s[HD+k] + p2*w1s[2*HD+k] + b1s[k]);
    }
    if (lane < 16) {
        int k = 32 + lane;
        h1 = gelu_exact(p0*w1s[k] + p1*w1s[HD+k] + p2*w1s[2*HD+k] + b1s[k]);
    }
    float acc0 = b2s[lane];
    float acc1 = (lane < 16) ? b2s[32 + lane] : 0.f;
    #pragma unroll 8
    for (int k = 0; k < HD; k++) {
        float hk = (k < 32) ? __shfl_sync(0xffffffffu, h0, k)
                            : __shfl_sync(0xffffffffu, h1, k - 32);
        acc0 += hk * w2s[k*HD + lane];
        if (lane < 16) acc1 += hk * w2s[k*HD + 32 + lane];
    }
    pe[(size_t)row*HD + lane] = acc0;
    if (lane < 16) pe[(size_t)row*HD + 32 + lane] = acc1;
}

/* one 32x32 transpose tile; sh holds tile[32][33] */
__device__ __forceinline__ void transpose_body(float* sh,
                                               const float* __restrict__ Wq,
                                               const float* __restrict__ Wk,
                                               const float* __restrict__ Wv,
                                               const float* __restrict__ Wo,
                                               const float* __restrict__ mw1,
                                               const float* __restrict__ mw2,
                                               __half* __restrict__ wqkvT,
                                               __half* __restrict__ woT,
                                               __half* __restrict__ mw1T,
                                               __half* __restrict__ mw2T, int tIdx) {
    const float* W; __half* Wt; int K, N;
    if (tIdx < 432) {
        int seg = tIdx / 144;
        W  = (seg == 0) ? Wq : (seg == 1) ? Wk : Wv;
        Wt = wqkvT + (size_t)seg * BDIM * BDIM;
        K = BDIM; N = BDIM; tIdx -= seg * 144;
    } else if (tIdx < 576) { W = Wo;  Wt = woT;  K = BDIM; N = BDIM; tIdx -= 432; }
    else if   (tIdx < 1152) { W = mw1; Wt = mw1T; K = BDIM; N = MLPH; tIdx -= 576; }
    else                    { W = mw2; Wt = mw2T; K = MLPH; N = BDIM; tIdx -= 1152; }
    int nt = N / 32;
    int n0 = (tIdx % nt) * 32, k0 = (tIdx / nt) * 32;
    int tx = threadIdx.x & 31, ty = threadIdx.x >> 5;  /* 32 x 8 */
    #pragma unroll
    for (int i = 0; i < 32; i += 8)
        sh[(ty+i)*33 + tx] = W[(size_t)(k0+ty+i)*N + n0+tx];
    __syncthreads();
    #pragma unroll
    for (int i = 0; i < 32; i += 8)
        Wt[(size_t)(n0+ty+i)*K + k0+tx] = __float2half_rn(sh[tx*33 + ty+i]);
}

/* mask sniff + convert (single block) */
__device__ __forceinline__ void mask_body(float* sh, const void* __restrict__ mptr,
                                          int n, int* __restrict__ out,
                                          float* __restrict__ fb) {
    int* ish = (int*)sh;
    const unsigned char* b = (const unsigned char*)mptr;
    if (threadIdx.x == 0) { ish[0] = 0; ish[1] = 0; }
    __syncthreads();
    int lf = 0, ln4 = 0;
    for (int i = threadIdx.x; i < n; i += 256) {
        unsigned char c = b[i];
        if (c == 0x3Fu && (i & 3) == 3) lf = 1;
        if (c != 0u   && (i & 3) != 0) ln4 = 1;
    }
    if (lf)  atomicOr(&ish[0], 1);
    if (ln4) atomicOr(&ish[1], 1);
    __syncthreads();
    int mode = ish[0] ? 2 : (ish[1] ? 0 : 1);
    for (int i = threadIdx.x; i < n; i += 256) {
        int v;
        if      (mode == 0) v = (b[i] != 0);
        else if (mode == 1) v = (((const int*)mptr)[i]   != 0);
        else                v = (((const float*)mptr)[i] != 0.0f);
        out[i] = v;
        fb[i]  = v ? 0.0f : -1e30f;
    }
}

__global__ __launch_bounds__(256)
void prep_kernel(const float* __restrict__ x,
                 const float* __restrict__ g1, const float* __restrict__ be1,
                 __half* __restrict__ h16,
                 const float* __restrict__ pos,
                 const float* __restrict__ pw1, const float* __restrict__ pb1,
                 const float* __restrict__ pw2, const float* __restrict__ pb2,
                 float* __restrict__ pe,
                 const float* __restrict__ Wq, const float* __restrict__ Wk,
                 const float* __restrict__ Wv, const float* __restrict__ Wo,
                 const float* __restrict__ mw1, const float* __restrict__ mw2,
                 __half* __restrict__ wqkvT, __half* __restrict__ woT,
                 __half* __restrict__ mw1T, __half* __restrict__ mw2T,
                 const void* __restrict__ mask, int* __restrict__ msk,
                 float* __restrict__ mbf,
                 const float* __restrict__ bq, const float* __restrict__ bk,
                 const float* __restrict__ bv, float* __restrict__ bqkv) {
    __shared__ float sh[2544];
    int bid = blockIdx.x;
    if (bid < 1024) {
        ln_body(x, g1, be1, h16, bid);
    } else if (bid < 2048) {
        pe_body(sh, pos, pw1, pb1, pw2, pb2, pe, bid - 1024);
    } else if (bid < 3776) {
        transpose_body(sh, Wq, Wk, Wv, Wo, mw1, mw2,
                       wqkvT, woT, mw1T, mw2T, bid - 2048);
    } else if (bid == 3776) {
        mask_body(sh, mask, MROWS, msk, mbf);
    } else {
        for (int i = threadIdx.x; i < QKVN; i += 256) {
            int sec = i / BDIM, c = i % BDIM;
            bqkv[i] = (sec == 0) ? bq[c] : (sec == 1) ? bk[c] : bv[c];
        }
    }
}

/* standalone LN (for LN2) */
__global__ __launch_bounds__(256)
void ln_kernel(const float* __restrict__ X,
               const float* __restrict__ g,
               const float* __restrict__ be,
               __half* __restrict__ Y) {
    ln_body(X, g, be, Y, blockIdx.x);
}

/* ------------ fp16 GEMM: 128x128x32, 3-stage cp.async, 1 barrier/iter ----
   8 warps: wm=w>>1 (32 m-rows), wn=w&1 (64 n-cols); warp tile 32x64.
   EPI 1: QKV scatter (Q pre-scaled by SCALE2F; K adds pe; V transposed)     */
#define GBM 128
#define GBN 128
#define GBK 32
#define APADH 40
#define BPADH 40
#define AST (GBM*APADH)
#define BST (GBN*BPADH)
#define GEMM_SMEM (3*(AST+BST)*2)     /* 61440 B */

template<int EPI>
__global__ __launch_bounds__(256, 2)
void gemm_tc(const __half* __restrict__ A, const __half* __restrict__ Bt,
             const float* __restrict__ bias,
             int K, int Nc,
             const float* __restrict__ extra, const int* __restrict__ mask,
             float* __restrict__ Cf, __half* __restrict__ Ch,
             __half* __restrict__ Ck, __half* __restrict__ Cv) {
    extern __shared__ __half gsm[];
    __half* As = gsm;
    __half* Bs = gsm + 3*AST;
    int tid = threadIdx.x, lane = tid & 31, w = tid >> 5;
    int g = lane >> 2, t = lane & 3;
    int wm = w >> 1, wn = w & 1;
    int bm = blockIdx.x * GBM, bn = blockIdx.y * GBN;
    int mlow = (lane >> 3) & 1, mhigh = lane >> 4, rr = lane & 7;

    float acc[2][8][4];
    #pragma unroll
    for (int mi = 0; mi < 2; mi++)
        #pragma unroll
        for (int nj = 0; nj < 8; nj++)
            #pragma unroll
            for (int r = 0; r < 4; r++) acc[mi][nj][r] = 0.f;

    int a_r = tid >> 2, a_c = (tid & 3) * 8;
    int b_r = tid >> 2, b_c = (tid & 3) * 8;

    uint32_t As_u = s2u(As);
    uint32_t Bs_u = s2u(Bs);
    uint32_t aoff0 = ((wm*32 + mlow*8 + rr)*APADH + mhigh*8)*2;
    uint32_t aoff1 = aoff0 + 16*APADH*2;
    uint32_t boffb = ((wn*64 + mhigh*8 + rr)*BPADH + mlow*8)*2;

    int ntiles = K / GBK;
    #pragma unroll
    for (int p = 0; p < 2; p++) {
        int k0 = p * GBK;
        cpa16(&As[p*AST + a_r*APADH + a_c], A + (size_t)(bm + a_r)*K + k0 + a_c);
        cpa16(&As[p*AST + (a_r+64)*APADH + a_c], A + (size_t)(bm + a_r + 64)*K + k0 + a_c);
        cpa16(&Bs[p*BST + b_r*BPADH + b_c], Bt + (size_t)(bn + b_r)*K + k0 + b_c);
        cpa16(&Bs[p*BST + (b_r+64)*BPADH + b_c], Bt + (size_t)(bn + b_r + 64)*K + k0 + b_c);
        CP_COMMIT();
    }

    int st = 0;
    for (int kt = 0; kt < ntiles; kt++) {
        cp_wait<1>();
        __syncthreads();
        if (kt + 2 < ntiles) {
            int k0 = (kt + 2) * GBK;
            int sn = st + 2; if (sn >= 3) sn -= 3;
            cpa16(&As[sn*AST + a_r*APADH + a_c], A + (size_t)(bm + a_r)*K + k0 + a_c);
            cpa16(&As[sn*AST + (a_r+64)*APADH + a_c], A + (size_t)(bm + a_r + 64)*K + k0 + a_c);
            cpa16(&Bs[sn*BST + b_r*BPADH + b_c], Bt + (size_t)(bn + b_r)*K + k0 + b_c);
            cpa16(&Bs[sn*BST + (b_r+64)*BPADH + b_c], Bt + (size_t)(bn + b_r + 64)*K + k0 + b_c);
        }
        CP_COMMIT();

        uint32_t asb = As_u + st*(AST*2);
        uint32_t bsb = Bs_u + st*(BST*2);
        #pragma unroll
        for (int ks = 0; ks < 2; ks++) {
            uint32_t kbb = ks*32;
            uint32_t af0[4], af1[4];
            ldsm4(af0[0], af0[1], af0[2], af0[3], asb + aoff0 + kbb);
            ldsm4(af1[0], af1[1], af1[2], af1[3], asb + aoff1 + kbb);
            #pragma unroll
            for (int njp = 0; njp < 4; njp++) {
                uint32_t b0, b1, b2, b3;
                ldsm4(b0, b1, b2, b3, bsb + boffb + njp*16*BPADH*2 + kbb);
                mma16(acc[0][2*njp],   af0[0], af0[1], af0[2], af0[3], b0, b1);
                mma16(acc[0][2*njp+1], af0[0], af0[1], af0[2], af0[3], b2, b3);
                mma16(acc[1][2*njp],   af1[0], af1[1], af1[2], af1[3], b0, b1);
                mma16(acc[1][2*njp+1], af1[0], af1[1], af1[2], af1[3], b2, b3);
            }
        }
        if (++st == 3) st = 0;
    }

    #pragma unroll
    for (int mi = 0; mi < 2; mi++) {
        #pragma unroll
        for (int half = 0; half < 2; half++) {
            int row = bm + wm*32 + mi*16 + g + half*8;
            #pragma unroll
            for (int nj = 0; nj < 8; nj++) {
                int col = bn + wn*64 + nj*8 + 2*t;
                float v0 = acc[mi][nj][half*2+0] + bias[col];
                float v1 = acc[mi][nj][half*2+1] + bias[col+1];
                if (EPI == 1) {
                    int sec = col / BDIM;
                    int c2  = col - sec*BDIM;
                    int d = c2 % HD, hh = c2 / HD;
                    int bb = row >> 11, n = row & (NSEQ-1);
                    if (sec == 2) {
                        __half* p = Cv + ((size_t)((bb*HEADS + hh)*HD + d))*NSEQ + n;
                        p[0]    = __float2half_rn(v0);
                        p[NSEQ] = __float2half_rn(v1);
                    } else if (sec == 1) {
                        v0 += extra[(size_t)row*HD + d];
                        v1 += extra[(size_t)row*HD + d + 1];
                        __half* p = Ck + (((size_t)(bb*HEADS + hh))*NSEQ + n)*HD + d;
                        *(uint32_t*)p = h2pack(v0, v1);
                    } else {
                        /* Q pre-scaled for exp2-domain softmax */
                        v0 *= SCALE2F; v1 *= SCALE2F;
                        __half* p = Ch + (((size_t)(bb*HEADS + hh))*NSEQ + n)*HD + d;
                        *(uint32_t*)p = h2pack(v0, v1);
                    }
                } else if (EPI == 2) {
                    float m = (float)mask[row];
                    v0 = v0*m + extra[(size_t)row*Nc + col];
                    v1 = v1*m + extra[(size_t)row*Nc + col + 1];
                    float* p = Cf + (size_t)row*Nc + col;
                    p[0] = v0; p[1] = v1;
                } else if (EPI == 3) {
                    *(uint32_t*)(Ch + (size_t)row*Nc + col) =
                        h2pack(gelu_exact(v0), gelu_exact(v1));
                } else {
                    float m = (float)mask[row];
                    v0 = (v0 + extra[(size_t)row*Nc + col])*m;
                    v1 = (v1 + extra[(size_t)row*Nc + col + 1])*m;
                    float* p = Cf + (size_t)row*Nc + col;
                    p[0] = v0; p[1] = v1;
                }
            }
        }
    }
}

/* ------- flash attention: register-direct P, Q pre-scaled (no FMUL) ------- */
#define KPADH 56
#define VTPADH 72
#define BQ 128
#define NT (NSEQ/64)
#define KST (64*KPADH)
#define VST (56*VTPADH)                              /* rows 48..55 = ones/zeros */
#define ATT_H_KS 0
#define ATT_H_VT (3*KST)                             /* 10752 */
#define ATT_H_QS (ATT_H_VT + 3*VST)                  /* 22848 */
#define ATT_H_END (ATT_H_QS + 128*KPADH)             /* 30016 halves */
#define ATT_MB_OFF ATT_H_END
#define ATT_SMEM (ATT_H_END*2 + 3*64*4)              /* 60800 B */

__global__ __launch_bounds__(256, 2)
void attn_tc(const __half* __restrict__ Q, const __half* __restrict__ Kb,
             const __half* __restrict__ Vt, const float* __restrict__ mb,
             __half* __restrict__ O) {
    extern __shared__ __half smh[];
    __half* Ks  = smh + ATT_H_KS;
    __half* Vts = smh + ATT_H_VT;
    __half* Qs  = smh + ATT_H_QS;
    float*  MBs = (float*)(smh + ATT_MB_OFF);

    int bh = blockIdx.y, b = bh >> 3, h = bh & 7;
    int q0 = blockIdx.x * BQ;
    int tid = threadIdx.x, lane = tid & 31, w = tid >> 5;
    int g = lane >> 2, t = lane & 3;
    int mlow = (lane >> 3) & 1, mhigh = lane >> 4, rr = lane & 7;
    const __half* qp = Q  + (size_t)bh * NSEQ * HD;
    const __half* kp = Kb + (size_t)bh * NSEQ * HD;
    const __half* vp = Vt + (size_t)bh * NSEQ * HD;   /* [d][n] */
    const float* mbp = mb + b * NSEQ;

    uint32_t Ks_u = s2u(Ks), Vt_u = s2u(Vts), Qs_u = s2u(Qs);
    uint32_t koff = ((mhigh*8 + rr)*KPADH + mlow*8)*2;
    uint32_t voff = ((mhigh*8 + rr)*VTPADH + mlow*8)*2;
    uint32_t loff = ((48 + rr)*VTPADH + mlow*8)*2;    /* ones-row ldsm.x2 */
    uint32_t qoff = Qs_u + ((w*16 + mlow*8 + rr)*KPADH + mhigh*8)*2;

    /* prologue FIRST: issue K/V/MB tiles 0 and 1 (overlaps Q staging) */
    #pragma unroll
    for (int p = 0; p < 2; p++) {
        int k0 = p * 64;
        #pragma unroll
        for (int i = 0; i < 2; i++) {
            int idx = tid + i*256;
            if (idx < 384) {
                int r = idx / 6, c = (idx % 6) * 8;
                cpa16(Ks + p*KST + r*KPADH + c, kp + (size_t)(k0 + r)*HD + c);
                int rv = idx >> 3, cv = (idx & 7) * 8;
                cpa16(Vts + p*VST + rv*VTPADH + cv, vp + (size_t)rv*NSEQ + k0 + cv);
            }
        }
        if (tid < 64) cpa4(MBs + p*64 + tid, mbp + k0 + tid);
        CP_COMMIT();
    }

    /* init ones/zeros rows 48..55 of V^T stages (never touched by cp.async) */
    {
        const __half one = __float2half(1.0f), zero = __float2half(0.0f);
        for (int idx = tid; idx < 3*8*64; idx += 256) {
            int stg = idx / 512, rem = idx - stg*512;
            int rw = 48 + rem / 64, cc = rem % 64;
            Vts[stg*VST + rw*VTPADH + cc] = (rw == 48) ? one : zero;
        }
    }

    /* stage Q ([128][56] halves), extract fragments via ldmatrix */
    #pragma unroll
    for (int i = 0; i < 3; i++) {
        int idx = tid + i*256;
        int r = idx / 6, c = (idx % 6) * 8;
        *(uint4*)(Qs + r*KPADH + c) = *(const uint4*)(qp + (size_t)(q0 + r)*HD + c);
    }
    __syncthreads();
    uint32_t qf[3][4];
    #pragma unroll
    for (int ks = 0; ks < 3; ks++)
        ldsm4(qf[ks][0], qf[ks][1], qf[ks][2], qf[ks][3], qoff + ks*32);

    float o[6][4];
    #pragma unroll
    for (int nj = 0; nj < 6; nj++)
        #pragma unroll
        for (int r = 0; r < 4; r++) o[nj][r] = 0.f;
    float l4[4] = {0.f, 0.f, 0.f, 0.f};
    float mA = -INFINITY, mB = -INFINITY;

    int st = 0;
    for (int kt = 0; kt < NT; kt++) {
        cp_wait<1>();
        __syncthreads();
        if (kt + 2 < NT) {
            int k0 = (kt + 2) * 64;
            int sn = st + 2; if (sn >= 3) sn -= 3;
            #pragma unroll
            for (int i = 0; i < 2; i++) {
                int idx = tid + i*256;
                if (idx < 384) {
                    int r = idx / 6, c = (idx % 6) * 8;
                    cpa16(Ks + sn*KST + r*KPADH + c, kp + (size_t)(k0 + r)*HD + c);
                    int rv = idx >> 3, cv = (idx & 7) * 8;
                    cpa16(Vts + sn*VST + rv*VTPADH + cv, vp + (size_t)rv*NSEQ + k0 + cv);
                }
            }
            if (tid < 64) cpa4(MBs + sn*64 + tid, mbp + k0 + tid);
        }
        CP_COMMIT();

        uint32_t Kst_u = Ks_u + st*KST*2;
        uint32_t Vst_u = Vt_u + st*VST*2;
        const float* MBst = MBs + st*64;

        /* S = Q K^T : warp tile 16x64 (already exp2-domain; Q pre-scaled) */
        float s[8][4];
        #pragma unroll
        for (int nj = 0; nj < 8; nj++)
            #pragma unroll
            for (int r = 0; r < 4; r++) s[nj][r] = 0.f;
        #pragma unroll
        for (int ks = 0; ks < 3; ks++) {
            uint32_t kbb = ks*32;
            #pragma unroll
            for (int njp = 0; njp < 4; njp++) {
                uint32_t b0, b1, b2, b3;
                ldsm4(b0, b1, b2, b3, Kst_u + koff + njp*16*KPADH*2 + kbb);
                mma16(s[2*njp],   qf[ks][0], qf[ks][1], qf[ks][2], qf[ks][3], b0, b1);
                mma16(s[2*njp+1], qf[ks][0], qf[ks][1], qf[ks][2], qf[ks][3], b2, b3);
            }
        }

        /* + mask bias (pure FADD), row max */
        float mxA = -INFINITY, mxB = -INFINITY;
        #pragma unroll
        for (int nj = 0; nj < 8; nj++) {
            float2 mbv = *(const float2*)(MBst + nj*8 + 2*t);
            s[nj][0] += mbv.x;
            s[nj][1] += mbv.y;
            s[nj][2] += mbv.x;
            s[nj][3] += mbv.y;
            mxA = fmaxf(mxA, fmaxf(s[nj][0], s[nj][1]));
            mxB = fmaxf(mxB, fmaxf(s[nj][2], s[nj][3]));
        }
        mxA = fmaxf(mxA, __shfl_xor_sync(0xffffffffu, mxA, 1));
        mxA = fmaxf(mxA, __shfl_xor_sync(0xffffffffu, mxA, 2));
        mxB = fmaxf(mxB, __shfl_xor_sync(0xffffffffu, mxB, 1));
        mxB = fmaxf(mxB, __shfl_xor_sync(0xffffffffu, mxB, 2));

        float mAn = fmaxf(mA, mxA), fA = ex2(mA - mAn);
        float mBn = fmaxf(mB, mxB), fB = ex2(mB - mBn);
        mA = mAn; mB = mBn;

        /* rescale output + l accumulators */
        #pragma unroll
        for (int nj = 0; nj < 6; nj++) {
            o[nj][0] *= fA; o[nj][1] *= fA;
            o[nj][2] *= fB; o[nj][3] *= fB;
        }
        l4[0] *= fA; l4[2] *= fB;

        /* P = exp2(S-m) REGISTER-DIRECT into PV mma (S C-frag == PV A-frag) */
        #pragma unroll
        for (int ks = 0; ks < 4; ks++) {
            uint32_t kbb = ks*32;
            uint32_t a0 = h2ex2(h2pack(s[2*ks][0]   - mA, s[2*ks][1]   - mA));
            uint32_t a1 = h2ex2(h2pack(s[2*ks][2]   - mB, s[2*ks][3]   - mB));
            uint32_t a2 = h2ex2(h2pack(s[2*ks+1][0] - mA, s[2*ks+1][1] - mA));
            uint32_t a3 = h2ex2(h2pack(s[2*ks+1][2] - mB, s[2*ks+1][3] - mB));
            #pragma unroll
            for (int njp = 0; njp < 3; njp++) {
                uint32_t b0, b1, b2, b3;
                ldsm4(b0, b1, b2, b3, Vst_u + voff + njp*16*VTPADH*2 + kbb);
                mma16(o[2*njp],   a0, a1, a2, a3, b0, b1);
                mma16(o[2*njp+1], a0, a1, a2, a3, b2, b3);
            }
            uint32_t c0, c1;
            ldsm2(c0, c1, Vst_u + loff + kbb);
            mma16(l4, a0, a1, a2, a3, c0, c1);
        }
        if (++st == 3) st = 0;
    }

    /* epilogue: l lives in column 48 -> lane t==0 of each quad */
    float lA = __shfl_sync(0xffffffffu, l4[0], lane & 28);
    float lB = __shfl_sync(0xffffffffu, l4[2], lane & 28);
    float invA = 1.0f / lA, invB = 1.0f / lB;
    int rA = q0 + w*16 + g, rB = rA + 8;
    #pragma unroll
    for (int nj = 0; nj < 6; nj++) {
        int cb = nj*8 + 2*t;
        *(uint32_t*)(O + ((size_t)(b*NSEQ + rA))*BDIM + h*HD + cb) =
            h2pack(o[nj][0]*invA, o[nj][1]*invA);
        *(uint32_t*)(O + ((size_t)(b*NSEQ + rB))*BDIM + h*HD + cb) =
            h2pack(o[nj][2]*invB, o[nj][3]*invB);
    }
}

/* ------------------------------ launch ------------------------------ */
extern "C" void kernel_launch(void* const* d_in, const int* in_sizes, int n_in,
                              void* d_out, int out_size) {
    const float* x    = (const float*)d_in[0];
    const float* pos  = (const float*)d_in[1];
    const void*  mask = d_in[2];
    const float* Wq   = (const float*)d_in[3];
    const float* bq   = (const float*)d_in[4];
    const float* Wk   = (const float*)d_in[5];
    const float* bk   = (const float*)d_in[6];
    const float* Wv   = (const float*)d_in[7];
    const float* bv   = (const float*)d_in[8];
    const float* pw1  = (const float*)d_in[9];
    const float* pb1  = (const float*)d_in[10];
    const float* pw2  = (const float*)d_in[11];
    const float* pb2  = (const float*)d_in[12];
    const float* Wo   = (const float*)d_in[13];
    const float* bo   = (const float*)d_in[14];
    const float* mw1  = (const float*)d_in[15];
    const float* mb1  = (const float*)d_in[16];
    const float* mw2  = (const float*)d_in[17];
    const float* mb2  = (const float*)d_in[18];
    const float* g1   = (const float*)d_in[19];
    const float* be1  = (const float*)d_in[20];
    const float* g2   = (const float*)d_in[21];
    const float* be2  = (const float*)d_in[22];
    float* out = (float*)d_out;

    void *ph, *pq, *pk, *pv, *patt, *phid, *pwq, *pwo, *pm1, *pm2;
    void *ppe, *px1, *pm, *pmb, *pbq;
    cudaGetSymbolAddress(&ph,  g_h16);
    cudaGetSymbolAddress(&pq,  g_q16);
    cudaGetSymbolAddress(&pk,  g_k16);
    cudaGetSymbolAddress(&pv,  g_v16t);
    cudaGetSymbolAddress(&patt,g_att16);
    cudaGetSymbolAddress(&phid,g_hid16);
    cudaGetSymbolAddress(&pwq, g_wqkvT);
    cudaGetSymbolAddress(&pwo, g_woT);
    cudaGetSymbolAddress(&pm1, g_mw1T);
    cudaGetSymbolAddress(&pm2, g_mw2T);
    cudaGetSymbolAddress(&ppe, g_pe);
    cudaGetSymbolAddress(&px1, g_x1);
    cudaGetSymbolAddress(&pm,  g_mask);
    cudaGetSymbolAddress(&pmb, g_mb);
    cudaGetSymbolAddress(&pbq, g_bqkv);
    __half* h16   = (__half*)ph;
    __half* q16   = (__half*)pq;
    __half* k16   = (__half*)pk;
    __half* v16t  = (__half*)pv;
    __half* att16 = (__half*)patt;
    __half* hid16 = (__half*)phid;
    __half* wqkvT = (__half*)pwq;
    __half* woT   = (__half*)pwo;
    __half* mw1T  = (__half*)pm1;
    __half* mw2T  = (__half*)pm2;
    float* pe   = (float*)ppe;
    float* x1   = (float*)px1;
    int*   msk  = (int*)pm;
    float* mbf  = (float*)pmb;
    float* bqkv = (float*)pbq;

    cudaFuncSetAttribute(attn_tc,
                         cudaFuncAttributeMaxDynamicSharedMemorySize, ATT_SMEM);
    cudaFuncSetAttribute(gemm_tc<1>,
                         cudaFuncAttributeMaxDynamicSharedMemorySize, GEMM_SMEM);
    cudaFuncSetAttribute(gemm_tc<2>,
                         cudaFuncAttributeMaxDynamicSharedMemorySize, GEMM_SMEM);
    cudaFuncSetAttribute(gemm_tc<3>,
                         cudaFuncAttributeMaxDynamicSharedMemorySize, GEMM_SMEM);
    cudaFuncSetAttribute(gemm_tc<4>,
                         cudaFuncAttributeMaxDynamicSharedMemorySize, GEMM_SMEM);

    /* 1. fused prep: LN1 + pe + transposes + mask + bias pack */
    prep_kernel<<<3778, 256>>>(x, g1, be1, h16,
                               pos, pw1, pb1, pw2, pb2, pe,
                               Wq, Wk, Wv, Wo, mw1, mw2,
                               wqkvT, woT, mw1T, mw2T,
                               mask, msk, mbf,
                               bq, bk, bv, bqkv);
    /* 2. fused QKV projection (Q pre-scaled) */
    dim3 gqkv(MROWS/GBM, QKVN/GBN);
    gemm_tc<1><<<gqkv, 256, GEMM_SMEM>>>(h16, wqkvT, bqkv, BDIM, QKVN, pe, nullptr,
                                         nullptr, q16, k16, v16t);
    /* 3. attention */
    dim3 ga(NSEQ/BQ, NB*HEADS);
    attn_tc<<<ga, 256, ATT_SMEM>>>(q16, k16, v16t, mbf, att16);
    /* 4. Wo + mask + residual -> x1 (f32) */
    dim3 gwo(MROWS/GBM, BDIM/GBN);
    gemm_tc<2><<<gwo, 256, GEMM_SMEM>>>(att16, woT, bo, BDIM, BDIM, x, msk,
                                        x1, nullptr, nullptr, nullptr);
    /* 5. LN2 -> fp16 */
    ln_kernel<<<MROWS/8, 256>>>(x1, g2, be2, h16);
    /* 6. MLP1 + gelu -> fp16 */
    dim3 gm1(MROWS/GBM, MLPH/GBN);
    gemm_tc<3><<<gm1, 256, GEMM_SMEM>>>(h16, mw1T, mb1, BDIM, MLPH, nullptr, nullptr,
                                        nullptr, hid16, nullptr, nullptr);
    /* 7. MLP2 + residual + mask -> out (f32) */
    gemm_tc<4><<<gwo, 256, GEMM_SMEM>>>(hid16, mw2T, mb2, MLPH, BDIM, x1, msk,
                                        out, nullptr, nullptr, nullptr);
}